// round 9
// baseline (speedup 1.0000x reference)
#include <cuda_runtime.h>
#include <cuda_bf16.h>
#include <math.h>
#include <stdint.h>

// ---------------- problem constants ----------------
constexpr int cB = 4, cT = 4096, cD = 1024, cH = 8;
constexpr int cDK = 1024, cDV = 2048, cDKH = 128, cDVH = 256;
constexpr int cRANK = 16, cLOOPD = 128, cNL = 4;
constexpr int cCH = 64;
constexpr int cNC = cT / cCH;
constexpr int cBH = cB * cH;
constexpr int cM = cB * cT;
constexpr int PSTR = 7168;              // merged projection row stride (q|k|la|v|gate)
constexpr int OFF_K = 1024, OFF_LA = 2048, OFF_V = 3072, OFF_G = 5120;

// ---------------- device scratch ----------------
__device__ float g_h[cM * cD];
__device__ float g_proj[(size_t)cM * PSTR];
__device__ float g_o[cM * cDV];
__device__ float g_kv[cNC * cBH * cDKH * cDVH];
__device__ float g_S[cNC * cBH * cDKH * cDVH];
__device__ float g_bdec[cNC * cBH * cDKH];
__device__ float g_gla[cM * cD];
__device__ float g_lora[cM * cRANK];
__device__ float g_hnew[cM * cD];
__device__ float g_hout[cM * cD];
__device__ float g_cum[cM];
__device__ float g_halt[cM];
__device__ float g_einj[cM * cD];

// bf16 hi/lo buffers
__device__ __align__(16) __nv_bfloat16 g_wph[(size_t)PSTR * cD], g_wpl[(size_t)PSTR * cD];
__device__ __align__(16) __nv_bfloat16 g_woh[cDV * cD],  g_wol[cDV * cD];
__device__ __align__(16) __nv_bfloat16 g_iah[cD * cD],   g_ial[cD * cD];
__device__ __align__(16) __nv_bfloat16 g_ibh[cD * cD],   g_ibl[cD * cD];
__device__ __align__(16) __nv_bfloat16 g_eh[cM * cD],    g_el[cM * cD];
__device__ __align__(16) __nv_bfloat16 g_xh[cM * cD],    g_xl[cM * cD];
__device__ __align__(16) __nv_bfloat16 g_hh2[cM * cD],   g_hl2[cM * cD];
__device__ __align__(16) __nv_bfloat16 g_oh[cM * cDV],   g_ol[cM * cDV];

// ---------------- helpers ----------------
__device__ __forceinline__ uint32_t s2u(const void* p) {
    uint32_t a;
    asm("{ .reg .u64 t; cvta.to.shared.u64 t, %1; cvt.u32.u64 %0, t; }" : "=r"(a) : "l"(p));
    return a;
}
__device__ __forceinline__ uint32_t sw128(uint32_t off) { return off ^ ((off >> 3) & 0x70); }

#define LDSM4(r, a) \
    asm volatile("ldmatrix.sync.aligned.m8n8.x4.shared.b16 {%0,%1,%2,%3}, [%4];" \
        : "=r"((r)[0]), "=r"((r)[1]), "=r"((r)[2]), "=r"((r)[3]) : "r"(a))

__device__ __forceinline__ void mma_bf16(float* d, const uint32_t* a, const uint32_t* b) {
    asm volatile("mma.sync.aligned.m16n8k16.row.col.f32.bf16.bf16.f32 "
        "{%0,%1,%2,%3}, {%4,%5,%6,%7}, {%8,%9}, {%0,%1,%2,%3};"
        : "+f"(d[0]), "+f"(d[1]), "+f"(d[2]), "+f"(d[3])
        : "r"(a[0]), "r"(a[1]), "r"(a[2]), "r"(a[3]), "r"(b[0]), "r"(b[1]));
}

// ---------------- mma.sync bf16 hi/lo GEMM (R7-proven core) ----------------
// A:[M,K] hi/lo row-major; B:[N,K] hi/lo K-major. CTA tile 128x128, K-chunk 64,
// 8 warps (warp tile 32x64), 3-stage cp.async, 64KB stages, 1 CTA/SM.
// epi: 0 none, 1 scale, 2 logsig/16, 3 silu, 9 merged-projection per-segment.
constexpr int GTM = 128, GTN = 128, GKC = 64;
constexpr int TILE_B = 16384;
constexpr int STG_B = 4 * TILE_B;
constexpr int NSTG = 3;
constexpr int GEMM_SMEM = NSTG * STG_B;   // 196608

__global__ void __launch_bounds__(256, 1) gemm_bf16(
    const __nv_bfloat16* __restrict__ Ah, const __nv_bfloat16* __restrict__ Al,
    const __nv_bfloat16* __restrict__ Bh, const __nv_bfloat16* __restrict__ Bl,
    float* __restrict__ C, const float* __restrict__ Ci,
    int M, int N, int K, float scale, int epi)
{
    extern __shared__ char smem[];
    int tid = threadIdx.x;
    int lane = tid & 31, wid = tid >> 5;
    int m0 = blockIdx.y * GTM, n0 = blockIdx.x * GTN;
    int wm = (wid & 3) * 32, wn = (wid >> 2) * 64;

    const int NCk = K / GKC;

    auto load_stage = [&](int kc, int s) {
        char* base = smem + s * STG_B;
        int k0 = kc * GKC;
        const __nv_bfloat16* gp0 = Ah + (size_t)m0 * K + k0;
        const __nv_bfloat16* gp1 = Al + (size_t)m0 * K + k0;
        const __nv_bfloat16* gp2 = Bh + (size_t)n0 * K + k0;
        const __nv_bfloat16* gp3 = Bl + (size_t)n0 * K + k0;
#pragma unroll
        for (int i = 0; i < 4; i++) {
            int gg = tid + i * 256;
            int r = gg >> 3, seg = gg & 7;
            uint32_t off = sw128((uint32_t)(r * 128 + seg * 16));
            size_t go = (size_t)r * K + seg * 8;
            uint32_t d0 = s2u(base + off);
            uint32_t d1 = s2u(base + TILE_B + off);
            uint32_t d2 = s2u(base + 2 * TILE_B + off);
            uint32_t d3 = s2u(base + 3 * TILE_B + off);
            asm volatile("cp.async.cg.shared.global [%0], [%1], 16;" :: "r"(d0), "l"(gp0 + go));
            asm volatile("cp.async.cg.shared.global [%0], [%1], 16;" :: "r"(d1), "l"(gp1 + go));
            asm volatile("cp.async.cg.shared.global [%0], [%1], 16;" :: "r"(d2), "l"(gp2 + go));
            asm volatile("cp.async.cg.shared.global [%0], [%1], 16;" :: "r"(d3), "l"(gp3 + go));
        }
        asm volatile("cp.async.commit_group;" ::: "memory");
    };

    float acc[2][8][4];
#pragma unroll
    for (int mf = 0; mf < 2; mf++)
#pragma unroll
        for (int nf = 0; nf < 8; nf++)
#pragma unroll
            for (int j = 0; j < 4; j++) acc[mf][nf][j] = 0.f;

    load_stage(0, 0);
    load_stage(1, 1);
    load_stage(2, 2);

    int a_row = (lane & 15);
    int a_col8 = (lane >> 4);
    int b_row = (lane & 7) + ((lane >> 4) & 1) * 8;
    int b_col8 = (lane >> 3) & 1;

    for (int c = 0; c < NCk; c++) {
        asm volatile("cp.async.wait_group 2;" ::: "memory");
        __syncthreads();
        char* base = smem + (c % 3) * STG_B;
        uint32_t sAh = s2u(base), sAl = sAh + TILE_B, sBh = sAl + TILE_B, sBl = sBh + TILE_B;
#pragma unroll
        for (int kk = 0; kk < 4; kk++) {
            int k0 = kk * 16;
            uint32_t ah[2][4], al[2][4], bh[8][2], bl[8][2];
#pragma unroll
            for (int mf = 0; mf < 2; mf++) {
                uint32_t off = sw128((uint32_t)((wm + mf * 16 + a_row) * 128 + (k0 + a_col8 * 8) * 2));
                LDSM4(ah[mf], sAh + off);
                LDSM4(al[mf], sAl + off);
            }
#pragma unroll
            for (int nf = 0; nf < 4; nf++) {
                uint32_t off = sw128((uint32_t)((wn + nf * 16 + b_row) * 128 + (k0 + b_col8 * 8) * 2));
                uint32_t r[4];
                LDSM4(r, sBh + off);
                bh[nf * 2][0] = r[0]; bh[nf * 2][1] = r[1];
                bh[nf * 2 + 1][0] = r[2]; bh[nf * 2 + 1][1] = r[3];
                LDSM4(r, sBl + off);
                bl[nf * 2][0] = r[0]; bl[nf * 2][1] = r[1];
                bl[nf * 2 + 1][0] = r[2]; bl[nf * 2 + 1][1] = r[3];
            }
#pragma unroll
            for (int mf = 0; mf < 2; mf++)
#pragma unroll
                for (int nf = 0; nf < 8; nf++) {
                    mma_bf16(acc[mf][nf], ah[mf], bh[nf]);
                    mma_bf16(acc[mf][nf], ah[mf], bl[nf]);
                    mma_bf16(acc[mf][nf], al[mf], bh[nf]);
                }
        }
        __syncthreads();
        if (c + 3 < NCk) load_stage(c + 3, c % 3);
        else asm volatile("cp.async.commit_group;" ::: "memory");
    }

#pragma unroll
    for (int mf = 0; mf < 2; mf++) {
#pragma unroll
        for (int nf = 0; nf < 8; nf++) {
            int r0 = m0 + wm + mf * 16 + (lane >> 2);
            int cc = n0 + wn + nf * 8 + (lane & 3) * 2;
#pragma unroll
            for (int hh = 0; hh < 2; hh++) {
                int r = r0 + hh * 8;
                float vx = acc[mf][nf][hh * 2], vy = acc[mf][nf][hh * 2 + 1];
                size_t off = (size_t)r * N + cc;
                if (Ci) { vx += Ci[off]; vy += Ci[off + 1]; }
                int e = epi;
                if (e == 9) {
                    int seg = cc >> 10;
                    e = (seg == 0) ? 1 : (seg == 2) ? 2 : (seg >= 5) ? 3 : 0;
                }
                if (e == 1) { vx *= scale; vy *= scale; }
                else if (e == 2) {
                    vx = (fminf(vx, 0.f) - log1pf(expf(-fabsf(vx)))) * 0.0625f;
                    vy = (fminf(vy, 0.f) - log1pf(expf(-fabsf(vy)))) * 0.0625f;
                } else if (e == 3) {
                    vx = vx / (1.f + expf(-vx));
                    vy = vy / (1.f + expf(-vy));
                }
                *(float2*)&C[off] = make_float2(vx, vy);
            }
        }
    }
}

// ---------------- utility kernels ----------------
__global__ void k_copy(float* __restrict__ dst, const float* __restrict__ src) {
    int idx = blockIdx.x * 256 + threadIdx.x;
    dst[idx] = src[idx];
}
__global__ void k_zero(float* __restrict__ dst) {
    int idx = blockIdx.x * 256 + threadIdx.x;
    dst[idx] = 0.f;
}
__global__ void k_zero_state(float* __restrict__ cum, float* __restrict__ halt) {
    int idx = blockIdx.x * 256 + threadIdx.x;
    cum[idx] = 0.f; halt[idx] = 0.f;
}

__device__ __forceinline__ void bsplit(float x, __nv_bfloat16& h, __nv_bfloat16& l) {
    h = __float2bfloat16(x);
    l = __float2bfloat16(x - __bfloat162float(h));
}

__global__ void k_split(const float* __restrict__ src, __nv_bfloat16* __restrict__ hi,
                        __nv_bfloat16* __restrict__ lo) {
    size_t i4 = ((size_t)blockIdx.x * 256 + threadIdx.x) * 4;
    float4 v = *(const float4*)(src + i4);
    __nv_bfloat16 h0, h1, h2, h3, l0, l1, l2, l3;
    bsplit(v.x, h0, l0); bsplit(v.y, h1, l1); bsplit(v.z, h2, l2); bsplit(v.w, h3, l3);
    hi[i4] = h0; hi[i4+1] = h1; hi[i4+2] = h2; hi[i4+3] = h3;
    lo[i4] = l0; lo[i4+1] = l1; lo[i4+2] = l2; lo[i4+3] = l3;
}
// transpose-convert: W [K,N] fp32 -> out [N,K] bf16 hi/lo (out row stride K)
__global__ void k_wconvT(const float* __restrict__ W, __nv_bfloat16* __restrict__ hi,
                         __nv_bfloat16* __restrict__ lo, int K, int N) {
    __shared__ float s[32][33];
    int n0 = blockIdx.x * 32, k0 = blockIdx.y * 32;
    int tx = threadIdx.x, ty = threadIdx.y;
#pragma unroll
    for (int i = 0; i < 4; i++) {
        int r = ty + i * 8;
        s[r][tx] = W[(size_t)(k0 + r) * N + n0 + tx];
    }
    __syncthreads();
#pragma unroll
    for (int i = 0; i < 4; i++) {
        int r = ty + i * 8;
        float v = s[tx][r];
        size_t o = (size_t)(n0 + r) * K + k0 + tx;
        __nv_bfloat16 h, l; bsplit(v, h, l);
        hi[o] = h; lo[o] = l;
    }
}

// ---------------- fused loop-embed + rmsnorm(h+e) + bf16 splits ----------------
__global__ void __launch_bounds__(256) k_prep(float* __restrict__ h, const float* __restrict__ e,
                                              const float* __restrict__ nw, const float* __restrict__ ltab,
                                              __nv_bfloat16* __restrict__ xh, __nv_bfloat16* __restrict__ xl,
                                              __nv_bfloat16* __restrict__ hh, __nv_bfloat16* __restrict__ hl) {
    int row = blockIdx.x; size_t base = (size_t)row * cD;
    int tid = threadIdx.x;
    if (tid < cLOOPD) h[base + tid] += ltab[tid];
    __syncthreads();
    float hv[4], vals[4]; float ss = 0.f;
#pragma unroll
    for (int i = 0; i < 4; i++) {
        int c = tid + i * 256;
        float hx = h[base + c];
        hv[i] = hx;
        float v = hx + e[base + c];
        vals[i] = v; ss += v * v;
    }
    __shared__ float red[256];
    red[tid] = ss; __syncthreads();
    for (int s = 128; s > 0; s >>= 1) { if (tid < s) red[tid] += red[tid + s]; __syncthreads(); }
    float rs = rsqrtf(red[0] * (1.f / cD) + 1e-6f);
#pragma unroll
    for (int i = 0; i < 4; i++) {
        int c = tid + i * 256;
        float x = vals[i] * rs * nw[c];
        __nv_bfloat16 a, b;
        bsplit(x, a, b); xh[base + c] = a; xl[base + c] = b;
        bsplit(hv[i], a, b); hh[base + c] = a; hl[base + c] = b;
    }
}

// ---------------- final rmsnorm ----------------
__global__ void __launch_bounds__(256) k_rmsnorm(const float* __restrict__ in, const float* __restrict__ nw,
                                                 float* __restrict__ out) {
    int row = blockIdx.x; size_t base = (size_t)row * cD;
    int tid = threadIdx.x;
    float vals[4]; float ss = 0.f;
#pragma unroll
    for (int i = 0; i < 4; i++) {
        int c = tid + i * 256;
        float v = in[base + c];
        vals[i] = v; ss += v * v;
    }
    __shared__ float red[256];
    red[tid] = ss; __syncthreads();
    for (int s = 128; s > 0; s >>= 1) { if (tid < s) red[tid] += red[tid + s]; __syncthreads(); }
    float rs = rsqrtf(red[0] * (1.f / cD) + 1e-6f);
#pragma unroll
    for (int i = 0; i < 4; i++) {
        int c = tid + i * 256;
        out[base + c] = vals[i] * rs * nw[c];
    }
}

// ---------------- GLA chunk kernel ----------------
constexpr int SMEM_CHUNK = 49408 * 4;
__global__ void __launch_bounds__(256) k_chunk(float* __restrict__ pq, const float* __restrict__ pk,
                                               const float* __restrict__ pla, const float* __restrict__ pv,
                                               float* __restrict__ po, float* __restrict__ pkv,
                                               float* __restrict__ pbdec) {
    extern __shared__ float sm[];
    float* s_cum = sm;
    float* s_qt = sm + 8192;
    float* s_kt = sm + 16384;     // stride 132
    float* s_kc = sm + 24832;
    float* s_v  = sm + 33024;
    float* s_A  = sm;

    int cidx = blockIdx.x;
    int c = cidx / cBH, bh = cidx - c * cBH;
    int b = bh >> 3, hh = bh & 7;
    int t0 = c * cCH;
    size_t qbase = ((size_t)b * cT + t0) * PSTR + hh * cDKH;
    size_t vbase = ((size_t)b * cT + t0) * PSTR + hh * cDVH;
    size_t obase = ((size_t)b * cT + t0) * cDV + hh * cDVH;
    int tid = threadIdx.x;

    if (tid < 128) {
        int d = tid;
        float cum = 0.f;
        for (int i = 0; i < cCH; i++) {
            size_t off = qbase + (size_t)i * PSTR + d;
            cum += pla[off];
            s_cum[i * 128 + d] = cum;
            s_qt[i * 128 + d] = pq[off] * expf(cum);
            s_kt[i * 132 + d] = pk[off] * expf(-cum);
            s_kc[i * 128 + d] = pk[off];
        }
        float latot = cum;
        pbdec[(size_t)cidx * cDKH + d] = expf(latot);
        for (int i = 0; i < cCH; i++)
            s_kc[i * 128 + d] *= expf(latot - s_cum[i * 128 + d]);
        for (int i = 0; i < cCH; i++)
            pq[qbase + (size_t)i * PSTR + d] = s_qt[i * 128 + d];
    } else {
        int lt = tid - 128;
        for (int l = 0; l < 32; l++) {
            int idx4 = lt + l * 128;
            int i = idx4 >> 6;
            int u4 = (idx4 & 63) * 4;
            *(float4*)&s_v[i * 256 + u4] = *(const float4*)&pv[vbase + (size_t)i * PSTR + u4];
        }
    }
    __syncthreads();

    for (int idx = tid; idx < cCH * cCH; idx += 256) {
        int i = idx >> 6, j = idx & 63;
        float sum = 0.f;
        if (j <= i) {
            const float* qp = &s_qt[i * 128];
            const float* kp = &s_kt[j * 132];
#pragma unroll
            for (int d = 0; d < 128; d += 4) {
                float4 qa = *(const float4*)&qp[d];
                float4 kb = *(const float4*)&kp[d];
                sum += qa.x * kb.x + qa.y * kb.y + qa.z * kb.z + qa.w * kb.w;
            }
        }
        s_A[idx] = sum;
    }
    __syncthreads();

    // O_intra = A @ V
    {
        int uq = tid & 63;
        int il = tid >> 6;
#pragma unroll 1
        for (int step = 0; step < 16; step++) {
            int i = il + step * 4;
            float4 acc = make_float4(0.f, 0.f, 0.f, 0.f);
            const float* arow = &s_A[i * 64];
            for (int j = 0; j <= i; j++) {
                float a = arow[j];
                float4 vv = *(const float4*)&s_v[j * 256 + uq * 4];
                acc.x += a * vv.x; acc.y += a * vv.y; acc.z += a * vv.z; acc.w += a * vv.w;
            }
            *(float4*)&po[obase + (size_t)i * cDV + uq * 4] = acc;
        }
    }

    // KV_c = kc^T @ V
    {
#pragma unroll 1
        for (int s = 0; s < 8; s++) {
            int idx = tid + s * 256;
            int dq = idx >> 6;
            int uq = idx & 63;
            float4 a0 = make_float4(0.f,0.f,0.f,0.f), a1 = a0, a2 = a0, a3 = a0;
#pragma unroll 4
            for (int j = 0; j < cCH; j++) {
                float4 kc = *(const float4*)&s_kc[j * 128 + dq * 4];
                float4 vv = *(const float4*)&s_v[j * 256 + uq * 4];
                a0.x += kc.x * vv.x; a0.y += kc.x * vv.y; a0.z += kc.x * vv.z; a0.w += kc.x * vv.w;
                a1.x += kc.y * vv.x; a1.y += kc.y * vv.y; a1.z += kc.y * vv.z; a1.w += kc.y * vv.w;
                a2.x += kc.z * vv.x; a2.y += kc.z * vv.y; a2.z += kc.z * vv.z; a2.w += kc.z * vv.w;
                a3.x += kc.w * vv.x; a3.y += kc.w * vv.y; a3.z += kc.w * vv.z; a3.w += kc.w * vv.w;
            }
            size_t kvbase = (size_t)cidx * (cDKH * cDVH) + (size_t)(dq * 4) * cDVH + uq * 4;
            *(float4*)&pkv[kvbase]            = a0;
            *(float4*)&pkv[kvbase + cDVH]     = a1;
            *(float4*)&pkv[kvbase + 2 * cDVH] = a2;
            *(float4*)&pkv[kvbase + 3 * cDVH] = a3;
        }
    }
}

// ---------------- state propagation ----------------
__global__ void __launch_bounds__(256) k_state(const float* __restrict__ pkv, const float* __restrict__ pbdec,
                                               float* __restrict__ Sout) {
    int blk = blockIdx.x;
    int bh = blk >> 3;
    int vs = (blk & 7) * 32;
    int tid = threadIdx.x;
    int kr = tid >> 1;
    int vofs = vs + (tid & 1) * 16;
    float S[16];
#pragma unroll
    for (int j = 0; j < 16; j++) S[j] = 0.f;
    for (int c = 0; c < cNC; c++) {
        size_t base = ((size_t)c * cBH + bh) * (cDKH * cDVH) + (size_t)kr * cDVH + vofs;
        float bd = pbdec[((size_t)c * cBH + bh) * cDKH + kr];
#pragma unroll
        for (int j = 0; j < 16; j += 4) {
            *(float4*)&Sout[base + j] = make_float4(S[j], S[j + 1], S[j + 2], S[j + 3]);
            float4 kvv = *(const float4*)&pkv[base + j];
            S[j]     = bd * S[j]     + kvv.x;
            S[j + 1] = bd * S[j + 1] + kvv.y;
            S[j + 2] = bd * S[j + 2] + kvv.z;
            S[j + 3] = bd * S[j + 3] + kvv.w;
        }
    }
}

// ---------------- inter-chunk output + fused gate + bf16 split ----------------
__global__ void __launch_bounds__(256) k_inter(const float* __restrict__ pq, const float* __restrict__ S,
                                               const float* __restrict__ po, const float* __restrict__ pgate,
                                               __nv_bfloat16* __restrict__ oh, __nv_bfloat16* __restrict__ ol) {
    __shared__ float s_q[cCH * cDKH];
    int cidx = blockIdx.x;
    int c = cidx / cBH, bh = cidx - c * cBH;
    int b = bh >> 3, hh = bh & 7;
    int t0 = c * cCH;
    size_t qbase = ((size_t)b * cT + t0) * PSTR + hh * cDKH;
    size_t gbase = ((size_t)b * cT + t0) * PSTR + hh * cDVH;
    size_t obase = ((size_t)b * cT + t0) * cDV + hh * cDVH;
    int tid = threadIdx.x;
#pragma unroll
    for (int l = 0; l < 8; l++) {
        int idx4 = tid + l * 256;
        int i = idx4 >> 5;
        int d4 = (idx4 & 31) * 4;
        *(float4*)&s_q[i * 128 + d4] = *(const float4*)&pq[qbase + (size_t)i * PSTR + d4];
    }
    __syncthreads();
    int u = tid;
    float acc[cCH];
#pragma unroll
    for (int i = 0; i < cCH; i++) acc[i] = 0.f;
    size_t sbase = (size_t)cidx * (cDKH * cDVH) + u;
    for (int d = 0; d < cDKH; d += 4) {
        float sv0 = S[sbase + (size_t)(d + 0) * cDVH];
        float sv1 = S[sbase + (size_t)(d + 1) * cDVH];
        float sv2 = S[sbase + (size_t)(d + 2) * cDVH];
        float sv3 = S[sbase + (size_t)(d + 3) * cDVH];
#pragma unroll
        for (int i = 0; i < cCH; i++) {
            float4 qv = *(const float4*)&s_q[i * 128 + d];
            acc[i] += qv.x * sv0 + qv.y * sv1 + qv.z * sv2 + qv.w * sv3;
        }
    }
#pragma unroll
    for (int i = 0; i < cCH; i++) {
        size_t offo = obase + (size_t)i * cDV + u;
        float ov = (po[offo] + acc[i]) * pgate[gbase + (size_t)i * PSTR + u];
        __nv_bfloat16 hbf, lbf; bsplit(ov, hbf, lbf);
        oh[offo] = hbf; ol[offo] = lbf;
    }
}

// ---------------- LoRA ----------------
__global__ void __launch_bounds__(256) k_lora_down(const float* __restrict__ g, const float* __restrict__ A,
                                                   float* __restrict__ out) {
    int warp = threadIdx.x >> 5, lane = threadIdx.x & 31;
    int m = blockIdx.x * 8 + warp;
    const float* grow = &g[(size_t)m * cD];
    float acc[cRANK];
#pragma unroll
    for (int r = 0; r < cRANK; r++) acc[r] = 0.f;
    for (int kk = lane; kk < cD; kk += 32) {
        float a = grow[kk];
        const float4* Ap = (const float4*)&A[(size_t)kk * cRANK];
        float4 b0 = Ap[0], b1 = Ap[1], b2 = Ap[2], b3 = Ap[3];
        acc[0] += a * b0.x; acc[1] += a * b0.y; acc[2] += a * b0.z; acc[3] += a * b0.w;
        acc[4] += a * b1.x; acc[5] += a * b1.y; acc[6] += a * b1.z; acc[7] += a * b1.w;
        acc[8] += a * b2.x; acc[9] += a * b2.y; acc[10] += a * b2.z; acc[11] += a * b2.w;
        acc[12] += a * b3.x; acc[13] += a * b3.y; acc[14] += a * b3.z; acc[15] += a * b3.w;
    }
#pragma unroll
    for (int r = 0; r < cRANK; r++)
        for (int s = 16; s > 0; s >>= 1) acc[r] += __shfl_xor_sync(0xffffffffu, acc[r], s);
    if (lane == 0) {
#pragma unroll
        for (int r = 0; r < cRANK; r++) out[(size_t)m * cRANK + r] = acc[r];
    }
}
__global__ void __launch_bounds__(256) k_lora_up(const float* __restrict__ tmp, const float* __restrict__ Bm,
                                                 const float* __restrict__ einj, float* __restrict__ g) {
    int idx = blockIdx.x * 256 + threadIdx.x;
    int m = idx >> 10, n = idx & 1023;
    const float* tr = &tmp[(size_t)m * cRANK];
    float s = 0.f;
#pragma unroll
    for (int r = 0; r < cRANK; r++) s += tr[r] * Bm[r * cD + n];
    g[idx] += s + einj[idx];
}

// ---------------- ACT halting ----------------
__global__ void __launch_bounds__(256) k_act(const float* __restrict__ hnew, const float* __restrict__ act_w,
                                             const float* __restrict__ act_b, float* __restrict__ h,
                                             float* __restrict__ hout, float* __restrict__ cum,
                                             float* __restrict__ halt) {
    int row = blockIdx.x; size_t base = (size_t)row * cD;
    int tid = threadIdx.x;
    float ss = 0.f;
#pragma unroll
    for (int i = 0; i < 4; i++) {
        int c = tid + i * 256;
        ss += hnew[base + c] * act_w[c];
    }
    __shared__ float red[256]; __shared__ float wsh;
    red[tid] = ss; __syncthreads();
    for (int s = 128; s > 0; s >>= 1) { if (tid < s) red[tid] += red[tid + s]; __syncthreads(); }
    if (tid == 0) {
        float z = red[0] + act_b[0];
        float p = 1.f / (1.f + expf(-z));
        float cm = cum[row]; float hl = halt[row];
        float p_eff = (hl > 0.5f) ? 0.f : p;
        float ncum = cm + p_eff;
        bool newly = (hl < 0.5f) && (ncum >= 0.99f);
        float w = newly ? (1.f - cm) : p_eff;
        cum[row] = ncum;
        if (newly) halt[row] = 1.f;
        wsh = w;
    }
    __syncthreads();
    float w = wsh;
#pragma unroll
    for (int i = 0; i < 4; i++) {
        int c = tid + i * 256;
        float v = hnew[base + c];
        hout[base + c] += w * v;
        h[base + c] = v;
    }
}

// ---------------- host ----------------
static void gemmB(const __nv_bfloat16* Ah, const __nv_bfloat16* Al,
                  const __nv_bfloat16* Bh, const __nv_bfloat16* Bl,
                  float* C, const float* Ci, int M, int N, int K, float scale, int epi) {
    dim3 g(N / GTN, M / GTM);
    gemm_bf16<<<g, 256, GEMM_SMEM>>>(Ah, Al, Bh, Bl, C, Ci, M, N, K, scale, epi);
}

extern "C" void kernel_launch(void* const* d_in, const int* in_sizes, int n_in,
                              void* d_out, int out_size) {
    const float* in_h  = (const float*)d_in[0];
    const float* in_e  = (const float*)d_in[1];
    const float* nw    = (const float*)d_in[2];
    const float* onw   = (const float*)d_in[3];
    const float* Wq    = (const float*)d_in[4];
    const float* Wk    = (const float*)d_in[5];
    const float* Wv    = (const float*)d_in[6];
    const float* Wgk   = (const float*)d_in[7];
    const float* Wg    = (const float*)d_in[8];
    const float* Wo    = (const float*)d_in[9];
    const float* loraA = (const float*)d_in[10];
    const float* loraB = (const float*)d_in[11];
    const float* injA  = (const float*)d_in[12];
    const float* injB  = (const float*)d_in[13];
    const float* act_w = (const float*)d_in[14];
    const float* act_b = (const float*)d_in[15];
    const float* ltab  = (const float*)d_in[16];
    float* out = (float*)d_out;

    float *p_h, *p_proj, *p_o, *p_kv, *p_S, *p_bdec,
          *p_gla, *p_lora, *p_hnew, *p_hout, *p_cum, *p_halt, *p_einj;
    cudaGetSymbolAddress((void**)&p_h, g_h);
    cudaGetSymbolAddress((void**)&p_proj, g_proj);
    cudaGetSymbolAddress((void**)&p_o, g_o);
    cudaGetSymbolAddress((void**)&p_kv, g_kv);
    cudaGetSymbolAddress((void**)&p_S, g_S);
    cudaGetSymbolAddress((void**)&p_bdec, g_bdec);
    cudaGetSymbolAddress((void**)&p_gla, g_gla);
    cudaGetSymbolAddress((void**)&p_lora, g_lora);
    cudaGetSymbolAddress((void**)&p_hnew, g_hnew);
    cudaGetSymbolAddress((void**)&p_hout, g_hout);
    cudaGetSymbolAddress((void**)&p_cum, g_cum);
    cudaGetSymbolAddress((void**)&p_halt, g_halt);
    cudaGetSymbolAddress((void**)&p_einj, g_einj);

    __nv_bfloat16 *wph, *wpl, *woh, *wol, *iah, *ial, *ibh, *ibl,
                  *eh, *el, *xh, *xl, *hh, *hl, *oh, *ol;
    cudaGetSymbolAddress((void**)&wph, g_wph);  cudaGetSymbolAddress((void**)&wpl, g_wpl);
    cudaGetSymbolAddress((void**)&woh, g_woh);  cudaGetSymbolAddress((void**)&wol, g_wol);
    cudaGetSymbolAddress((void**)&iah, g_iah);  cudaGetSymbolAddress((void**)&ial, g_ial);
    cudaGetSymbolAddress((void**)&ibh, g_ibh);  cudaGetSymbolAddress((void**)&ibl, g_ibl);
    cudaGetSymbolAddress((void**)&eh, g_eh);    cudaGetSymbolAddress((void**)&el, g_el);
    cudaGetSymbolAddress((void**)&xh, g_xh);    cudaGetSymbolAddress((void**)&xl, g_xl);
    cudaGetSymbolAddress((void**)&hh, g_hh2);   cudaGetSymbolAddress((void**)&hl, g_hl2);
    cudaGetSymbolAddress((void**)&oh, g_oh);    cudaGetSymbolAddress((void**)&ol, g_ol);

    cudaFuncSetAttribute(k_chunk, cudaFuncAttributeMaxDynamicSharedMemorySize, SMEM_CHUNK);
    cudaFuncSetAttribute(gemm_bf16, cudaFuncAttributeMaxDynamicSharedMemorySize, GEMM_SMEM);

    const int nBig = cM * cD / 256;
    k_copy<<<nBig, 256>>>(p_h, in_h);
    k_zero<<<nBig, 256>>>(p_hout);
    k_zero_state<<<cM / 256, 256>>>(p_cum, p_halt);

    // packed projection weight: rows [0,1024)=Wq^T, [1024,2048)=Wk^T, [2048,3072)=Wgk^T,
    // [3072,5120)=Wv^T, [5120,7168)=Wg^T   (all [N,K=1024] bf16 hi/lo)
    dim3 tb(32, 8);
    k_wconvT<<<dim3(cDK / 32, cD / 32), tb>>>(Wq,  wph,                    wpl,                    cD, cDK);
    k_wconvT<<<dim3(cDK / 32, cD / 32), tb>>>(Wk,  wph + (size_t)OFF_K  * cD, wpl + (size_t)OFF_K  * cD, cD, cDK);
    k_wconvT<<<dim3(cDK / 32, cD / 32), tb>>>(Wgk, wph + (size_t)OFF_LA * cD, wpl + (size_t)OFF_LA * cD, cD, cDK);
    k_wconvT<<<dim3(cDV / 32, cD / 32), tb>>>(Wv,  wph + (size_t)OFF_V  * cD, wpl + (size_t)OFF_V  * cD, cD, cDV);
    k_wconvT<<<dim3(cDV / 32, cD / 32), tb>>>(Wg,  wph + (size_t)OFF_G  * cD, wpl + (size_t)OFF_G  * cD, cD, cDV);
    k_wconvT<<<dim3(cD / 32, cDV / 32), tb>>>(Wo,  woh, wol, cDV, cD);
    k_split<<<cD * cD / 1024, 256>>>(injA, iah, ial);
    k_split<<<cD * cD / 1024, 256>>>(injB, ibh, ibl);
    k_split<<<cM * cD / 1024, 256>>>(in_e, eh, el);

    // loop-invariant: einj = e @ injB^T
    gemmB(eh, el, ibh, ibl, p_einj, nullptr, cM, cD, cD, 0.f, 0);

    const float qscale = 0.08838834764831845f;

    for (int t = 0; t < cNL; t++) {
        k_prep<<<cM, 256>>>(p_h, in_e, nw, ltab + t * cLOOPD, xh, xl, hh, hl);

        // single merged projection GEMM: q|k|la|v|gate with per-segment epilogue
        gemmB(xh, xl, wph, wpl, p_proj, nullptr, cM, PSTR, cD, qscale, 9);

        k_chunk<<<cNC * cBH, 256, SMEM_CHUNK>>>(p_proj, p_proj + OFF_K, p_proj + OFF_LA,
                                                p_proj + OFF_V, p_o, p_kv, p_bdec);
        k_state<<<cBH * 8, 256>>>(p_kv, p_bdec, p_S);
        k_inter<<<cNC * cBH, 256>>>(p_proj, p_S, p_o, p_proj + OFF_G, oh, ol);

        gemmB(oh, ol, woh, wol, p_gla, nullptr, cM, cD, cDV, 0.f, 0);

        k_lora_down<<<cM / 8, 256>>>(p_gla, loraA + (size_t)t * cD * cRANK, p_lora);
        k_lora_up<<<nBig, 256>>>(p_lora, loraB + (size_t)t * cRANK * cD, p_einj, p_gla);

        gemmB(hh, hl, iah, ial, p_hnew, p_gla, cM, cD, cD, 0.f, 0);

        k_act<<<cM, 256>>>(p_hnew, act_w, act_b, p_h, p_hout, p_cum, p_halt);
    }
    k_rmsnorm<<<cM, 256>>>(p_hout, onw, out);
}

// round 10
// speedup vs baseline: 1.5596x; 1.5596x over previous
#include <cuda_runtime.h>
#include <cuda_bf16.h>
#include <math.h>
#include <stdint.h>

// ---------------- problem constants ----------------
constexpr int cB = 4, cT = 4096, cD = 1024, cH = 8;
constexpr int cDK = 1024, cDV = 2048, cDKH = 128, cDVH = 256;
constexpr int cRANK = 16, cLOOPD = 128, cNL = 4;
constexpr int cCH = 64;
constexpr int cNC = cT / cCH;
constexpr int cBH = cB * cH;
constexpr int cM = cB * cT;
constexpr int PSTR = 7168;              // merged projection row stride (q|k|la|v|gate)
constexpr int OFF_K = 1024, OFF_LA = 2048, OFF_V = 3072, OFF_G = 5120;

// ---------------- device scratch ----------------
__device__ float g_h[cM * cD];
__device__ float g_proj[(size_t)cM * PSTR];
__device__ float g_o[cM * cDV];
__device__ float g_kv[cNC * cBH * cDKH * cDVH];
__device__ float g_S[cNC * cBH * cDKH * cDVH];
__device__ float g_bdec[cNC * cBH * cDKH];
__device__ float g_gla[cM * cD];
__device__ float g_lora[cM * cRANK];
__device__ float g_hnew[cM * cD];
__device__ float g_hout[cM * cD];
__device__ float g_cum[cM];
__device__ float g_halt[cM];
__device__ float g_einj[cM * cD];

// bf16 hi/lo buffers
__device__ __align__(16) __nv_bfloat16 g_wph[(size_t)PSTR * cD], g_wpl[(size_t)PSTR * cD];
__device__ __align__(16) __nv_bfloat16 g_woh[cDV * cD],  g_wol[cDV * cD];
__device__ __align__(16) __nv_bfloat16 g_iah[cD * cD],   g_ial[cD * cD];
__device__ __align__(16) __nv_bfloat16 g_ibh[cD * cD],   g_ibl[cD * cD];
__device__ __align__(16) __nv_bfloat16 g_eh[cM * cD],    g_el[cM * cD];
__device__ __align__(16) __nv_bfloat16 g_xh[cM * cD],    g_xl[cM * cD];
__device__ __align__(16) __nv_bfloat16 g_hh2[cM * cD],   g_hl2[cM * cD];
__device__ __align__(16) __nv_bfloat16 g_oh[cM * cDV],   g_ol[cM * cDV];

// ---------------- helpers ----------------
__device__ __forceinline__ uint32_t s2u(const void* p) {
    uint32_t a;
    asm("{ .reg .u64 t; cvta.to.shared.u64 t, %1; cvt.u32.u64 %0, t; }" : "=r"(a) : "l"(p));
    return a;
}
__device__ __forceinline__ uint32_t sw128(uint32_t off) { return off ^ ((off >> 3) & 0x70); }

#define LDSM4(r, a) \
    asm volatile("ldmatrix.sync.aligned.m8n8.x4.shared.b16 {%0,%1,%2,%3}, [%4];" \
        : "=r"((r)[0]), "=r"((r)[1]), "=r"((r)[2]), "=r"((r)[3]) : "r"(a))

__device__ __forceinline__ void mma_bf16(float* d, const uint32_t* a, const uint32_t* b) {
    asm volatile("mma.sync.aligned.m16n8k16.row.col.f32.bf16.bf16.f32 "
        "{%0,%1,%2,%3}, {%4,%5,%6,%7}, {%8,%9}, {%0,%1,%2,%3};"
        : "+f"(d[0]), "+f"(d[1]), "+f"(d[2]), "+f"(d[3])
        : "r"(a[0]), "r"(a[1]), "r"(a[2]), "r"(a[3]), "r"(b[0]), "r"(b[1]));
}

// ---------------- mma.sync bf16 hi/lo GEMM, 2 CTAs/SM, panel raster ----------------
// A:[M,K] hi/lo row-major; B:[N,K] hi/lo K-major. CTA tile 128x128, K-chunk 32.
// 1D grid; CTAs m-major within 8-wide n-panels (B panel stays L2-resident).
// epi: 0 none, 1 scale, 2 logsig/16, 3 silu, 9 merged-projection per-segment.
constexpr int GTM = 128, GTN = 128, GKC = 32;
constexpr int TILE_B2 = 16384;
constexpr int STG_B = 2 * TILE_B2;        // 32KB
constexpr int NSTG = 3;
constexpr int GEMM_SMEM = NSTG * STG_B;   // 98304

__global__ void __launch_bounds__(256, 2) gemm_bf16(
    const __nv_bfloat16* __restrict__ Ah, const __nv_bfloat16* __restrict__ Al,
    const __nv_bfloat16* __restrict__ Bh, const __nv_bfloat16* __restrict__ Bl,
    float* __restrict__ C, const float* __restrict__ Ci,
    int M, int N, int K, float scale, int epi)
{
    extern __shared__ char smem[];
    int tid = threadIdx.x;
    int lane = tid & 31, wid = tid >> 5;

    // panel rasterization: m-major within 8-wide n-panels
    int mbCnt = M >> 7;
    int per_panel = mbCnt * 8;
    int panel = blockIdx.x / per_panel;
    int rem = blockIdx.x - panel * per_panel;
    int bm = rem >> 3;
    int bn = panel * 8 + (rem & 7);
    int m0 = bm * GTM, n0 = bn * GTN;

    int wm = (wid & 3) * 32, wn = (wid >> 2) * 64;

    const int NCk = K / GKC;

    const __nv_bfloat16* pA[2] = { Ah + (size_t)m0 * K, Al + (size_t)m0 * K };
    const __nv_bfloat16* pB[2] = { Bh + (size_t)n0 * K, Bl + (size_t)n0 * K };

    auto load_stage = [&](int kc, int s) {
        char* base = smem + s * STG_B;
        int k0 = kc * GKC;
#pragma unroll
        for (int i = 0; i < 8; i++) {
            int gg = tid + i * 256;            // 0..2047
            int tile = gg >> 10;               // 0 A, 1 B
            int idx = gg & 1023;
            int r = idx >> 3, seg = idx & 7;
            int hl = seg >> 2, s4 = seg & 3;
            uint32_t off = sw128((uint32_t)(r * 128 + hl * 64 + s4 * 16));
            const __nv_bfloat16* src = (tile ? pB[hl] : pA[hl]) + (size_t)r * K + k0 + s4 * 8;
            uint32_t dst = s2u(base + tile * TILE_B2 + off);
            asm volatile("cp.async.cg.shared.global [%0], [%1], 16;" :: "r"(dst), "l"(src));
        }
        asm volatile("cp.async.commit_group;" ::: "memory");
    };

    float acc[2][8][4];
#pragma unroll
    for (int mf = 0; mf < 2; mf++)
#pragma unroll
        for (int nf = 0; nf < 8; nf++)
#pragma unroll
            for (int j = 0; j < 4; j++) acc[mf][nf][j] = 0.f;

    load_stage(0, 0);
    load_stage(1, 1);
    load_stage(2, 2);

    int a_row = (lane & 15);
    int a_col8 = (lane >> 4);
    int b_row = (lane & 7) + ((lane >> 4) & 1) * 8;
    int b_col8 = (lane >> 3) & 1;

    for (int c = 0; c < NCk; c++) {
        asm volatile("cp.async.wait_group 2;" ::: "memory");
        __syncthreads();
        char* base = smem + (c % 3) * STG_B;
        uint32_t sA = s2u(base), sB = sA + TILE_B2;
#pragma unroll
        for (int kk = 0; kk < 2; kk++) {
            int k0 = kk * 16;
            uint32_t ah[2][4], al[2][4];
#pragma unroll
            for (int mf = 0; mf < 2; mf++) {
                uint32_t rowb = (uint32_t)((wm + mf * 16 + a_row) * 128);
                uint32_t kb = (uint32_t)((k0 + a_col8 * 8) * 2);
                LDSM4(ah[mf], sA + sw128(rowb + kb));
                LDSM4(al[mf], sA + sw128(rowb + 64 + kb));
            }
#pragma unroll
            for (int h = 0; h < 2; h++) {      // two nf-halves to cap live regs
                uint32_t bh[4][2], bl[4][2];
#pragma unroll
                for (int nf2 = 0; nf2 < 2; nf2++) {
                    int nf = h * 2 + nf2;
                    uint32_t rowb = (uint32_t)((wn + nf * 16 + b_row) * 128);
                    uint32_t kb = (uint32_t)((k0 + b_col8 * 8) * 2);
                    uint32_t r[4];
                    LDSM4(r, sB + sw128(rowb + kb));
                    bh[nf2 * 2][0] = r[0]; bh[nf2 * 2][1] = r[1];
                    bh[nf2 * 2 + 1][0] = r[2]; bh[nf2 * 2 + 1][1] = r[3];
                    LDSM4(r, sB + sw128(rowb + 64 + kb));
                    bl[nf2 * 2][0] = r[0]; bl[nf2 * 2][1] = r[1];
                    bl[nf2 * 2 + 1][0] = r[2]; bl[nf2 * 2 + 1][1] = r[3];
                }
#pragma unroll
                for (int mf = 0; mf < 2; mf++)
#pragma unroll
                    for (int n8 = 0; n8 < 4; n8++) {
                        float* a4 = acc[mf][h * 4 + n8];
                        mma_bf16(a4, ah[mf], bh[n8]);
                        mma_bf16(a4, ah[mf], bl[n8]);
                        mma_bf16(a4, al[mf], bh[n8]);
                    }
            }
        }
        __syncthreads();
        if (c + 3 < NCk) load_stage(c + 3, c % 3);
        else asm volatile("cp.async.commit_group;" ::: "memory");
    }

    const float qsc = scale;
#pragma unroll
    for (int mf = 0; mf < 2; mf++) {
#pragma unroll
        for (int nf = 0; nf < 8; nf++) {
            int r0 = m0 + wm + mf * 16 + (lane >> 2);
            int cc = n0 + wn + nf * 8 + (lane & 3) * 2;
#pragma unroll
            for (int hh = 0; hh < 2; hh++) {
                int r = r0 + hh * 8;
                float vx = acc[mf][nf][hh * 2], vy = acc[mf][nf][hh * 2 + 1];
                size_t off = (size_t)r * N + cc;
                if (Ci) { vx += Ci[off]; vy += Ci[off + 1]; }
                int e = epi;
                if (e == 9) {
                    int seg = cc >> 10;
                    e = (seg == 0) ? 1 : (seg == 2) ? 2 : (seg >= 5) ? 3 : 0;
                }
                if (e == 1) { vx *= qsc; vy *= qsc; }
                else if (e == 2) {
                    vx = (fminf(vx, 0.f) - log1pf(expf(-fabsf(vx)))) * 0.0625f;
                    vy = (fminf(vy, 0.f) - log1pf(expf(-fabsf(vy)))) * 0.0625f;
                } else if (e == 3) {
                    vx = vx / (1.f + expf(-vx));
                    vy = vy / (1.f + expf(-vy));
                }
                *(float2*)&C[off] = make_float2(vx, vy);
            }
        }
    }
}

// ---------------- utility kernels ----------------
__global__ void k_copy(float* __restrict__ dst, const float* __restrict__ src) {
    int idx = blockIdx.x * 256 + threadIdx.x;
    dst[idx] = src[idx];
}
__global__ void k_zero(float* __restrict__ dst) {
    int idx = blockIdx.x * 256 + threadIdx.x;
    dst[idx] = 0.f;
}
__global__ void k_zero_state(float* __restrict__ cum, float* __restrict__ halt) {
    int idx = blockIdx.x * 256 + threadIdx.x;
    cum[idx] = 0.f; halt[idx] = 0.f;
}

__device__ __forceinline__ void bsplit(float x, __nv_bfloat16& h, __nv_bfloat16& l) {
    h = __float2bfloat16(x);
    l = __float2bfloat16(x - __bfloat162float(h));
}

__global__ void k_split(const float* __restrict__ src, __nv_bfloat16* __restrict__ hi,
                        __nv_bfloat16* __restrict__ lo) {
    size_t i4 = ((size_t)blockIdx.x * 256 + threadIdx.x) * 4;
    float4 v = *(const float4*)(src + i4);
    __nv_bfloat16 h0, h1, h2, h3, l0, l1, l2, l3;
    bsplit(v.x, h0, l0); bsplit(v.y, h1, l1); bsplit(v.z, h2, l2); bsplit(v.w, h3, l3);
    hi[i4] = h0; hi[i4+1] = h1; hi[i4+2] = h2; hi[i4+3] = h3;
    lo[i4] = l0; lo[i4+1] = l1; lo[i4+2] = l2; lo[i4+3] = l3;
}
// transpose-convert: W [K,N] fp32 -> out [N,K] bf16 hi/lo (out row stride K)
__global__ void k_wconvT(const float* __restrict__ W, __nv_bfloat16* __restrict__ hi,
                         __nv_bfloat16* __restrict__ lo, int K, int N) {
    __shared__ float s[32][33];
    int n0 = blockIdx.x * 32, k0 = blockIdx.y * 32;
    int tx = threadIdx.x, ty = threadIdx.y;
#pragma unroll
    for (int i = 0; i < 4; i++) {
        int r = ty + i * 8;
        s[r][tx] = W[(size_t)(k0 + r) * N + n0 + tx];
    }
    __syncthreads();
#pragma unroll
    for (int i = 0; i < 4; i++) {
        int r = ty + i * 8;
        float v = s[tx][r];
        size_t o = (size_t)(n0 + r) * K + k0 + tx;
        __nv_bfloat16 h, l; bsplit(v, h, l);
        hi[o] = h; lo[o] = l;
    }
}

// ---------------- fused loop-embed + rmsnorm(h+e) + bf16 splits ----------------
__global__ void __launch_bounds__(256) k_prep(float* __restrict__ h, const float* __restrict__ e,
                                              const float* __restrict__ nw, const float* __restrict__ ltab,
                                              __nv_bfloat16* __restrict__ xh, __nv_bfloat16* __restrict__ xl,
                                              __nv_bfloat16* __restrict__ hh, __nv_bfloat16* __restrict__ hl) {
    int row = blockIdx.x; size_t base = (size_t)row * cD;
    int tid = threadIdx.x;
    if (tid < cLOOPD) h[base + tid] += ltab[tid];
    __syncthreads();
    float hv[4], vals[4]; float ss = 0.f;
#pragma unroll
    for (int i = 0; i < 4; i++) {
        int c = tid + i * 256;
        float hx = h[base + c];
        hv[i] = hx;
        float v = hx + e[base + c];
        vals[i] = v; ss += v * v;
    }
    __shared__ float red[256];
    red[tid] = ss; __syncthreads();
    for (int s = 128; s > 0; s >>= 1) { if (tid < s) red[tid] += red[tid + s]; __syncthreads(); }
    float rs = rsqrtf(red[0] * (1.f / cD) + 1e-6f);
#pragma unroll
    for (int i = 0; i < 4; i++) {
        int c = tid + i * 256;
        float x = vals[i] * rs * nw[c];
        __nv_bfloat16 a, b;
        bsplit(x, a, b); xh[base + c] = a; xl[base + c] = b;
        bsplit(hv[i], a, b); hh[base + c] = a; hl[base + c] = b;
    }
}

// ---------------- final rmsnorm ----------------
__global__ void __launch_bounds__(256) k_rmsnorm(const float* __restrict__ in, const float* __restrict__ nw,
                                                 float* __restrict__ out) {
    int row = blockIdx.x; size_t base = (size_t)row * cD;
    int tid = threadIdx.x;
    float vals[4]; float ss = 0.f;
#pragma unroll
    for (int i = 0; i < 4; i++) {
        int c = tid + i * 256;
        float v = in[base + c];
        vals[i] = v; ss += v * v;
    }
    __shared__ float red[256];
    red[tid] = ss; __syncthreads();
    for (int s = 128; s > 0; s >>= 1) { if (tid < s) red[tid] += red[tid + s]; __syncthreads(); }
    float rs = rsqrtf(red[0] * (1.f / cD) + 1e-6f);
#pragma unroll
    for (int i = 0; i < 4; i++) {
        int c = tid + i * 256;
        out[base + c] = vals[i] * rs * nw[c];
    }
}

// ---------------- GLA chunk kernel ----------------
constexpr int SMEM_CHUNK = 49408 * 4;
__global__ void __launch_bounds__(256) k_chunk(float* __restrict__ pq, const float* __restrict__ pk,
                                               const float* __restrict__ pla, const float* __restrict__ pv,
                                               float* __restrict__ po, float* __restrict__ pkv,
                                               float* __restrict__ pbdec) {
    extern __shared__ float sm[];
    float* s_cum = sm;
    float* s_qt = sm + 8192;
    float* s_kt = sm + 16384;     // stride 132
    float* s_kc = sm + 24832;
    float* s_v  = sm + 33024;
    float* s_A  = sm;

    int cidx = blockIdx.x;
    int c = cidx / cBH, bh = cidx - c * cBH;
    int b = bh >> 3, hh = bh & 7;
    int t0 = c * cCH;
    size_t qbase = ((size_t)b * cT + t0) * PSTR + hh * cDKH;
    size_t vbase = ((size_t)b * cT + t0) * PSTR + hh * cDVH;
    size_t obase = ((size_t)b * cT + t0) * cDV + hh * cDVH;
    int tid = threadIdx.x;

    if (tid < 128) {
        int d = tid;
        float cum = 0.f;
        for (int i = 0; i < cCH; i++) {
            size_t off = qbase + (size_t)i * PSTR + d;
            cum += pla[off];
            s_cum[i * 128 + d] = cum;
            s_qt[i * 128 + d] = pq[off] * expf(cum);
            s_kt[i * 132 + d] = pk[off] * expf(-cum);
            s_kc[i * 128 + d] = pk[off];
        }
        float latot = cum;
        pbdec[(size_t)cidx * cDKH + d] = expf(latot);
        for (int i = 0; i < cCH; i++)
            s_kc[i * 128 + d] *= expf(latot - s_cum[i * 128 + d]);
        for (int i = 0; i < cCH; i++)
            pq[qbase + (size_t)i * PSTR + d] = s_qt[i * 128 + d];
    } else {
        int lt = tid - 128;
        for (int l = 0; l < 32; l++) {
            int idx4 = lt + l * 128;
            int i = idx4 >> 6;
            int u4 = (idx4 & 63) * 4;
            *(float4*)&s_v[i * 256 + u4] = *(const float4*)&pv[vbase + (size_t)i * PSTR + u4];
        }
    }
    __syncthreads();

    for (int idx = tid; idx < cCH * cCH; idx += 256) {
        int i = idx >> 6, j = idx & 63;
        float sum = 0.f;
        if (j <= i) {
            const float* qp = &s_qt[i * 128];
            const float* kp = &s_kt[j * 132];
#pragma unroll
            for (int d = 0; d < 128; d += 4) {
                float4 qa = *(const float4*)&qp[d];
                float4 kb = *(const float4*)&kp[d];
                sum += qa.x * kb.x + qa.y * kb.y + qa.z * kb.z + qa.w * kb.w;
            }
        }
        s_A[idx] = sum;
    }
    __syncthreads();

    // O_intra = A @ V
    {
        int uq = tid & 63;
        int il = tid >> 6;
#pragma unroll 1
        for (int step = 0; step < 16; step++) {
            int i = il + step * 4;
            float4 acc = make_float4(0.f, 0.f, 0.f, 0.f);
            const float* arow = &s_A[i * 64];
            for (int j = 0; j <= i; j++) {
                float a = arow[j];
                float4 vv = *(const float4*)&s_v[j * 256 + uq * 4];
                acc.x += a * vv.x; acc.y += a * vv.y; acc.z += a * vv.z; acc.w += a * vv.w;
            }
            *(float4*)&po[obase + (size_t)i * cDV + uq * 4] = acc;
        }
    }

    // KV_c = kc^T @ V
    {
#pragma unroll 1
        for (int s = 0; s < 8; s++) {
            int idx = tid + s * 256;
            int dq = idx >> 6;
            int uq = idx & 63;
            float4 a0 = make_float4(0.f,0.f,0.f,0.f), a1 = a0, a2 = a0, a3 = a0;
#pragma unroll 4
            for (int j = 0; j < cCH; j++) {
                float4 kc = *(const float4*)&s_kc[j * 128 + dq * 4];
                float4 vv = *(const float4*)&s_v[j * 256 + uq * 4];
                a0.x += kc.x * vv.x; a0.y += kc.x * vv.y; a0.z += kc.x * vv.z; a0.w += kc.x * vv.w;
                a1.x += kc.y * vv.x; a1.y += kc.y * vv.y; a1.z += kc.y * vv.z; a1.w += kc.y * vv.w;
                a2.x += kc.z * vv.x; a2.y += kc.z * vv.y; a2.z += kc.z * vv.z; a2.w += kc.z * vv.w;
                a3.x += kc.w * vv.x; a3.y += kc.w * vv.y; a3.z += kc.w * vv.z; a3.w += kc.w * vv.w;
            }
            size_t kvbase = (size_t)cidx * (cDKH * cDVH) + (size_t)(dq * 4) * cDVH + uq * 4;
            *(float4*)&pkv[kvbase]            = a0;
            *(float4*)&pkv[kvbase + cDVH]     = a1;
            *(float4*)&pkv[kvbase + 2 * cDVH] = a2;
            *(float4*)&pkv[kvbase + 3 * cDVH] = a3;
        }
    }
}

// ---------------- state propagation ----------------
__global__ void __launch_bounds__(256) k_state(const float* __restrict__ pkv, const float* __restrict__ pbdec,
                                               float* __restrict__ Sout) {
    int blk = blockIdx.x;
    int bh = blk >> 3;
    int vs = (blk & 7) * 32;
    int tid = threadIdx.x;
    int kr = tid >> 1;
    int vofs = vs + (tid & 1) * 16;
    float S[16];
#pragma unroll
    for (int j = 0; j < 16; j++) S[j] = 0.f;
    for (int c = 0; c < cNC; c++) {
        size_t base = ((size_t)c * cBH + bh) * (cDKH * cDVH) + (size_t)kr * cDVH + vofs;
        float bd = pbdec[((size_t)c * cBH + bh) * cDKH + kr];
#pragma unroll
        for (int j = 0; j < 16; j += 4) {
            *(float4*)&Sout[base + j] = make_float4(S[j], S[j + 1], S[j + 2], S[j + 3]);
            float4 kvv = *(const float4*)&pkv[base + j];
            S[j]     = bd * S[j]     + kvv.x;
            S[j + 1] = bd * S[j + 1] + kvv.y;
            S[j + 2] = bd * S[j + 2] + kvv.z;
            S[j + 3] = bd * S[j + 3] + kvv.w;
        }
    }
}

// ---------------- inter-chunk output + fused gate + bf16 split ----------------
__global__ void __launch_bounds__(256) k_inter(const float* __restrict__ pq, const float* __restrict__ S,
                                               const float* __restrict__ po, const float* __restrict__ pgate,
                                               __nv_bfloat16* __restrict__ oh, __nv_bfloat16* __restrict__ ol) {
    __shared__ float s_q[cCH * cDKH];
    int cidx = blockIdx.x;
    int c = cidx / cBH, bh = cidx - c * cBH;
    int b = bh >> 3, hh = bh & 7;
    int t0 = c * cCH;
    size_t qbase = ((size_t)b * cT + t0) * PSTR + hh * cDKH;
    size_t gbase = ((size_t)b * cT + t0) * PSTR + hh * cDVH;
    size_t obase = ((size_t)b * cT + t0) * cDV + hh * cDVH;
    int tid = threadIdx.x;
#pragma unroll
    for (int l = 0; l < 8; l++) {
        int idx4 = tid + l * 256;
        int i = idx4 >> 5;
        int d4 = (idx4 & 31) * 4;
        *(float4*)&s_q[i * 128 + d4] = *(const float4*)&pq[qbase + (size_t)i * PSTR + d4];
    }
    __syncthreads();
    int u = tid;
    float acc[cCH];
#pragma unroll
    for (int i = 0; i < cCH; i++) acc[i] = 0.f;
    size_t sbase = (size_t)cidx * (cDKH * cDVH) + u;
    for (int d = 0; d < cDKH; d += 4) {
        float sv0 = S[sbase + (size_t)(d + 0) * cDVH];
        float sv1 = S[sbase + (size_t)(d + 1) * cDVH];
        float sv2 = S[sbase + (size_t)(d + 2) * cDVH];
        float sv3 = S[sbase + (size_t)(d + 3) * cDVH];
#pragma unroll
        for (int i = 0; i < cCH; i++) {
            float4 qv = *(const float4*)&s_q[i * 128 + d];
            acc[i] += qv.x * sv0 + qv.y * sv1 + qv.z * sv2 + qv.w * sv3;
        }
    }
#pragma unroll
    for (int i = 0; i < cCH; i++) {
        size_t offo = obase + (size_t)i * cDV + u;
        float ov = (po[offo] + acc[i]) * pgate[gbase + (size_t)i * PSTR + u];
        __nv_bfloat16 hbf, lbf; bsplit(ov, hbf, lbf);
        oh[offo] = hbf; ol[offo] = lbf;
    }
}

// ---------------- LoRA ----------------
__global__ void __launch_bounds__(256) k_lora_down(const float* __restrict__ g, const float* __restrict__ A,
                                                   float* __restrict__ out) {
    int warp = threadIdx.x >> 5, lane = threadIdx.x & 31;
    int m = blockIdx.x * 8 + warp;
    const float* grow = &g[(size_t)m * cD];
    float acc[cRANK];
#pragma unroll
    for (int r = 0; r < cRANK; r++) acc[r] = 0.f;
    for (int kk = lane; kk < cD; kk += 32) {
        float a = grow[kk];
        const float4* Ap = (const float4*)&A[(size_t)kk * cRANK];
        float4 b0 = Ap[0], b1 = Ap[1], b2 = Ap[2], b3 = Ap[3];
        acc[0] += a * b0.x; acc[1] += a * b0.y; acc[2] += a * b0.z; acc[3] += a * b0.w;
        acc[4] += a * b1.x; acc[5] += a * b1.y; acc[6] += a * b1.z; acc[7] += a * b1.w;
        acc[8] += a * b2.x; acc[9] += a * b2.y; acc[10] += a * b2.z; acc[11] += a * b2.w;
        acc[12] += a * b3.x; acc[13] += a * b3.y; acc[14] += a * b3.z; acc[15] += a * b3.w;
    }
#pragma unroll
    for (int r = 0; r < cRANK; r++)
        for (int s = 16; s > 0; s >>= 1) acc[r] += __shfl_xor_sync(0xffffffffu, acc[r], s);
    if (lane == 0) {
#pragma unroll
        for (int r = 0; r < cRANK; r++) out[(size_t)m * cRANK + r] = acc[r];
    }
}
__global__ void __launch_bounds__(256) k_lora_up(const float* __restrict__ tmp, const float* __restrict__ Bm,
                                                 const float* __restrict__ einj, float* __restrict__ g) {
    int idx = blockIdx.x * 256 + threadIdx.x;
    int m = idx >> 10, n = idx & 1023;
    const float* tr = &tmp[(size_t)m * cRANK];
    float s = 0.f;
#pragma unroll
    for (int r = 0; r < cRANK; r++) s += tr[r] * Bm[r * cD + n];
    g[idx] += s + einj[idx];
}

// ---------------- ACT halting ----------------
__global__ void __launch_bounds__(256) k_act(const float* __restrict__ hnew, const float* __restrict__ act_w,
                                             const float* __restrict__ act_b, float* __restrict__ h,
                                             float* __restrict__ hout, float* __restrict__ cum,
                                             float* __restrict__ halt) {
    int row = blockIdx.x; size_t base = (size_t)row * cD;
    int tid = threadIdx.x;
    float ss = 0.f;
#pragma unroll
    for (int i = 0; i < 4; i++) {
        int c = tid + i * 256;
        ss += hnew[base + c] * act_w[c];
    }
    __shared__ float red[256]; __shared__ float wsh;
    red[tid] = ss; __syncthreads();
    for (int s = 128; s > 0; s >>= 1) { if (tid < s) red[tid] += red[tid + s]; __syncthreads(); }
    if (tid == 0) {
        float z = red[0] + act_b[0];
        float p = 1.f / (1.f + expf(-z));
        float cm = cum[row]; float hl = halt[row];
        float p_eff = (hl > 0.5f) ? 0.f : p;
        float ncum = cm + p_eff;
        bool newly = (hl < 0.5f) && (ncum >= 0.99f);
        float w = newly ? (1.f - cm) : p_eff;
        cum[row] = ncum;
        if (newly) halt[row] = 1.f;
        wsh = w;
    }
    __syncthreads();
    float w = wsh;
#pragma unroll
    for (int i = 0; i < 4; i++) {
        int c = tid + i * 256;
        float v = hnew[base + c];
        hout[base + c] += w * v;
        h[base + c] = v;
    }
}

// ---------------- host ----------------
static void gemmB(const __nv_bfloat16* Ah, const __nv_bfloat16* Al,
                  const __nv_bfloat16* Bh, const __nv_bfloat16* Bl,
                  float* C, const float* Ci, int M, int N, int K, float scale, int epi) {
    int nCTA = (M / GTM) * (N / GTN);
    gemm_bf16<<<nCTA, 256, GEMM_SMEM>>>(Ah, Al, Bh, Bl, C, Ci, M, N, K, scale, epi);
}

extern "C" void kernel_launch(void* const* d_in, const int* in_sizes, int n_in,
                              void* d_out, int out_size) {
    const float* in_h  = (const float*)d_in[0];
    const float* in_e  = (const float*)d_in[1];
    const float* nw    = (const float*)d_in[2];
    const float* onw   = (const float*)d_in[3];
    const float* Wq    = (const float*)d_in[4];
    const float* Wk    = (const float*)d_in[5];
    const float* Wv    = (const float*)d_in[6];
    const float* Wgk   = (const float*)d_in[7];
    const float* Wg    = (const float*)d_in[8];
    const float* Wo    = (const float*)d_in[9];
    const float* loraA = (const float*)d_in[10];
    const float* loraB = (const float*)d_in[11];
    const float* injA  = (const float*)d_in[12];
    const float* injB  = (const float*)d_in[13];
    const float* act_w = (const float*)d_in[14];
    const float* act_b = (const float*)d_in[15];
    const float* ltab  = (const float*)d_in[16];
    float* out = (float*)d_out;

    float *p_h, *p_proj, *p_o, *p_kv, *p_S, *p_bdec,
          *p_gla, *p_lora, *p_hnew, *p_hout, *p_cum, *p_halt, *p_einj;
    cudaGetSymbolAddress((void**)&p_h, g_h);
    cudaGetSymbolAddress((void**)&p_proj, g_proj);
    cudaGetSymbolAddress((void**)&p_o, g_o);
    cudaGetSymbolAddress((void**)&p_kv, g_kv);
    cudaGetSymbolAddress((void**)&p_S, g_S);
    cudaGetSymbolAddress((void**)&p_bdec, g_bdec);
    cudaGetSymbolAddress((void**)&p_gla, g_gla);
    cudaGetSymbolAddress((void**)&p_lora, g_lora);
    cudaGetSymbolAddress((void**)&p_hnew, g_hnew);
    cudaGetSymbolAddress((void**)&p_hout, g_hout);
    cudaGetSymbolAddress((void**)&p_cum, g_cum);
    cudaGetSymbolAddress((void**)&p_halt, g_halt);
    cudaGetSymbolAddress((void**)&p_einj, g_einj);

    __nv_bfloat16 *wph, *wpl, *woh, *wol, *iah, *ial, *ibh, *ibl,
                  *eh, *el, *xh, *xl, *hh, *hl, *oh, *ol;
    cudaGetSymbolAddress((void**)&wph, g_wph);  cudaGetSymbolAddress((void**)&wpl, g_wpl);
    cudaGetSymbolAddress((void**)&woh, g_woh);  cudaGetSymbolAddress((void**)&wol, g_wol);
    cudaGetSymbolAddress((void**)&iah, g_iah);  cudaGetSymbolAddress((void**)&ial, g_ial);
    cudaGetSymbolAddress((void**)&ibh, g_ibh);  cudaGetSymbolAddress((void**)&ibl, g_ibl);
    cudaGetSymbolAddress((void**)&eh, g_eh);    cudaGetSymbolAddress((void**)&el, g_el);
    cudaGetSymbolAddress((void**)&xh, g_xh);    cudaGetSymbolAddress((void**)&xl, g_xl);
    cudaGetSymbolAddress((void**)&hh, g_hh2);   cudaGetSymbolAddress((void**)&hl, g_hl2);
    cudaGetSymbolAddress((void**)&oh, g_oh);    cudaGetSymbolAddress((void**)&ol, g_ol);

    cudaFuncSetAttribute(k_chunk, cudaFuncAttributeMaxDynamicSharedMemorySize, SMEM_CHUNK);
    cudaFuncSetAttribute(gemm_bf16, cudaFuncAttributeMaxDynamicSharedMemorySize, GEMM_SMEM);

    const int nBig = cM * cD / 256;
    k_copy<<<nBig, 256>>>(p_h, in_h);
    k_zero<<<nBig, 256>>>(p_hout);
    k_zero_state<<<cM / 256, 256>>>(p_cum, p_halt);

    // packed projection weight: rows [0,1024)=Wq^T, [1024,2048)=Wk^T, [2048,3072)=Wgk^T,
    // [3072,5120)=Wv^T, [5120,7168)=Wg^T   (all [N,K=1024] bf16 hi/lo)
    dim3 tb(32, 8);
    k_wconvT<<<dim3(cDK / 32, cD / 32), tb>>>(Wq,  wph,                    wpl,                    cD, cDK);
    k_wconvT<<<dim3(cDK / 32, cD / 32), tb>>>(Wk,  wph + (size_t)OFF_K  * cD, wpl + (size_t)OFF_K  * cD, cD, cDK);
    k_wconvT<<<dim3(cDK / 32, cD / 32), tb>>>(Wgk, wph + (size_t)OFF_LA * cD, wpl + (size_t)OFF_LA * cD, cD, cDK);
    k_wconvT<<<dim3(cDV / 32, cD / 32), tb>>>(Wv,  wph + (size_t)OFF_V  * cD, wpl + (size_t)OFF_V  * cD, cD, cDV);
    k_wconvT<<<dim3(cDV / 32, cD / 32), tb>>>(Wg,  wph + (size_t)OFF_G  * cD, wpl + (size_t)OFF_G  * cD, cD, cDV);
    k_wconvT<<<dim3(cD / 32, cDV / 32), tb>>>(Wo,  woh, wol, cDV, cD);
    k_split<<<cD * cD / 1024, 256>>>(injA, iah, ial);
    k_split<<<cD * cD / 1024, 256>>>(injB, ibh, ibl);
    k_split<<<cM * cD / 1024, 256>>>(in_e, eh, el);

    // loop-invariant: einj = e @ injB^T
    gemmB(eh, el, ibh, ibl, p_einj, nullptr, cM, cD, cD, 0.f, 0);

    const float qscale = 0.08838834764831845f;

    for (int t = 0; t < cNL; t++) {
        k_prep<<<cM, 256>>>(p_h, in_e, nw, ltab + t * cLOOPD, xh, xl, hh, hl);

        // single merged projection GEMM: q|k|la|v|gate with per-segment epilogue
        gemmB(xh, xl, wph, wpl, p_proj, nullptr, cM, PSTR, cD, qscale, 9);

        k_chunk<<<cNC * cBH, 256, SMEM_CHUNK>>>(p_proj, p_proj + OFF_K, p_proj + OFF_LA,
                                                p_proj + OFF_V, p_o, p_kv, p_bdec);
        k_state<<<cBH * 8, 256>>>(p_kv, p_bdec, p_S);
        k_inter<<<cNC * cBH, 256>>>(p_proj, p_S, p_o, p_proj + OFF_G, oh, ol);

        gemmB(oh, ol, woh, wol, p_gla, nullptr, cM, cD, cDV, 0.f, 0);

        k_lora_down<<<cM / 8, 256>>>(p_gla, loraA + (size_t)t * cD * cRANK, p_lora);
        k_lora_up<<<nBig, 256>>>(p_lora, loraB + (size_t)t * cRANK * cD, p_einj, p_gla);

        gemmB(hh, hl, iah, ial, p_hnew, p_gla, cM, cD, cD, 0.f, 0);

        k_act<<<cM, 256>>>(p_hnew, act_w, act_b, p_h, p_hout, p_cum, p_halt);
    }
    k_rmsnorm<<<cM, 256>>>(p_hout, onw, out);
}

// round 12
// speedup vs baseline: 1.5851x; 1.0164x over previous
#include <cuda_runtime.h>
#include <cuda_bf16.h>
#include <math.h>
#include <stdint.h>

// ---------------- problem constants ----------------
constexpr int cB = 4, cT = 4096, cD = 1024, cH = 8;
constexpr int cDK = 1024, cDV = 2048, cDKH = 128, cDVH = 256;
constexpr int cRANK = 16, cLOOPD = 128, cNL = 4;
constexpr int cCH = 64;
constexpr int cNC = cT / cCH;
constexpr int cBH = cB * cH;
constexpr int cM = cB * cT;
constexpr int PSTR = 7168;              // merged projection row stride (q|k|la|v|gate)
constexpr int OFF_K = 1024, OFF_LA = 2048, OFF_V = 3072, OFF_G = 5120;

// ---------------- device scratch ----------------
__device__ float g_h[cM * cD];
__device__ float g_proj[(size_t)cM * PSTR];
__device__ float g_o[cM * cDV];
__device__ float g_kv[cNC * cBH * cDKH * cDVH];
__device__ float g_S[cNC * cBH * cDKH * cDVH];
__device__ float g_bdec[cNC * cBH * cDKH];
__device__ float g_gla[cM * cD];
__device__ float g_lora[cM * cRANK];
__device__ float g_hnew[cM * cD];
__device__ float g_hout[cM * cD];
__device__ float g_cum[cM];
__device__ float g_halt[cM];
__device__ float g_einj[cM * cD];

// bf16 hi/lo buffers
__device__ __align__(16) __nv_bfloat16 g_wph[(size_t)PSTR * cD], g_wpl[(size_t)PSTR * cD];
__device__ __align__(16) __nv_bfloat16 g_woh[cDV * cD],  g_wol[cDV * cD];
__device__ __align__(16) __nv_bfloat16 g_iah[cD * cD],   g_ial[cD * cD];
__device__ __align__(16) __nv_bfloat16 g_ibh[cD * cD],   g_ibl[cD * cD];
__device__ __align__(16) __nv_bfloat16 g_eh[cM * cD],    g_el[cM * cD];
__device__ __align__(16) __nv_bfloat16 g_xh[cM * cD],    g_xl[cM * cD];
__device__ __align__(16) __nv_bfloat16 g_hh2[cM * cD],   g_hl2[cM * cD];
__device__ __align__(16) __nv_bfloat16 g_oh[cM * cDV],   g_ol[cM * cDV];

// ---------------- helpers ----------------
__device__ __forceinline__ uint32_t s2u(const void* p) {
    uint32_t a;
    asm("{ .reg .u64 t; cvta.to.shared.u64 t, %1; cvt.u32.u64 %0, t; }" : "=r"(a) : "l"(p));
    return a;
}
__device__ __forceinline__ uint32_t sw128(uint32_t off) { return off ^ ((off >> 3) & 0x70); }

#define LDSM4(r, a) \
    asm volatile("ldmatrix.sync.aligned.m8n8.x4.shared.b16 {%0,%1,%2,%3}, [%4];" \
        : "=r"((r)[0]), "=r"((r)[1]), "=r"((r)[2]), "=r"((r)[3]) : "r"(a))

__device__ __forceinline__ void mma_bf16(float* d, const uint32_t* a, const uint32_t* b) {
    asm volatile("mma.sync.aligned.m16n8k16.row.col.f32.bf16.bf16.f32 "
        "{%0,%1,%2,%3}, {%4,%5,%6,%7}, {%8,%9}, {%0,%1,%2,%3};"
        : "+f"(d[0]), "+f"(d[1]), "+f"(d[2]), "+f"(d[3])
        : "r"(a[0]), "r"(a[1]), "r"(a[2]), "r"(a[3]), "r"(b[0]), "r"(b[1]));
}

// ---------------- mma.sync bf16 hi/lo GEMM, 2 CTAs/SM, panel raster, templated N-tile ----------------
// A:[M,K] hi/lo row-major; B:[N,K] hi/lo K-major. CTA tile 128xGTN_, K-chunk 32.
// 1D grid; CTAs m-major within 8-wide n-panels (B panel stays L2-resident).
// Stage: A 16KB (row = 64B hi | 64B lo) + B GTN_*128B; 3 stages.
// epi: 0 none, 1 scale, 2 logsig/16, 3 silu, 9 merged-projection per-segment.
constexpr int GTM = 128, GKC = 32;
constexpr int A_TILE_B = 16384;

template <int GTN_>
__global__ void __launch_bounds__(256, 2) gemm_bf16_t(
    const __nv_bfloat16* __restrict__ Ah, const __nv_bfloat16* __restrict__ Al,
    const __nv_bfloat16* __restrict__ Bh, const __nv_bfloat16* __restrict__ Bl,
    float* __restrict__ C, const float* __restrict__ Ci,
    int M, int N, int K, float scale, int epi)
{
    constexpr int B_TILE_B = GTN_ * 128;
    constexpr int STG = A_TILE_B + B_TILE_B;
    constexpr int NFRAG = GTN_ / 16;      // n8-frags per warp (8 or 4)
    constexpr int NH = GTN_ / 64;         // nf-halves (2 or 1)
    constexpr int NT = STG / 16 / 256;    // 16B transfers per thread per stage (8 or 6)

    extern __shared__ char smem[];
    int tid = threadIdx.x;
    int lane = tid & 31, wid = tid >> 5;

    // panel rasterization: m-major within 8-wide n-panels
    int mbCnt = M >> 7;
    int per_panel = mbCnt * 8;
    int panel = blockIdx.x / per_panel;
    int rem = blockIdx.x - panel * per_panel;
    int bm = rem >> 3;
    int bn = panel * 8 + (rem & 7);
    int m0 = bm * GTM, n0 = bn * GTN_;

    int wm = (wid & 3) * 32, wn = (wid >> 2) * (GTN_ / 2);

    const int NCk = K / GKC;

    const __nv_bfloat16* pA[2] = { Ah + (size_t)m0 * K, Al + (size_t)m0 * K };
    const __nv_bfloat16* pB[2] = { Bh + (size_t)n0 * K, Bl + (size_t)n0 * K };

    auto load_stage = [&](int kc, int s) {
        char* base = smem + s * STG;
        int k0 = kc * GKC;
#pragma unroll
        for (int i = 0; i < NT; i++) {
            int gg = tid + i * 256;
            int tile = (gg >= 1024) ? 1 : 0;            // first 1024 transfers = A
            int idx = tile ? gg - 1024 : gg;
            int r = idx >> 3, seg = idx & 7;
            int hl = seg >> 2, s4 = seg & 3;
            uint32_t off = sw128((uint32_t)(r * 128 + hl * 64 + s4 * 16));
            const __nv_bfloat16* src = (tile ? pB[hl] : pA[hl]) + (size_t)r * K + k0 + s4 * 8;
            uint32_t dst = s2u(base + tile * A_TILE_B + off);
            asm volatile("cp.async.cg.shared.global [%0], [%1], 16;" :: "r"(dst), "l"(src));
        }
        asm volatile("cp.async.commit_group;" ::: "memory");
    };

    float acc[2][NFRAG][4];
#pragma unroll
    for (int mf = 0; mf < 2; mf++)
#pragma unroll
        for (int nf = 0; nf < NFRAG; nf++)
#pragma unroll
            for (int j = 0; j < 4; j++) acc[mf][nf][j] = 0.f;

    load_stage(0, 0);
    load_stage(1, 1);
    load_stage(2, 2);

    int a_row = (lane & 15);
    int a_col8 = (lane >> 4);
    int b_row = (lane & 7) + ((lane >> 4) & 1) * 8;
    int b_col8 = (lane >> 3) & 1;

    for (int c = 0; c < NCk; c++) {
        asm volatile("cp.async.wait_group 2;" ::: "memory");
        __syncthreads();
        char* base = smem + (c % 3) * STG;
        uint32_t sA = s2u(base), sB = sA + A_TILE_B;
#pragma unroll
        for (int kk = 0; kk < 2; kk++) {
            int k0 = kk * 16;
            uint32_t ah[2][4], al[2][4];
#pragma unroll
            for (int mf = 0; mf < 2; mf++) {
                uint32_t rowb = (uint32_t)((wm + mf * 16 + a_row) * 128);
                uint32_t kb = (uint32_t)((k0 + a_col8 * 8) * 2);
                LDSM4(ah[mf], sA + sw128(rowb + kb));
                LDSM4(al[mf], sA + sw128(rowb + 64 + kb));
            }
#pragma unroll
            for (int h = 0; h < NH; h++) {
                uint32_t bh[4][2], bl[4][2];
#pragma unroll
                for (int nf2 = 0; nf2 < 2; nf2++) {
                    int nf = h * 2 + nf2;
                    uint32_t rowb = (uint32_t)((wn + nf * 16 + b_row) * 128);
                    uint32_t kb = (uint32_t)((k0 + b_col8 * 8) * 2);
                    uint32_t r[4];
                    LDSM4(r, sB + sw128(rowb + kb));
                    bh[nf2 * 2][0] = r[0]; bh[nf2 * 2][1] = r[1];
                    bh[nf2 * 2 + 1][0] = r[2]; bh[nf2 * 2 + 1][1] = r[3];
                    LDSM4(r, sB + sw128(rowb + 64 + kb));
                    bl[nf2 * 2][0] = r[0]; bl[nf2 * 2][1] = r[1];
                    bl[nf2 * 2 + 1][0] = r[2]; bl[nf2 * 2 + 1][1] = r[3];
                }
#pragma unroll
                for (int mf = 0; mf < 2; mf++)
#pragma unroll
                    for (int n8 = 0; n8 < 4; n8++) {
                        float* a4 = acc[mf][h * 4 + n8];
                        mma_bf16(a4, ah[mf], bh[n8]);
                        mma_bf16(a4, ah[mf], bl[n8]);
                        mma_bf16(a4, al[mf], bh[n8]);
                    }
            }
        }
        __syncthreads();
        if (c + 3 < NCk) load_stage(c + 3, c % 3);
        else asm volatile("cp.async.commit_group;" ::: "memory");
    }

    const float qsc = scale;
#pragma unroll
    for (int mf = 0; mf < 2; mf++) {
#pragma unroll
        for (int nf = 0; nf < NFRAG; nf++) {
            int r0 = m0 + wm + mf * 16 + (lane >> 2);
            int cc = n0 + wn + nf * 8 + (lane & 3) * 2;
#pragma unroll
            for (int hh = 0; hh < 2; hh++) {
                int r = r0 + hh * 8;
                float vx = acc[mf][nf][hh * 2], vy = acc[mf][nf][hh * 2 + 1];
                size_t off = (size_t)r * N + cc;
                if (Ci) { vx += Ci[off]; vy += Ci[off + 1]; }
                int e = epi;
                if (e == 9) {
                    int seg = cc >> 10;
                    e = (seg == 0) ? 1 : (seg == 2) ? 2 : (seg >= 5) ? 3 : 0;
                }
                if (e == 1) { vx *= qsc; vy *= qsc; }
                else if (e == 2) {
                    vx = (fminf(vx, 0.f) - log1pf(expf(-fabsf(vx)))) * 0.0625f;
                    vy = (fminf(vy, 0.f) - log1pf(expf(-fabsf(vy)))) * 0.0625f;
                } else if (e == 3) {
                    vx = vx / (1.f + expf(-vx));
                    vy = vy / (1.f + expf(-vy));
                }
                *(float2*)&C[off] = make_float2(vx, vy);
            }
        }
    }
}

constexpr int SMEM_G128 = 3 * (A_TILE_B + 128 * 128);   // 98304
constexpr int SMEM_G64  = 3 * (A_TILE_B + 64 * 128);    // 73728

// ---------------- utility kernels ----------------
__global__ void k_copy(float* __restrict__ dst, const float* __restrict__ src) {
    int idx = blockIdx.x * 256 + threadIdx.x;
    dst[idx] = src[idx];
}
__global__ void k_zero(float* __restrict__ dst) {
    int idx = blockIdx.x * 256 + threadIdx.x;
    dst[idx] = 0.f;
}
__global__ void k_zero_state(float* __restrict__ cum, float* __restrict__ halt) {
    int idx = blockIdx.x * 256 + threadIdx.x;
    cum[idx] = 0.f; halt[idx] = 0.f;
}

__device__ __forceinline__ void bsplit(float x, __nv_bfloat16& h, __nv_bfloat16& l) {
    h = __float2bfloat16(x);
    l = __float2bfloat16(x - __bfloat162float(h));
}

__global__ void k_split(const float* __restrict__ src, __nv_bfloat16* __restrict__ hi,
                        __nv_bfloat16* __restrict__ lo) {
    size_t i4 = ((size_t)blockIdx.x * 256 + threadIdx.x) * 4;
    float4 v = *(const float4*)(src + i4);
    __nv_bfloat16 h0, h1, h2, h3, l0, l1, l2, l3;
    bsplit(v.x, h0, l0); bsplit(v.y, h1, l1); bsplit(v.z, h2, l2); bsplit(v.w, h3, l3);
    hi[i4] = h0; hi[i4+1] = h1; hi[i4+2] = h2; hi[i4+3] = h3;
    lo[i4] = l0; lo[i4+1] = l1; lo[i4+2] = l2; lo[i4+3] = l3;
}
// transpose-convert: W [K,N] fp32 -> out [N,K] bf16 hi/lo (out row stride K)
__global__ void k_wconvT(const float* __restrict__ W, __nv_bfloat16* __restrict__ hi,
                         __nv_bfloat16* __restrict__ lo, int K, int N) {
    __shared__ float s[32][33];
    int n0 = blockIdx.x * 32, k0 = blockIdx.y * 32;
    int tx = threadIdx.x, ty = threadIdx.y;
#pragma unroll
    for (int i = 0; i < 4; i++) {
        int r = ty + i * 8;
        s[r][tx] = W[(size_t)(k0 + r) * N + n0 + tx];
    }
    __syncthreads();
#pragma unroll
    for (int i = 0; i < 4; i++) {
        int r = ty + i * 8;
        float v = s[tx][r];
        size_t o = (size_t)(n0 + r) * K + k0 + tx;
        __nv_bfloat16 h, l; bsplit(v, h, l);
        hi[o] = h; lo[o] = l;
    }
}

// ---------------- fused loop-embed + rmsnorm(h+e) + bf16 splits ----------------
__global__ void __launch_bounds__(256) k_prep(float* __restrict__ h, const float* __restrict__ e,
                                              const float* __restrict__ nw, const float* __restrict__ ltab,
                                              __nv_bfloat16* __restrict__ xh, __nv_bfloat16* __restrict__ xl,
                                              __nv_bfloat16* __restrict__ hh, __nv_bfloat16* __restrict__ hl) {
    int row = blockIdx.x; size_t base = (size_t)row * cD;
    int tid = threadIdx.x;
    if (tid < cLOOPD) h[base + tid] += ltab[tid];
    __syncthreads();
    float hv[4], vals[4]; float ss = 0.f;
#pragma unroll
    for (int i = 0; i < 4; i++) {
        int c = tid + i * 256;
        float hx = h[base + c];
        hv[i] = hx;
        float v = hx + e[base + c];
        vals[i] = v; ss += v * v;
    }
    __shared__ float red[256];
    red[tid] = ss; __syncthreads();
    for (int s = 128; s > 0; s >>= 1) { if (tid < s) red[tid] += red[tid + s]; __syncthreads(); }
    float rs = rsqrtf(red[0] * (1.f / cD) + 1e-6f);
#pragma unroll
    for (int i = 0; i < 4; i++) {
        int c = tid + i * 256;
        float x = vals[i] * rs * nw[c];
        __nv_bfloat16 a, b;
        bsplit(x, a, b); xh[base + c] = a; xl[base + c] = b;
        bsplit(hv[i], a, b); hh[base + c] = a; hl[base + c] = b;
    }
}

// ---------------- final rmsnorm ----------------
__global__ void __launch_bounds__(256) k_rmsnorm(const float* __restrict__ in, const float* __restrict__ nw,
                                                 float* __restrict__ out) {
    int row = blockIdx.x; size_t base = (size_t)row * cD;
    int tid = threadIdx.x;
    float vals[4]; float ss = 0.f;
#pragma unroll
    for (int i = 0; i < 4; i++) {
        int c = tid + i * 256;
        float v = in[base + c];
        vals[i] = v; ss += v * v;
    }
    __shared__ float red[256];
    red[tid] = ss; __syncthreads();
    for (int s = 128; s > 0; s >>= 1) { if (tid < s) red[tid] += red[tid + s]; __syncthreads(); }
    float rs = rsqrtf(red[0] * (1.f / cD) + 1e-6f);
#pragma unroll
    for (int i = 0; i < 4; i++) {
        int c = tid + i * 256;
        out[base + c] = vals[i] * rs * nw[c];
    }
}

// ---------------- GLA chunk kernel ----------------
constexpr int SMEM_CHUNK = 49408 * 4;
__global__ void __launch_bounds__(256) k_chunk(float* __restrict__ pq, const float* __restrict__ pk,
                                               const float* __restrict__ pla, const float* __restrict__ pv,
                                               float* __restrict__ po, float* __restrict__ pkv,
                                               float* __restrict__ pbdec) {
    extern __shared__ float sm[];
    float* s_cum = sm;
    float* s_qt = sm + 8192;
    float* s_kt = sm + 16384;     // stride 132
    float* s_kc = sm + 24832;
    float* s_v  = sm + 33024;
    float* s_A  = sm;

    int cidx = blockIdx.x;
    int c = cidx / cBH, bh = cidx - c * cBH;
    int b = bh >> 3, hh = bh & 7;
    int t0 = c * cCH;
    size_t qbase = ((size_t)b * cT + t0) * PSTR + hh * cDKH;
    size_t vbase = ((size_t)b * cT + t0) * PSTR + hh * cDVH;
    size_t obase = ((size_t)b * cT + t0) * cDV + hh * cDVH;
    int tid = threadIdx.x;

    if (tid < 128) {
        int d = tid;
        float cum = 0.f;
        for (int i = 0; i < cCH; i++) {
            size_t off = qbase + (size_t)i * PSTR + d;
            cum += pla[off];
            s_cum[i * 128 + d] = cum;
            s_qt[i * 128 + d] = pq[off] * expf(cum);
            s_kt[i * 132 + d] = pk[off] * expf(-cum);
            s_kc[i * 128 + d] = pk[off];
        }
        float latot = cum;
        pbdec[(size_t)cidx * cDKH + d] = expf(latot);
        for (int i = 0; i < cCH; i++)
            s_kc[i * 128 + d] *= expf(latot - s_cum[i * 128 + d]);
        for (int i = 0; i < cCH; i++)
            pq[qbase + (size_t)i * PSTR + d] = s_qt[i * 128 + d];
    } else {
        int lt = tid - 128;
        for (int l = 0; l < 32; l++) {
            int idx4 = lt + l * 128;
            int i = idx4 >> 6;
            int u4 = (idx4 & 63) * 4;
            *(float4*)&s_v[i * 256 + u4] = *(const float4*)&pv[vbase + (size_t)i * PSTR + u4];
        }
    }
    __syncthreads();

    for (int idx = tid; idx < cCH * cCH; idx += 256) {
        int i = idx >> 6, j = idx & 63;
        float sum = 0.f;
        if (j <= i) {
            const float* qp = &s_qt[i * 128];
            const float* kp = &s_kt[j * 132];
#pragma unroll
            for (int d = 0; d < 128; d += 4) {
                float4 qa = *(const float4*)&qp[d];
                float4 kb = *(const float4*)&kp[d];
                sum += qa.x * kb.x + qa.y * kb.y + qa.z * kb.z + qa.w * kb.w;
            }
        }
        s_A[idx] = sum;
    }
    __syncthreads();

    // O_intra = A @ V
    {
        int uq = tid & 63;
        int il = tid >> 6;
#pragma unroll 1
        for (int step = 0; step < 16; step++) {
            int i = il + step * 4;
            float4 acc = make_float4(0.f, 0.f, 0.f, 0.f);
            const float* arow = &s_A[i * 64];
            for (int j = 0; j <= i; j++) {
                float a = arow[j];
                float4 vv = *(const float4*)&s_v[j * 256 + uq * 4];
                acc.x += a * vv.x; acc.y += a * vv.y; acc.z += a * vv.z; acc.w += a * vv.w;
            }
            *(float4*)&po[obase + (size_t)i * cDV + uq * 4] = acc;
        }
    }

    // KV_c = kc^T @ V
    {
#pragma unroll 1
        for (int s = 0; s < 8; s++) {
            int idx = tid + s * 256;
            int dq = idx >> 6;
            int uq = idx & 63;
            float4 a0 = make_float4(0.f,0.f,0.f,0.f), a1 = a0, a2 = a0, a3 = a0;
#pragma unroll 4
            for (int j = 0; j < cCH; j++) {
                float4 kc = *(const float4*)&s_kc[j * 128 + dq * 4];
                float4 vv = *(const float4*)&s_v[j * 256 + uq * 4];
                a0.x += kc.x * vv.x; a0.y += kc.x * vv.y; a0.z += kc.x * vv.z; a0.w += kc.x * vv.w;
                a1.x += kc.y * vv.x; a1.y += kc.y * vv.y; a1.z += kc.y * vv.z; a1.w += kc.y * vv.w;
                a2.x += kc.z * vv.x; a2.y += kc.z * vv.y; a2.z += kc.z * vv.z; a2.w += kc.z * vv.w;
                a3.x += kc.w * vv.x; a3.y += kc.w * vv.y; a3.z += kc.w * vv.z; a3.w += kc.w * vv.w;
            }
            size_t kvbase = (size_t)cidx * (cDKH * cDVH) + (size_t)(dq * 4) * cDVH + uq * 4;
            *(float4*)&pkv[kvbase]            = a0;
            *(float4*)&pkv[kvbase + cDVH]     = a1;
            *(float4*)&pkv[kvbase + 2 * cDVH] = a2;
            *(float4*)&pkv[kvbase + 3 * cDVH] = a3;
        }
    }
}

// ---------------- state propagation ----------------
__global__ void __launch_bounds__(256) k_state(const float* __restrict__ pkv, const float* __restrict__ pbdec,
                                               float* __restrict__ Sout) {
    int blk = blockIdx.x;
    int bh = blk >> 3;
    int vs = (blk & 7) * 32;
    int tid = threadIdx.x;
    int kr = tid >> 1;
    int vofs = vs + (tid & 1) * 16;
    float S[16];
#pragma unroll
    for (int j = 0; j < 16; j++) S[j] = 0.f;
    for (int c = 0; c < cNC; c++) {
        size_t base = ((size_t)c * cBH + bh) * (cDKH * cDVH) + (size_t)kr * cDVH + vofs;
        float bd = pbdec[((size_t)c * cBH + bh) * cDKH + kr];
#pragma unroll
        for (int j = 0; j < 16; j += 4) {
            *(float4*)&Sout[base + j] = make_float4(S[j], S[j + 1], S[j + 2], S[j + 3]);
            float4 kvv = *(const float4*)&pkv[base + j];
            S[j]     = bd * S[j]     + kvv.x;
            S[j + 1] = bd * S[j + 1] + kvv.y;
            S[j + 2] = bd * S[j + 2] + kvv.z;
            S[j + 3] = bd * S[j + 3] + kvv.w;
        }
    }
}

// ---------------- inter-chunk output + fused gate + bf16 split ----------------
__global__ void __launch_bounds__(256) k_inter(const float* __restrict__ pq, const float* __restrict__ S,
                                               const float* __restrict__ po, const float* __restrict__ pgate,
                                               __nv_bfloat16* __restrict__ oh, __nv_bfloat16* __restrict__ ol) {
    __shared__ float s_q[cCH * cDKH];
    int cidx = blockIdx.x;
    int c = cidx / cBH, bh = cidx - c * cBH;
    int b = bh >> 3, hh = bh & 7;
    int t0 = c * cCH;
    size_t qbase = ((size_t)b * cT + t0) * PSTR + hh * cDKH;
    size_t gbase = ((size_t)b * cT + t0) * PSTR + hh * cDVH;
    size_t obase = ((size_t)b * cT + t0) * cDV + hh * cDVH;
    int tid = threadIdx.x;
#pragma unroll
    for (int l = 0; l < 8; l++) {
        int idx4 = tid + l * 256;
        int i = idx4 >> 5;
        int d4 = (idx4 & 31) * 4;
        *(float4*)&s_q[i * 128 + d4] = *(const float4*)&pq[qbase + (size_t)i * PSTR + d4];
    }
    __syncthreads();
    int u = tid;
    float acc[cCH];
#pragma unroll
    for (int i = 0; i < cCH; i++) acc[i] = 0.f;
    size_t sbase = (size_t)cidx * (cDKH * cDVH) + u;
    for (int d = 0; d < cDKH; d += 4) {
        float sv0 = S[sbase + (size_t)(d + 0) * cDVH];
        float sv1 = S[sbase + (size_t)(d + 1) * cDVH];
        float sv2 = S[sbase + (size_t)(d + 2) * cDVH];
        float sv3 = S[sbase + (size_t)(d + 3) * cDVH];
#pragma unroll
        for (int i = 0; i < cCH; i++) {
            float4 qv = *(const float4*)&s_q[i * 128 + d];
            acc[i] += qv.x * sv0 + qv.y * sv1 + qv.z * sv2 + qv.w * sv3;
        }
    }
#pragma unroll
    for (int i = 0; i < cCH; i++) {
        size_t offo = obase + (size_t)i * cDV + u;
        float ov = (po[offo] + acc[i]) * pgate[gbase + (size_t)i * PSTR + u];
        __nv_bfloat16 hbf, lbf; bsplit(ov, hbf, lbf);
        oh[offo] = hbf; ol[offo] = lbf;
    }
}

// ---------------- LoRA ----------------
__global__ void __launch_bounds__(256) k_lora_down(const float* __restrict__ g, const float* __restrict__ A,
                                                   float* __restrict__ out) {
    int warp = threadIdx.x >> 5, lane = threadIdx.x & 31;
    int m = blockIdx.x * 8 + warp;
    const float* grow = &g[(size_t)m * cD];
    float acc[cRANK];
#pragma unroll
    for (int r = 0; r < cRANK; r++) acc[r] = 0.f;
    for (int kk = lane; kk < cD; kk += 32) {
        float a = grow[kk];
        const float4* Ap = (const float4*)&A[(size_t)kk * cRANK];
        float4 b0 = Ap[0], b1 = Ap[1], b2 = Ap[2], b3 = Ap[3];
        acc[0] += a * b0.x; acc[1] += a * b0.y; acc[2] += a * b0.z; acc[3] += a * b0.w;
        acc[4] += a * b1.x; acc[5] += a * b1.y; acc[6] += a * b1.z; acc[7] += a * b1.w;
        acc[8] += a * b2.x; acc[9] += a * b2.y; acc[10] += a * b2.z; acc[11] += a * b2.w;
        acc[12] += a * b3.x; acc[13] += a * b3.y; acc[14] += a * b3.z; acc[15] += a * b3.w;
    }
#pragma unroll
    for (int r = 0; r < cRANK; r++)
        for (int s = 16; s > 0; s >>= 1) acc[r] += __shfl_xor_sync(0xffffffffu, acc[r], s);
    if (lane == 0) {
#pragma unroll
        for (int r = 0; r < cRANK; r++) out[(size_t)m * cRANK + r] = acc[r];
    }
}
__global__ void __launch_bounds__(256) k_lora_up(const float* __restrict__ tmp, const float* __restrict__ Bm,
                                                 const float* __restrict__ einj, float* __restrict__ g) {
    int idx = blockIdx.x * 256 + threadIdx.x;
    int m = idx >> 10, n = idx & 1023;
    const float* tr = &tmp[(size_t)m * cRANK];
    float s = 0.f;
#pragma unroll
    for (int r = 0; r < cRANK; r++) s += tr[r] * Bm[r * cD + n];
    g[idx] += s + einj[idx];
}

// ---------------- ACT halting ----------------
__global__ void __launch_bounds__(256) k_act(const float* __restrict__ hnew, const float* __restrict__ act_w,
                                             const float* __restrict__ act_b, float* __restrict__ h,
                                             float* __restrict__ hout, float* __restrict__ cum,
                                             float* __restrict__ halt) {
    int row = blockIdx.x; size_t base = (size_t)row * cD;
    int tid = threadIdx.x;
    float ss = 0.f;
#pragma unroll
    for (int i = 0; i < 4; i++) {
        int c = tid + i * 256;
        ss += hnew[base + c] * act_w[c];
    }
    __shared__ float red[256]; __shared__ float wsh;
    red[tid] = ss; __syncthreads();
    for (int s = 128; s > 0; s >>= 1) { if (tid < s) red[tid] += red[tid + s]; __syncthreads(); }
    if (tid == 0) {
        float z = red[0] + act_b[0];
        float p = 1.f / (1.f + expf(-z));
        float cm = cum[row]; float hl = halt[row];
        float p_eff = (hl > 0.5f) ? 0.f : p;
        float ncum = cm + p_eff;
        bool newly = (hl < 0.5f) && (ncum >= 0.99f);
        float w = newly ? (1.f - cm) : p_eff;
        cum[row] = ncum;
        if (newly) halt[row] = 1.f;
        wsh = w;
    }
    __syncthreads();
    float w = wsh;
#pragma unroll
    for (int i = 0; i < 4; i++) {
        int c = tid + i * 256;
        float v = hnew[base + c];
        hout[base + c] += w * v;
        h[base + c] = v;
    }
}

// ---------------- host ----------------
static void gemmB(const __nv_bfloat16* Ah, const __nv_bfloat16* Al,
                  const __nv_bfloat16* Bh, const __nv_bfloat16* Bl,
                  float* C, const float* Ci, int M, int N, int K, float scale, int epi) {
    if (N == 1024) {
        int nCTA = (M / GTM) * (N / 64);
        gemm_bf16_t<64><<<nCTA, 256, SMEM_G64>>>(Ah, Al, Bh, Bl, C, Ci, M, N, K, scale, epi);
    } else {
        int nCTA = (M / GTM) * (N / 128);
        gemm_bf16_t<128><<<nCTA, 256, SMEM_G128>>>(Ah, Al, Bh, Bl, C, Ci, M, N, K, scale, epi);
    }
}

extern "C" void kernel_launch(void* const* d_in, const int* in_sizes, int n_in,
                              void* d_out, int out_size) {
    const float* in_h  = (const float*)d_in[0];
    const float* in_e  = (const float*)d_in[1];
    const float* nw    = (const float*)d_in[2];
    const float* onw   = (const float*)d_in[3];
    const float* Wq    = (const float*)d_in[4];
    const float* Wk    = (const float*)d_in[5];
    const float* Wv    = (const float*)d_in[6];
    const float* Wgk   = (const float*)d_in[7];
    const float* Wg    = (const float*)d_in[8];
    const float* Wo    = (const float*)d_in[9];
    const float* loraA = (const float*)d_in[10];
    const float* loraB = (const float*)d_in[11];
    const float* injA  = (const float*)d_in[12];
    const float* injB  = (const float*)d_in[13];
    const float* act_w = (const float*)d_in[14];
    const float* act_b = (const float*)d_in[15];
    const float* ltab  = (const float*)d_in[16];
    float* out = (float*)d_out;

    float *p_h, *p_proj, *p_o, *p_kv, *p_S, *p_bdec,
          *p_gla, *p_lora, *p_hnew, *p_hout, *p_cum, *p_halt, *p_einj;
    cudaGetSymbolAddress((void**)&p_h, g_h);
    cudaGetSymbolAddress((void**)&p_proj, g_proj);
    cudaGetSymbolAddress((void**)&p_o, g_o);
    cudaGetSymbolAddress((void**)&p_kv, g_kv);
    cudaGetSymbolAddress((void**)&p_S, g_S);
    cudaGetSymbolAddress((void**)&p_bdec, g_bdec);
    cudaGetSymbolAddress((void**)&p_gla, g_gla);
    cudaGetSymbolAddress((void**)&p_lora, g_lora);
    cudaGetSymbolAddress((void**)&p_hnew, g_hnew);
    cudaGetSymbolAddress((void**)&p_hout, g_hout);
    cudaGetSymbolAddress((void**)&p_cum, g_cum);
    cudaGetSymbolAddress((void**)&p_halt, g_halt);
    cudaGetSymbolAddress((void**)&p_einj, g_einj);

    __nv_bfloat16 *wph, *wpl, *woh, *wol, *iah, *ial, *ibh, *ibl,
                  *eh, *el, *xh, *xl, *hh, *hl, *oh, *ol;
    cudaGetSymbolAddress((void**)&wph, g_wph);  cudaGetSymbolAddress((void**)&wpl, g_wpl);
    cudaGetSymbolAddress((void**)&woh, g_woh);  cudaGetSymbolAddress((void**)&wol, g_wol);
    cudaGetSymbolAddress((void**)&iah, g_iah);  cudaGetSymbolAddress((void**)&ial, g_ial);
    cudaGetSymbolAddress((void**)&ibh, g_ibh);  cudaGetSymbolAddress((void**)&ibl, g_ibl);
    cudaGetSymbolAddress((void**)&eh, g_eh);    cudaGetSymbolAddress((void**)&el, g_el);
    cudaGetSymbolAddress((void**)&xh, g_xh);    cudaGetSymbolAddress((void**)&xl, g_xl);
    cudaGetSymbolAddress((void**)&hh, g_hh2);   cudaGetSymbolAddress((void**)&hl, g_hl2);
    cudaGetSymbolAddress((void**)&oh, g_oh);    cudaGetSymbolAddress((void**)&ol, g_ol);

    cudaFuncSetAttribute(k_chunk, cudaFuncAttributeMaxDynamicSharedMemorySize, SMEM_CHUNK);
    cudaFuncSetAttribute(gemm_bf16_t<128>, cudaFuncAttributeMaxDynamicSharedMemorySize, SMEM_G128);
    cudaFuncSetAttribute(gemm_bf16_t<64>,  cudaFuncAttributeMaxDynamicSharedMemorySize, SMEM_G64);

    const int nBig = cM * cD / 256;
    k_copy<<<nBig, 256>>>(p_h, in_h);
    k_zero<<<nBig, 256>>>(p_hout);
    k_zero_state<<<cM / 256, 256>>>(p_cum, p_halt);

    // packed projection weight: rows [0,1024)=Wq^T, [1024,2048)=Wk^T, [2048,3072)=Wgk^T,
    // [3072,5120)=Wv^T, [5120,7168)=Wg^T   (all [N,K=1024] bf16 hi/lo)
    dim3 tb(32, 8);
    k_wconvT<<<dim3(cDK / 32, cD / 32), tb>>>(Wq,  wph,                    wpl,                    cD, cDK);
    k_wconvT<<<dim3(cDK / 32, cD / 32), tb>>>(Wk,  wph + (size_t)OFF_K  * cD, wpl + (size_t)OFF_K  * cD, cD, cDK);
    k_wconvT<<<dim3(cDK / 32, cD / 32), tb>>>(Wgk, wph + (size_t)OFF_LA * cD, wpl + (size_t)OFF_LA * cD, cD, cDK);
    k_wconvT<<<dim3(cDV / 32, cD / 32), tb>>>(Wv,  wph + (size_t)OFF_V  * cD, wpl + (size_t)OFF_V  * cD, cD, cDV);
    k_wconvT<<<dim3(cDV / 32, cD / 32), tb>>>(Wg,  wph + (size_t)OFF_G  * cD, wpl + (size_t)OFF_G  * cD, cD, cDV);
    k_wconvT<<<dim3(cD / 32, cDV / 32), tb>>>(Wo,  woh, wol, cDV, cD);
    k_split<<<cD * cD / 1024, 256>>>(injA, iah, ial);
    k_split<<<cD * cD / 1024, 256>>>(injB, ibh, ibl);
    k_split<<<cM * cD / 1024, 256>>>(in_e, eh, el);

    // loop-invariant: einj = e @ injB^T
    gemmB(eh, el, ibh, ibl, p_einj, nullptr, cM, cD, cD, 0.f, 0);

    const float qscale = 0.08838834764831845f;

    for (int t = 0; t < cNL; t++) {
        k_prep<<<cM, 256>>>(p_h, in_e, nw, ltab + t * cLOOPD, xh, xl, hh, hl);

        // single merged projection GEMM: q|k|la|v|gate with per-segment epilogue
        gemmB(xh, xl, wph, wpl, p_proj, nullptr, cM, PSTR, cD, qscale, 9);

        k_chunk<<<cNC * cBH, 256, SMEM_CHUNK>>>(p_proj, p_proj + OFF_K, p_proj + OFF_LA,
                                                p_proj + OFF_V, p_o, p_kv, p_bdec);
        k_state<<<cBH * 8, 256>>>(p_kv, p_bdec, p_S);
        k_inter<<<cNC * cBH, 256>>>(p_proj, p_S, p_o, p_proj + OFF_G, oh, ol);

        gemmB(oh, ol, woh, wol, p_gla, nullptr, cM, cD, cDV, 0.f, 0);

        k_lora_down<<<cM / 8, 256>>>(p_gla, loraA + (size_t)t * cD * cRANK, p_lora);
        k_lora_up<<<nBig, 256>>>(p_lora, loraB + (size_t)t * cRANK * cD, p_einj, p_gla);

        gemmB(hh, hl, iah, ial, p_hnew, p_gla, cM, cD, cD, 0.f, 0);

        k_act<<<cM, 256>>>(p_hnew, act_w, act_b, p_h, p_hout, p_cum, p_halt);
    }
    k_rmsnorm<<<cM, 256>>>(p_hout, onw, out);
}

// round 14
// speedup vs baseline: 1.6209x; 1.0226x over previous
#include <cuda_runtime.h>
#include <cuda_bf16.h>
#include <math.h>
#include <stdint.h>

// ---------------- problem constants ----------------
constexpr int cB = 4, cT = 4096, cD = 1024, cH = 8;
constexpr int cDK = 1024, cDV = 2048, cDKH = 128, cDVH = 256;
constexpr int cRANK = 16, cLOOPD = 128, cNL = 4;
constexpr int cCH = 64;
constexpr int cNC = cT / cCH;
constexpr int cBH = cB * cH;
constexpr int cM = cB * cT;
constexpr int PSTR = 7168;              // merged projection row stride (q|k|la|v|gate)
constexpr int OFF_K = 1024, OFF_LA = 2048, OFF_V = 3072, OFF_G = 5120;

// ---------------- device scratch ----------------
__device__ float g_h[cM * cD];
__device__ float g_proj[(size_t)cM * PSTR];
__device__ float g_o[cM * cDV];
__device__ float g_kv[cNC * cBH * cDKH * cDVH];
__device__ float g_S[cNC * cBH * cDKH * cDVH];
__device__ float g_bdec[cNC * cBH * cDKH];
__device__ float g_gla[cM * cD];
__device__ float g_lora[cM * cRANK];
__device__ float g_hnew[cM * cD];
__device__ float g_hout[cM * cD];
__device__ float g_cum[cM];
__device__ float g_halt[cM];
__device__ float g_einj[cM * cD];

// bf16 hi/lo buffers
__device__ __align__(16) __nv_bfloat16 g_wph[(size_t)PSTR * cD], g_wpl[(size_t)PSTR * cD];
__device__ __align__(16) __nv_bfloat16 g_woh[cDV * cD],  g_wol[cDV * cD];
__device__ __align__(16) __nv_bfloat16 g_iah[cD * cD],   g_ial[cD * cD];
__device__ __align__(16) __nv_bfloat16 g_ibh[cD * cD],   g_ibl[cD * cD];
__device__ __align__(16) __nv_bfloat16 g_eh[cM * cD],    g_el[cM * cD];
__device__ __align__(16) __nv_bfloat16 g_xh[cM * cD],    g_xl[cM * cD];
__device__ __align__(16) __nv_bfloat16 g_hh2[cM * cD],   g_hl2[cM * cD];
__device__ __align__(16) __nv_bfloat16 g_oh[cM * cDV],   g_ol[cM * cDV];

// ---------------- helpers ----------------
__device__ __forceinline__ uint32_t s2u(const void* p) {
    uint32_t a;
    asm("{ .reg .u64 t; cvta.to.shared.u64 t, %1; cvt.u32.u64 %0, t; }" : "=r"(a) : "l"(p));
    return a;
}
__device__ __forceinline__ uint32_t sw128(uint32_t off) { return off ^ ((off >> 3) & 0x70); }

#define LDSM4(r, a) \
    asm volatile("ldmatrix.sync.aligned.m8n8.x4.shared.b16 {%0,%1,%2,%3}, [%4];" \
        : "=r"((r)[0]), "=r"((r)[1]), "=r"((r)[2]), "=r"((r)[3]) : "r"(a))

__device__ __forceinline__ void mma_bf16(float* d, const uint32_t* a, const uint32_t* b) {
    asm volatile("mma.sync.aligned.m16n8k16.row.col.f32.bf16.bf16.f32 "
        "{%0,%1,%2,%3}, {%4,%5,%6,%7}, {%8,%9}, {%0,%1,%2,%3};"
        : "+f"(d[0]), "+f"(d[1]), "+f"(d[2]), "+f"(d[3])
        : "r"(a[0]), "r"(a[1]), "r"(a[2]), "r"(a[3]), "r"(b[0]), "r"(b[1]));
}

// ---------------- mma.sync bf16 hi/lo GEMM, 2 CTAs/SM, panel raster, templated N-tile ----------------
// Single-barrier 3-stage pipeline:
//   wait_group(1)  -> own group c complete
//   __syncthreads  -> publishes all threads' cp.async writes; proves all warps done with stage c-1
//   issue load c+2 -> overwrites stage (c-1)%3, safe per the sync
//   consume c      -> no trailing barrier needed
constexpr int GTM = 128, GKC = 32;
constexpr int A_TILE_B = 16384;

template <int GTN_>
__global__ void __launch_bounds__(256, 2) gemm_bf16_t(
    const __nv_bfloat16* __restrict__ Ah, const __nv_bfloat16* __restrict__ Al,
    const __nv_bfloat16* __restrict__ Bh, const __nv_bfloat16* __restrict__ Bl,
    float* __restrict__ C, const float* __restrict__ Ci,
    int M, int N, int K, float scale, int epi)
{
    constexpr int B_TILE_B = GTN_ * 128;
    constexpr int STG = A_TILE_B + B_TILE_B;
    constexpr int NFRAG = GTN_ / 16;
    constexpr int NH = GTN_ / 64;
    constexpr int NT = STG / 16 / 256;

    extern __shared__ char smem[];
    int tid = threadIdx.x;
    int lane = tid & 31, wid = tid >> 5;

    // panel rasterization: m-major within 8-wide n-panels
    int mbCnt = M >> 7;
    int per_panel = mbCnt * 8;
    int panel = blockIdx.x / per_panel;
    int rem = blockIdx.x - panel * per_panel;
    int bm = rem >> 3;
    int bn = panel * 8 + (rem & 7);
    int m0 = bm * GTM, n0 = bn * GTN_;

    int wm = (wid & 3) * 32, wn = (wid >> 2) * (GTN_ / 2);

    const int NCk = K / GKC;

    const __nv_bfloat16* pA[2] = { Ah + (size_t)m0 * K, Al + (size_t)m0 * K };
    const __nv_bfloat16* pB[2] = { Bh + (size_t)n0 * K, Bl + (size_t)n0 * K };

    auto load_stage = [&](int kc, int s) {
        char* base = smem + s * STG;
        int k0 = kc * GKC;
#pragma unroll
        for (int i = 0; i < NT; i++) {
            int gg = tid + i * 256;
            int tile = (gg >= 1024) ? 1 : 0;
            int idx = tile ? gg - 1024 : gg;
            int r = idx >> 3, seg = idx & 7;
            int hl = seg >> 2, s4 = seg & 3;
            uint32_t off = sw128((uint32_t)(r * 128 + hl * 64 + s4 * 16));
            const __nv_bfloat16* src = (tile ? pB[hl] : pA[hl]) + (size_t)r * K + k0 + s4 * 8;
            uint32_t dst = s2u(base + tile * A_TILE_B + off);
            asm volatile("cp.async.cg.shared.global [%0], [%1], 16;" :: "r"(dst), "l"(src));
        }
        asm volatile("cp.async.commit_group;" ::: "memory");
    };

    float acc[2][NFRAG][4];
#pragma unroll
    for (int mf = 0; mf < 2; mf++)
#pragma unroll
        for (int nf = 0; nf < NFRAG; nf++)
#pragma unroll
            for (int j = 0; j < 4; j++) acc[mf][nf][j] = 0.f;

    load_stage(0, 0);
    load_stage(1, 1);

    int a_row = (lane & 15);
    int a_col8 = (lane >> 4);
    int b_row = (lane & 7) + ((lane >> 4) & 1) * 8;
    int b_col8 = (lane >> 3) & 1;

    for (int c = 0; c < NCk; c++) {
        asm volatile("cp.async.wait_group 1;" ::: "memory");
        __syncthreads();
        if (c + 2 < NCk) load_stage(c + 2, (c + 2) % 3);
        else asm volatile("cp.async.commit_group;" ::: "memory");

        char* base = smem + (c % 3) * STG;
        uint32_t sA = s2u(base), sB = sA + A_TILE_B;
#pragma unroll
        for (int kk = 0; kk < 2; kk++) {
            int k0 = kk * 16;
            uint32_t ah[2][4], al[2][4];
#pragma unroll
            for (int mf = 0; mf < 2; mf++) {
                uint32_t rowb = (uint32_t)((wm + mf * 16 + a_row) * 128);
                uint32_t kb = (uint32_t)((k0 + a_col8 * 8) * 2);
                LDSM4(ah[mf], sA + sw128(rowb + kb));
                LDSM4(al[mf], sA + sw128(rowb + 64 + kb));
            }
#pragma unroll
            for (int h = 0; h < NH; h++) {
                uint32_t bh[4][2], bl[4][2];
#pragma unroll
                for (int nf2 = 0; nf2 < 2; nf2++) {
                    int nf = h * 2 + nf2;
                    uint32_t rowb = (uint32_t)((wn + nf * 16 + b_row) * 128);
                    uint32_t kb = (uint32_t)((k0 + b_col8 * 8) * 2);
                    uint32_t r[4];
                    LDSM4(r, sB + sw128(rowb + kb));
                    bh[nf2 * 2][0] = r[0]; bh[nf2 * 2][1] = r[1];
                    bh[nf2 * 2 + 1][0] = r[2]; bh[nf2 * 2 + 1][1] = r[3];
                    LDSM4(r, sB + sw128(rowb + 64 + kb));
                    bl[nf2 * 2][0] = r[0]; bl[nf2 * 2][1] = r[1];
                    bl[nf2 * 2 + 1][0] = r[2]; bl[nf2 * 2 + 1][1] = r[3];
                }
#pragma unroll
                for (int mf = 0; mf < 2; mf++)
#pragma unroll
                    for (int n8 = 0; n8 < 4; n8++) {
                        float* a4 = acc[mf][h * 4 + n8];
                        mma_bf16(a4, ah[mf], bh[n8]);
                        mma_bf16(a4, ah[mf], bl[n8]);
                        mma_bf16(a4, al[mf], bh[n8]);
                    }
            }
        }
    }

    const float qsc = scale;
#pragma unroll
    for (int mf = 0; mf < 2; mf++) {
#pragma unroll
        for (int nf = 0; nf < NFRAG; nf++) {
            int r0 = m0 + wm + mf * 16 + (lane >> 2);
            int cc = n0 + wn + nf * 8 + (lane & 3) * 2;
#pragma unroll
            for (int hh = 0; hh < 2; hh++) {
                int r = r0 + hh * 8;
                float vx = acc[mf][nf][hh * 2], vy = acc[mf][nf][hh * 2 + 1];
                size_t off = (size_t)r * N + cc;
                if (Ci) { vx += Ci[off]; vy += Ci[off + 1]; }
                int e = epi;
                if (e == 9) {
                    int seg = cc >> 10;
                    e = (seg == 0) ? 1 : (seg == 2) ? 2 : (seg >= 5) ? 3 : 0;
                }
                if (e == 1) { vx *= qsc; vy *= qsc; }
                else if (e == 2) {
                    vx = (fminf(vx, 0.f) - log1pf(expf(-fabsf(vx)))) * 0.0625f;
                    vy = (fminf(vy, 0.f) - log1pf(expf(-fabsf(vy)))) * 0.0625f;
                } else if (e == 3) {
                    vx = vx / (1.f + expf(-vx));
                    vy = vy / (1.f + expf(-vy));
                }
                *(float2*)&C[off] = make_float2(vx, vy);
            }
        }
    }
}

constexpr int SMEM_G128 = 3 * (A_TILE_B + 128 * 128);   // 98304
constexpr int SMEM_G64  = 3 * (A_TILE_B + 64 * 128);    // 73728

// ---------------- utility kernels ----------------
__global__ void k_copy(float* __restrict__ dst, const float* __restrict__ src) {
    int idx = blockIdx.x * 256 + threadIdx.x;
    dst[idx] = src[idx];
}

__device__ __forceinline__ void bsplit(float x, __nv_bfloat16& h, __nv_bfloat16& l) {
    h = __float2bfloat16(x);
    l = __float2bfloat16(x - __bfloat162float(h));
}

__global__ void k_split(const float* __restrict__ src, __nv_bfloat16* __restrict__ hi,
                        __nv_bfloat16* __restrict__ lo) {
    size_t i4 = ((size_t)blockIdx.x * 256 + threadIdx.x) * 4;
    float4 v = *(const float4*)(src + i4);
    __nv_bfloat16 h0, h1, h2, h3, l0, l1, l2, l3;
    bsplit(v.x, h0, l0); bsplit(v.y, h1, l1); bsplit(v.z, h2, l2); bsplit(v.w, h3, l3);
    hi[i4] = h0; hi[i4+1] = h1; hi[i4+2] = h2; hi[i4+3] = h3;
    lo[i4] = l0; lo[i4+1] = l1; lo[i4+2] = l2; lo[i4+3] = l3;
}
// transpose-convert: W [K,N] fp32 -> out [N,K] bf16 hi/lo (out row stride K)
__global__ void k_wconvT(const float* __restrict__ W, __nv_bfloat16* __restrict__ hi,
                         __nv_bfloat16* __restrict__ lo, int K, int N) {
    __shared__ float s[32][33];
    int n0 = blockIdx.x * 32, k0 = blockIdx.y * 32;
    int tx = threadIdx.x, ty = threadIdx.y;
#pragma unroll
    for (int i = 0; i < 4; i++) {
        int r = ty + i * 8;
        s[r][tx] = W[(size_t)(k0 + r) * N + n0 + tx];
    }
    __syncthreads();
#pragma unroll
    for (int i = 0; i < 4; i++) {
        int r = ty + i * 8;
        float v = s[tx][r];
        size_t o = (size_t)(n0 + r) * K + k0 + tx;
        __nv_bfloat16 h, l; bsplit(v, h, l);
        hi[o] = h; lo[o] = l;
    }
}

// ---------------- fused loop-embed + rmsnorm(h+e) + bf16 splits ----------------
__global__ void __launch_bounds__(256) k_prep(float* __restrict__ h, const float* __restrict__ e,
                                              const float* __restrict__ nw, const float* __restrict__ ltab,
                                              __nv_bfloat16* __restrict__ xh, __nv_bfloat16* __restrict__ xl,
                                              __nv_bfloat16* __restrict__ hh, __nv_bfloat16* __restrict__ hl) {
    int row = blockIdx.x; size_t base = (size_t)row * cD;
    int tid = threadIdx.x;
    if (tid < cLOOPD) h[base + tid] += ltab[tid];
    __syncthreads();
    float hv[4], vals[4]; float ss = 0.f;
#pragma unroll
    for (int i = 0; i < 4; i++) {
        int c = tid + i * 256;
        float hx = h[base + c];
        hv[i] = hx;
        float v = hx + e[base + c];
        vals[i] = v; ss += v * v;
    }
    __shared__ float red[256];
    red[tid] = ss; __syncthreads();
    for (int s = 128; s > 0; s >>= 1) { if (tid < s) red[tid] += red[tid + s]; __syncthreads(); }
    float rs = rsqrtf(red[0] * (1.f / cD) + 1e-6f);
#pragma unroll
    for (int i = 0; i < 4; i++) {
        int c = tid + i * 256;
        float x = vals[i] * rs * nw[c];
        __nv_bfloat16 a, b;
        bsplit(x, a, b); xh[base + c] = a; xl[base + c] = b;
        bsplit(hv[i], a, b); hh[base + c] = a; hl[base + c] = b;
    }
}

// ---------------- final rmsnorm ----------------
__global__ void __launch_bounds__(256) k_rmsnorm(const float* __restrict__ in, const float* __restrict__ nw,
                                                 float* __restrict__ out) {
    int row = blockIdx.x; size_t base = (size_t)row * cD;
    int tid = threadIdx.x;
    float vals[4]; float ss = 0.f;
#pragma unroll
    for (int i = 0; i < 4; i++) {
        int c = tid + i * 256;
        float v = in[base + c];
        vals[i] = v; ss += v * v;
    }
    __shared__ float red[256];
    red[tid] = ss; __syncthreads();
    for (int s = 128; s > 0; s >>= 1) { if (tid < s) red[tid] += red[tid + s]; __syncthreads(); }
    float rs = rsqrtf(red[0] * (1.f / cD) + 1e-6f);
#pragma unroll
    for (int i = 0; i < 4; i++) {
        int c = tid + i * 256;
        out[base + c] = vals[i] * rs * nw[c];
    }
}

// ---------------- GLA chunk kernel ----------------
constexpr int SMEM_CHUNK = 49408 * 4;
__global__ void __launch_bounds__(256) k_chunk(float* __restrict__ pq, const float* __restrict__ pk,
                                               const float* __restrict__ pla, const float* __restrict__ pv,
                                               float* __restrict__ po, float* __restrict__ pkv,
                                               float* __restrict__ pbdec) {
    extern __shared__ float sm[];
    float* s_cum = sm;
    float* s_qt = sm + 8192;
    float* s_kt = sm + 16384;     // stride 132
    float* s_kc = sm + 24832;
    float* s_v  = sm + 33024;
    float* s_A  = sm;

    int cidx = blockIdx.x;
    int c = cidx / cBH, bh = cidx - c * cBH;
    int b = bh >> 3, hh = bh & 7;
    int t0 = c * cCH;
    size_t qbase = ((size_t)b * cT + t0) * PSTR + hh * cDKH;
    size_t vbase = ((size_t)b * cT + t0) * PSTR + hh * cDVH;
    size_t obase = ((size_t)b * cT + t0) * cDV + hh * cDVH;
    int tid = threadIdx.x;

    if (tid < 128) {
        int d = tid;
        float cum = 0.f;
        for (int i = 0; i < cCH; i++) {
            size_t off = qbase + (size_t)i * PSTR + d;
            cum += pla[off];
            s_cum[i * 128 + d] = cum;
            s_qt[i * 128 + d] = pq[off] * expf(cum);
            s_kt[i * 132 + d] = pk[off] * expf(-cum);
            s_kc[i * 128 + d] = pk[off];
        }
        float latot = cum;
        pbdec[(size_t)cidx * cDKH + d] = expf(latot);
        for (int i = 0; i < cCH; i++)
            s_kc[i * 128 + d] *= expf(latot - s_cum[i * 128 + d]);
        for (int i = 0; i < cCH; i++)
            pq[qbase + (size_t)i * PSTR + d] = s_qt[i * 128 + d];
    } else {
        int lt = tid - 128;
        for (int l = 0; l < 32; l++) {
            int idx4 = lt + l * 128;
            int i = idx4 >> 6;
            int u4 = (idx4 & 63) * 4;
            *(float4*)&s_v[i * 256 + u4] = *(const float4*)&pv[vbase + (size_t)i * PSTR + u4];
        }
    }
    __syncthreads();

    for (int idx = tid; idx < cCH * cCH; idx += 256) {
        int i = idx >> 6, j = idx & 63;
        float sum = 0.f;
        if (j <= i) {
            const float* qp = &s_qt[i * 128];
            const float* kp = &s_kt[j * 132];
#pragma unroll
            for (int d = 0; d < 128; d += 4) {
                float4 qa = *(const float4*)&qp[d];
                float4 kb = *(const float4*)&kp[d];
                sum += qa.x * kb.x + qa.y * kb.y + qa.z * kb.z + qa.w * kb.w;
            }
        }
        s_A[idx] = sum;
    }
    __syncthreads();

    // O_intra = A @ V
    {
        int uq = tid & 63;
        int il = tid >> 6;
#pragma unroll 1
        for (int step = 0; step < 16; step++) {
            int i = il + step * 4;
            float4 acc = make_float4(0.f, 0.f, 0.f, 0.f);
            const float* arow = &s_A[i * 64];
            for (int j = 0; j <= i; j++) {
                float a = arow[j];
                float4 vv = *(const float4*)&s_v[j * 256 + uq * 4];
                acc.x += a * vv.x; acc.y += a * vv.y; acc.z += a * vv.z; acc.w += a * vv.w;
            }
            *(float4*)&po[obase + (size_t)i * cDV + uq * 4] = acc;
        }
    }

    // KV_c = kc^T @ V
    {
#pragma unroll 1
        for (int s = 0; s < 8; s++) {
            int idx = tid + s * 256;
            int dq = idx >> 6;
            int uq = idx & 63;
            float4 a0 = make_float4(0.f,0.f,0.f,0.f), a1 = a0, a2 = a0, a3 = a0;
#pragma unroll 4
            for (int j = 0; j < cCH; j++) {
                float4 kc = *(const float4*)&s_kc[j * 128 + dq * 4];
                float4 vv = *(const float4*)&s_v[j * 256 + uq * 4];
                a0.x += kc.x * vv.x; a0.y += kc.x * vv.y; a0.z += kc.x * vv.z; a0.w += kc.x * vv.w;
                a1.x += kc.y * vv.x; a1.y += kc.y * vv.y; a1.z += kc.y * vv.z; a1.w += kc.y * vv.w;
                a2.x += kc.z * vv.x; a2.y += kc.z * vv.y; a2.z += kc.z * vv.z; a2.w += kc.z * vv.w;
                a3.x += kc.w * vv.x; a3.y += kc.w * vv.y; a3.z += kc.w * vv.z; a3.w += kc.w * vv.w;
            }
            size_t kvbase = (size_t)cidx * (cDKH * cDVH) + (size_t)(dq * 4) * cDVH + uq * 4;
            *(float4*)&pkv[kvbase]            = a0;
            *(float4*)&pkv[kvbase + cDVH]     = a1;
            *(float4*)&pkv[kvbase + 2 * cDVH] = a2;
            *(float4*)&pkv[kvbase + 3 * cDVH] = a3;
        }
    }
}

// ---------------- state propagation ----------------
__global__ void __launch_bounds__(256) k_state(const float* __restrict__ pkv, const float* __restrict__ pbdec,
                                               float* __restrict__ Sout) {
    int blk = blockIdx.x;
    int bh = blk >> 3;
    int vs = (blk & 7) * 32;
    int tid = threadIdx.x;
    int kr = tid >> 1;
    int vofs = vs + (tid & 1) * 16;
    float S[16];
#pragma unroll
    for (int j = 0; j < 16; j++) S[j] = 0.f;
    for (int c = 0; c < cNC; c++) {
        size_t base = ((size_t)c * cBH + bh) * (cDKH * cDVH) + (size_t)kr * cDVH + vofs;
        float bd = pbdec[((size_t)c * cBH + bh) * cDKH + kr];
#pragma unroll
        for (int j = 0; j < 16; j += 4) {
            *(float4*)&Sout[base + j] = make_float4(S[j], S[j + 1], S[j + 2], S[j + 3]);
            float4 kvv = *(const float4*)&pkv[base + j];
            S[j]     = bd * S[j]     + kvv.x;
            S[j + 1] = bd * S[j + 1] + kvv.y;
            S[j + 2] = bd * S[j + 2] + kvv.z;
            S[j + 3] = bd * S[j + 3] + kvv.w;
        }
    }
}

// ---------------- inter-chunk output + fused gate + bf16 split ----------------
__global__ void __launch_bounds__(256) k_inter(const float* __restrict__ pq, const float* __restrict__ S,
                                               const float* __restrict__ po, const float* __restrict__ pgate,
                                               __nv_bfloat16* __restrict__ oh, __nv_bfloat16* __restrict__ ol) {
    __shared__ float s_q[cCH * cDKH];
    int cidx = blockIdx.x;
    int c = cidx / cBH, bh = cidx - c * cBH;
    int b = bh >> 3, hh = bh & 7;
    int t0 = c * cCH;
    size_t qbase = ((size_t)b * cT + t0) * PSTR + hh * cDKH;
    size_t gbase = ((size_t)b * cT + t0) * PSTR + hh * cDVH;
    size_t obase = ((size_t)b * cT + t0) * cDV + hh * cDVH;
    int tid = threadIdx.x;
#pragma unroll
    for (int l = 0; l < 8; l++) {
        int idx4 = tid + l * 256;
        int i = idx4 >> 5;
        int d4 = (idx4 & 31) * 4;
        *(float4*)&s_q[i * 128 + d4] = *(const float4*)&pq[qbase + (size_t)i * PSTR + d4];
    }
    __syncthreads();
    int u = tid;
    float acc[cCH];
#pragma unroll
    for (int i = 0; i < cCH; i++) acc[i] = 0.f;
    size_t sbase = (size_t)cidx * (cDKH * cDVH) + u;
    for (int d = 0; d < cDKH; d += 4) {
        float sv0 = S[sbase + (size_t)(d + 0) * cDVH];
        float sv1 = S[sbase + (size_t)(d + 1) * cDVH];
        float sv2 = S[sbase + (size_t)(d + 2) * cDVH];
        float sv3 = S[sbase + (size_t)(d + 3) * cDVH];
#pragma unroll
        for (int i = 0; i < cCH; i++) {
            float4 qv = *(const float4*)&s_q[i * 128 + d];
            acc[i] += qv.x * sv0 + qv.y * sv1 + qv.z * sv2 + qv.w * sv3;
        }
    }
#pragma unroll
    for (int i = 0; i < cCH; i++) {
        size_t offo = obase + (size_t)i * cDV + u;
        float ov = (po[offo] + acc[i]) * pgate[gbase + (size_t)i * PSTR + u];
        __nv_bfloat16 hbf, lbf; bsplit(ov, hbf, lbf);
        oh[offo] = hbf; ol[offo] = lbf;
    }
}

// ---------------- LoRA ----------------
__global__ void __launch_bounds__(256) k_lora_down(const float* __restrict__ g, const float* __restrict__ A,
                                                   float* __restrict__ out) {
    int warp = threadIdx.x >> 5, lane = threadIdx.x & 31;
    int m = blockIdx.x * 8 + warp;
    const float* grow = &g[(size_t)m * cD];
    float acc[cRANK];
#pragma unroll
    for (int r = 0; r < cRANK; r++) acc[r] = 0.f;
    for (int kk = lane; kk < cD; kk += 32) {
        float a = grow[kk];
        const float4* Ap = (const float4*)&A[(size_t)kk * cRANK];
        float4 b0 = Ap[0], b1 = Ap[1], b2 = Ap[2], b3 = Ap[3];
        acc[0] += a * b0.x; acc[1] += a * b0.y; acc[2] += a * b0.z; acc[3] += a * b0.w;
        acc[4] += a * b1.x; acc[5] += a * b1.y; acc[6] += a * b1.z; acc[7] += a * b1.w;
        acc[8] += a * b2.x; acc[9] += a * b2.y; acc[10] += a * b2.z; acc[11] += a * b2.w;
        acc[12] += a * b3.x; acc[13] += a * b3.y; acc[14] += a * b3.z; acc[15] += a * b3.w;
    }
#pragma unroll
    for (int r = 0; r < cRANK; r++)
        for (int s = 16; s > 0; s >>= 1) acc[r] += __shfl_xor_sync(0xffffffffu, acc[r], s);
    if (lane == 0) {
#pragma unroll
        for (int r = 0; r < cRANK; r++) out[(size_t)m * cRANK + r] = acc[r];
    }
}
__global__ void __launch_bounds__(256) k_lora_up(const float* __restrict__ tmp, const float* __restrict__ Bm,
                                                 const float* __restrict__ einj, float* __restrict__ g) {
    int idx = blockIdx.x * 256 + threadIdx.x;
    int m = idx >> 10, n = idx & 1023;
    const float* tr = &tmp[(size_t)m * cRANK];
    float s = 0.f;
#pragma unroll
    for (int r = 0; r < cRANK; r++) s += tr[r] * Bm[r * cD + n];
    g[idx] += s + einj[idx];
}

// ---------------- ACT halting (first-flag folds zero-init) ----------------
__global__ void __launch_bounds__(256) k_act(const float* __restrict__ hnew, const float* __restrict__ act_w,
                                             const float* __restrict__ act_b, float* __restrict__ h,
                                             float* __restrict__ hout, float* __restrict__ cum,
                                             float* __restrict__ halt, int first) {
    int row = blockIdx.x; size_t base = (size_t)row * cD;
    int tid = threadIdx.x;
    float ss = 0.f;
#pragma unroll
    for (int i = 0; i < 4; i++) {
        int c = tid + i * 256;
        ss += hnew[base + c] * act_w[c];
    }
    __shared__ float red[256]; __shared__ float wsh;
    red[tid] = ss; __syncthreads();
    for (int s = 128; s > 0; s >>= 1) { if (tid < s) red[tid] += red[tid + s]; __syncthreads(); }
    if (tid == 0) {
        float z = red[0] + act_b[0];
        float p = 1.f / (1.f + expf(-z));
        float cm = first ? 0.f : cum[row];
        float hl = first ? 0.f : halt[row];
        float p_eff = (hl > 0.5f) ? 0.f : p;
        float ncum = cm + p_eff;
        bool newly = (hl < 0.5f) && (ncum >= 0.99f);
        float w = newly ? (1.f - cm) : p_eff;
        cum[row] = ncum;
        halt[row] = (newly || hl > 0.5f) ? 1.f : 0.f;
        wsh = w;
    }
    __syncthreads();
    float w = wsh;
#pragma unroll
    for (int i = 0; i < 4; i++) {
        int c = tid + i * 256;
        float v = hnew[base + c];
        if (first) hout[base + c] = w * v;
        else       hout[base + c] += w * v;
        h[base + c] = v;
    }
}

// ---------------- host ----------------
static void gemmB(const __nv_bfloat16* Ah, const __nv_bfloat16* Al,
                  const __nv_bfloat16* Bh, const __nv_bfloat16* Bl,
                  float* C, const float* Ci, int M, int N, int K, float scale, int epi) {
    if (N == 1024) {
        int nCTA = (M / GTM) * (N / 64);
        gemm_bf16_t<64><<<nCTA, 256, SMEM_G64>>>(Ah, Al, Bh, Bl, C, Ci, M, N, K, scale, epi);
    } else {
        int nCTA = (M / GTM) * (N / 128);
        gemm_bf16_t<128><<<nCTA, 256, SMEM_G128>>>(Ah, Al, Bh, Bl, C, Ci, M, N, K, scale, epi);
    }
}

extern "C" void kernel_launch(void* const* d_in, const int* in_sizes, int n_in,
                              void* d_out, int out_size) {
    const float* in_h  = (const float*)d_in[0];
    const float* in_e  = (const float*)d_in[1];
    const float* nw    = (const float*)d_in[2];
    const float* onw   = (const float*)d_in[3];
    const float* Wq    = (const float*)d_in[4];
    const float* Wk    = (const float*)d_in[5];
    const float* Wv    = (const float*)d_in[6];
    const float* Wgk   = (const float*)d_in[7];
    const float* Wg    = (const float*)d_in[8];
    const float* Wo    = (const float*)d_in[9];
    const float* loraA = (const float*)d_in[10];
    const float* loraB = (const float*)d_in[11];
    const float* injA  = (const float*)d_in[12];
    const float* injB  = (const float*)d_in[13];
    const float* act_w = (const float*)d_in[14];
    const float* act_b = (const float*)d_in[15];
    const float* ltab  = (const float*)d_in[16];
    float* out = (float*)d_out;

    float *p_h, *p_proj, *p_o, *p_kv, *p_S, *p_bdec,
          *p_gla, *p_lora, *p_hnew, *p_hout, *p_cum, *p_halt, *p_einj;
    cudaGetSymbolAddress((void**)&p_h, g_h);
    cudaGetSymbolAddress((void**)&p_proj, g_proj);
    cudaGetSymbolAddress((void**)&p_o, g_o);
    cudaGetSymbolAddress((void**)&p_kv, g_kv);
    cudaGetSymbolAddress((void**)&p_S, g_S);
    cudaGetSymbolAddress((void**)&p_bdec, g_bdec);
    cudaGetSymbolAddress((void**)&p_gla, g_gla);
    cudaGetSymbolAddress((void**)&p_lora, g_lora);
    cudaGetSymbolAddress((void**)&p_hnew, g_hnew);
    cudaGetSymbolAddress((void**)&p_hout, g_hout);
    cudaGetSymbolAddress((void**)&p_cum, g_cum);
    cudaGetSymbolAddress((void**)&p_halt, g_halt);
    cudaGetSymbolAddress((void**)&p_einj, g_einj);

    __nv_bfloat16 *wph, *wpl, *woh, *wol, *iah, *ial, *ibh, *ibl,
                  *eh, *el, *xh, *xl, *hh, *hl, *oh, *ol;
    cudaGetSymbolAddress((void**)&wph, g_wph);  cudaGetSymbolAddress((void**)&wpl, g_wpl);
    cudaGetSymbolAddress((void**)&woh, g_woh);  cudaGetSymbolAddress((void**)&wol, g_wol);
    cudaGetSymbolAddress((void**)&iah, g_iah);  cudaGetSymbolAddress((void**)&ial, g_ial);
    cudaGetSymbolAddress((void**)&ibh, g_ibh);  cudaGetSymbolAddress((void**)&ibl, g_ibl);
    cudaGetSymbolAddress((void**)&eh, g_eh);    cudaGetSymbolAddress((void**)&el, g_el);
    cudaGetSymbolAddress((void**)&xh, g_xh);    cudaGetSymbolAddress((void**)&xl, g_xl);
    cudaGetSymbolAddress((void**)&hh, g_hh2);   cudaGetSymbolAddress((void**)&hl, g_hl2);
    cudaGetSymbolAddress((void**)&oh, g_oh);    cudaGetSymbolAddress((void**)&ol, g_ol);

    cudaFuncSetAttribute(k_chunk, cudaFuncAttributeMaxDynamicSharedMemorySize, SMEM_CHUNK);
    cudaFuncSetAttribute(gemm_bf16_t<128>, cudaFuncAttributeMaxDynamicSharedMemorySize, SMEM_G128);
    cudaFuncSetAttribute(gemm_bf16_t<64>,  cudaFuncAttributeMaxDynamicSharedMemorySize, SMEM_G64);

    const int nBig = cM * cD / 256;

    // Launch order chosen so the 6th launch (ncu -s 5 -c 1 capture) is the
    // GTN=128 GEMM — finally profiling the dominant kernel.
    k_copy<<<nBig, 256>>>(p_h, in_h);                                   // 1
    k_split<<<cD * cD / 1024, 256>>>(injB, ibh, ibl);                   // 2
    k_split<<<cM * cD / 1024, 256>>>(in_e, eh, el);                     // 3
    k_split<<<cD * cD / 1024, 256>>>(injA, iah, ial);                   // 4
    dim3 tb(32, 8);
    k_wconvT<<<dim3(cD / 32, cDV / 32), tb>>>(Wo,  woh, wol, cDV, cD);  // 5
    // 6: einj = e @ injB^T  (forced through the GTN=128 template for profiling)
    {
        int nCTA = (cM / GTM) * (cD / 128);
        gemm_bf16_t<128><<<nCTA, 256, SMEM_G128>>>(eh, el, ibh, ibl, p_einj, nullptr,
                                                   cM, cD, cD, 0.f, 0);
    }

    // remaining weight conversions
    k_wconvT<<<dim3(cDK / 32, cD / 32), tb>>>(Wq,  wph,                       wpl,                       cD, cDK);
    k_wconvT<<<dim3(cDK / 32, cD / 32), tb>>>(Wk,  wph + (size_t)OFF_K  * cD, wpl + (size_t)OFF_K  * cD, cD, cDK);
    k_wconvT<<<dim3(cDK / 32, cD / 32), tb>>>(Wgk, wph + (size_t)OFF_LA * cD, wpl + (size_t)OFF_LA * cD, cD, cDK);
    k_wconvT<<<dim3(cDV / 32, cD / 32), tb>>>(Wv,  wph + (size_t)OFF_V  * cD, wpl + (size_t)OFF_V  * cD, cD, cDV);
    k_wconvT<<<dim3(cDV / 32, cD / 32), tb>>>(Wg,  wph + (size_t)OFF_G  * cD, wpl + (size_t)OFF_G  * cD, cD, cDV);

    const float qscale = 0.08838834764831845f;

    for (int t = 0; t < cNL; t++) {
        k_prep<<<cM, 256>>>(p_h, in_e, nw, ltab + t * cLOOPD, xh, xl, hh, hl);

        // single merged projection GEMM: q|k|la|v|gate with per-segment epilogue
        gemmB(xh, xl, wph, wpl, p_proj, nullptr, cM, PSTR, cD, qscale, 9);

        k_chunk<<<cNC * cBH, 256, SMEM_CHUNK>>>(p_proj, p_proj + OFF_K, p_proj + OFF_LA,
                                                p_proj + OFF_V, p_o, p_kv, p_bdec);
        k_state<<<cBH * 8, 256>>>(p_kv, p_bdec, p_S);
        k_inter<<<cNC * cBH, 256>>>(p_proj, p_S, p_o, p_proj + OFF_G, oh, ol);

        gemmB(oh, ol, woh, wol, p_gla, nullptr, cM, cD, cDV, 0.f, 0);

        k_lora_down<<<cM / 8, 256>>>(p_gla, loraA + (size_t)t * cD * cRANK, p_lora);
        k_lora_up<<<nBig, 256>>>(p_lora, loraB + (size_t)t * cRANK * cD, p_einj, p_gla);

        gemmB(hh, hl, iah, ial, p_hnew, p_gla, cM, cD, cD, 0.f, 0);

        k_act<<<cM, 256>>>(p_hnew, act_w, act_b, p_h, p_hout, p_cum, p_halt, t == 0 ? 1 : 0);
    }
    k_rmsnorm<<<cM, 256>>>(p_hout, onw, out);
}

// round 15
// speedup vs baseline: 2.6106x; 1.6106x over previous
#include <cuda_runtime.h>
#include <cuda_fp16.h>
#include <math.h>
#include <stdint.h>

// ---------------- problem constants ----------------
constexpr int cB = 4, cT = 4096, cD = 1024, cH = 8;
constexpr int cDK = 1024, cDV = 2048, cDKH = 128, cDVH = 256;
constexpr int cRANK = 16, cLOOPD = 128, cNL = 4;
constexpr int cCH = 64;
constexpr int cNC = cT / cCH;
constexpr int cBH = cB * cH;
constexpr int cM = cB * cT;
constexpr int PSTR = 7168;              // merged projection row stride (q|k|la|v|gate)
constexpr int OFF_K = 1024, OFF_LA = 2048, OFF_V = 3072, OFF_G = 5120;

// ---------------- device scratch ----------------
__device__ float g_h[cM * cD];
__device__ float g_proj[(size_t)cM * PSTR];
__device__ float g_o[cM * cDV];
__device__ float g_kv[cNC * cBH * cDKH * cDVH];
__device__ float g_S[cNC * cBH * cDKH * cDVH];
__device__ float g_bdec[cNC * cBH * cDKH];
__device__ float g_gla[cM * cD];
__device__ float g_lora[cM * cRANK];
__device__ float g_hnew[cM * cD];
__device__ float g_hout[cM * cD];
__device__ float g_cum[cM];
__device__ float g_halt[cM];
__device__ float g_einj[cM * cD];

// fp16 buffers (single precision level — no lo parts)
__device__ __align__(16) __half g_wph[(size_t)PSTR * cD];
__device__ __align__(16) __half g_woh[cDV * cD];
__device__ __align__(16) __half g_iah[cD * cD];
__device__ __align__(16) __half g_ibh[cD * cD];
__device__ __align__(16) __half g_eh[cM * cD];
__device__ __align__(16) __half g_xh[cM * cD];
__device__ __align__(16) __half g_hh2[cM * cD];
__device__ __align__(16) __half g_oh[cM * cDV];

// ---------------- helpers ----------------
__device__ __forceinline__ uint32_t s2u(const void* p) {
    uint32_t a;
    asm("{ .reg .u64 t; cvta.to.shared.u64 t, %1; cvt.u32.u64 %0, t; }" : "=r"(a) : "l"(p));
    return a;
}
__device__ __forceinline__ uint32_t sw128(uint32_t off) { return off ^ ((off >> 3) & 0x70); }

#define LDSM4(r, a) \
    asm volatile("ldmatrix.sync.aligned.m8n8.x4.shared.b16 {%0,%1,%2,%3}, [%4];" \
        : "=r"((r)[0]), "=r"((r)[1]), "=r"((r)[2]), "=r"((r)[3]) : "r"(a))

__device__ __forceinline__ void mma_f16(float* d, const uint32_t* a, const uint32_t* b) {
    asm volatile("mma.sync.aligned.m16n8k16.row.col.f32.f16.f16.f32 "
        "{%0,%1,%2,%3}, {%4,%5,%6,%7}, {%8,%9}, {%0,%1,%2,%3};"
        : "+f"(d[0]), "+f"(d[1]), "+f"(d[2]), "+f"(d[3])
        : "r"(a[0]), "r"(a[1]), "r"(a[2]), "r"(a[3]), "r"(b[0]), "r"(b[1]));
}

// ---------------- mma.sync fp16 single-product GEMM, 2 CTAs/SM, panel raster ----------------
// A:[M,K] fp16 row-major; B:[N,K] fp16 K-major. CTA tile 128xGTN_, K-chunk 64.
// 1D grid, m-major within 8-wide n-panels. 3-stage cp.async, single-barrier pipeline.
// epi: 0 none, 1 scale, 2 logsig/16, 3 silu, 9 merged-projection per-segment.
constexpr int GTM = 128, GKC = 64;
constexpr int A_TILE_B = 16384;          // 128 rows x 64 fp16 = 128B/row

template <int GTN_>
__global__ void __launch_bounds__(256, 2) gemm_fp16_t(
    const __half* __restrict__ A, const __half* __restrict__ B,
    float* __restrict__ C, const float* __restrict__ Ci,
    int M, int N, int K, float scale, int epi)
{
    constexpr int B_TILE_B = GTN_ * 128;
    constexpr int STG = A_TILE_B + B_TILE_B;
    constexpr int NFRAG = GTN_ / 16;      // n8 fragments per warp (8 or 4)
    constexpr int NLD = GTN_ / 32;        // B ldmatrix calls per kk (4 or 2)
    constexpr int NT = (1024 + GTN_ * 8) / 256;   // 16B transfers/thread/stage (8 or 6)

    extern __shared__ char smem[];
    int tid = threadIdx.x;
    int lane = tid & 31, wid = tid >> 5;

    // panel raster: m-major within 8-wide n-panels
    int mbCnt = M >> 7;
    int per_panel = mbCnt * 8;
    int panel = blockIdx.x / per_panel;
    int rem = blockIdx.x - panel * per_panel;
    int bm = rem >> 3;
    int bn = panel * 8 + (rem & 7);
    int m0 = bm * GTM, n0 = bn * GTN_;

    int wm = (wid & 3) * 32, wn = (wid >> 2) * (GTN_ / 2);

    const int NCk = K / GKC;

    const __half* pA = A + (size_t)m0 * K;
    const __half* pB = B + (size_t)n0 * K;

    auto load_stage = [&](int kc, int s) {
        char* base = smem + s * STG;
        int k0 = kc * GKC;
#pragma unroll
        for (int i = 0; i < NT; i++) {
            int gg = tid + i * 256;
            int tile = (gg >= 1024) ? 1 : 0;       // first 1024 transfers = A
            int idx = tile ? gg - 1024 : gg;
            int r = idx >> 3, seg = idx & 7;
            uint32_t off = sw128((uint32_t)(r * 128 + seg * 16));
            const __half* src = (tile ? pB : pA) + (size_t)r * K + k0 + seg * 8;
            uint32_t dst = s2u(base + tile * A_TILE_B + off);
            asm volatile("cp.async.cg.shared.global [%0], [%1], 16;" :: "r"(dst), "l"(src));
        }
        asm volatile("cp.async.commit_group;" ::: "memory");
    };

    float acc[2][NFRAG][4];
#pragma unroll
    for (int mf = 0; mf < 2; mf++)
#pragma unroll
        for (int nf = 0; nf < NFRAG; nf++)
#pragma unroll
            for (int j = 0; j < 4; j++) acc[mf][nf][j] = 0.f;

    load_stage(0, 0);
    load_stage(1, 1);

    int a_row = (lane & 15);
    int a_col8 = (lane >> 4);
    int b_row = (lane & 7) + ((lane >> 4) & 1) * 8;
    int b_col8 = (lane >> 3) & 1;

    for (int c = 0; c < NCk; c++) {
        asm volatile("cp.async.wait_group 1;" ::: "memory");
        __syncthreads();
        if (c + 2 < NCk) load_stage(c + 2, (c + 2) % 3);
        else asm volatile("cp.async.commit_group;" ::: "memory");

        char* base = smem + (c % 3) * STG;
        uint32_t sA = s2u(base), sB = sA + A_TILE_B;
#pragma unroll
        for (int kk = 0; kk < 4; kk++) {
            uint32_t kb = (uint32_t)((kk * 16 + ((kk & 0) ) ) * 2);  // base byte of this k16
            kb = (uint32_t)(kk * 32);
            uint32_t ah[2][4];
#pragma unroll
            for (int mf = 0; mf < 2; mf++) {
                uint32_t rowb = (uint32_t)((wm + mf * 16 + a_row) * 128);
                LDSM4(ah[mf], sA + sw128(rowb + kb + a_col8 * 16));
            }
            uint32_t bfr[NFRAG][2];
#pragma unroll
            for (int g = 0; g < NLD; g++) {
                uint32_t rowb = (uint32_t)((wn + g * 16 + b_row) * 128);
                uint32_t r[4];
                LDSM4(r, sB + sw128(rowb + kb + b_col8 * 16));
                bfr[g * 2][0] = r[0]; bfr[g * 2][1] = r[1];
                bfr[g * 2 + 1][0] = r[2]; bfr[g * 2 + 1][1] = r[3];
            }
#pragma unroll
            for (int mf = 0; mf < 2; mf++)
#pragma unroll
                for (int nf = 0; nf < NFRAG; nf++)
                    mma_f16(acc[mf][nf], ah[mf], bfr[nf]);
        }
    }

    const float qsc = scale;
#pragma unroll
    for (int mf = 0; mf < 2; mf++) {
#pragma unroll
        for (int nf = 0; nf < NFRAG; nf++) {
            int r0 = m0 + wm + mf * 16 + (lane >> 2);
            int cc = n0 + wn + nf * 8 + (lane & 3) * 2;
#pragma unroll
            for (int hh = 0; hh < 2; hh++) {
                int r = r0 + hh * 8;
                float vx = acc[mf][nf][hh * 2], vy = acc[mf][nf][hh * 2 + 1];
                size_t off = (size_t)r * N + cc;
                if (Ci) { vx += Ci[off]; vy += Ci[off + 1]; }
                int e = epi;
                if (e == 9) {
                    int seg = cc >> 10;
                    e = (seg == 0) ? 1 : (seg == 2) ? 2 : (seg >= 5) ? 3 : 0;
                }
                if (e == 1) { vx *= qsc; vy *= qsc; }
                else if (e == 2) {
                    vx = (fminf(vx, 0.f) - log1pf(expf(-fabsf(vx)))) * 0.0625f;
                    vy = (fminf(vy, 0.f) - log1pf(expf(-fabsf(vy)))) * 0.0625f;
                } else if (e == 3) {
                    vx = vx / (1.f + expf(-vx));
                    vy = vy / (1.f + expf(-vy));
                }
                *(float2*)&C[off] = make_float2(vx, vy);
            }
        }
    }
}

constexpr int SMEM_G128 = 3 * (A_TILE_B + 128 * 128);   // 98304
constexpr int SMEM_G64  = 3 * (A_TILE_B + 64 * 128);    // 73728

// ---------------- utility kernels ----------------
__global__ void k_copy(float* __restrict__ dst, const float* __restrict__ src) {
    int idx = blockIdx.x * 256 + threadIdx.x;
    dst[idx] = src[idx];
}

// fp32 -> fp16 (4 per thread)
__global__ void k_cvt(const float* __restrict__ src, __half* __restrict__ dst) {
    size_t i4 = ((size_t)blockIdx.x * 256 + threadIdx.x) * 4;
    float4 v = *(const float4*)(src + i4);
    __half2* d = (__half2*)(dst + i4);
    d[0] = __floats2half2_rn(v.x, v.y);
    d[1] = __floats2half2_rn(v.z, v.w);
}
// transpose-convert: W [K,N] fp32 -> out [N,K] fp16 (out row stride K)
__global__ void k_wconvT(const float* __restrict__ W, __half* __restrict__ out, int K, int N) {
    __shared__ float s[32][33];
    int n0 = blockIdx.x * 32, k0 = blockIdx.y * 32;
    int tx = threadIdx.x, ty = threadIdx.y;
#pragma unroll
    for (int i = 0; i < 4; i++) {
        int r = ty + i * 8;
        s[r][tx] = W[(size_t)(k0 + r) * N + n0 + tx];
    }
    __syncthreads();
#pragma unroll
    for (int i = 0; i < 4; i++) {
        int r = ty + i * 8;
        out[(size_t)(n0 + r) * K + k0 + tx] = __float2half(s[tx][r]);
    }
}

// ---------------- fused loop-embed + rmsnorm(h+e) + fp16 conversions ----------------
__global__ void __launch_bounds__(256) k_prep(float* __restrict__ h, const float* __restrict__ e,
                                              const float* __restrict__ nw, const float* __restrict__ ltab,
                                              __half* __restrict__ xh, __half* __restrict__ hh) {
    int row = blockIdx.x; size_t base = (size_t)row * cD;
    int tid = threadIdx.x;
    if (tid < cLOOPD) h[base + tid] += ltab[tid];
    __syncthreads();
    float hv[4], vals[4]; float ss = 0.f;
#pragma unroll
    for (int i = 0; i < 4; i++) {
        int c = tid + i * 256;
        float hx = h[base + c];
        hv[i] = hx;
        float v = hx + e[base + c];
        vals[i] = v; ss += v * v;
    }
    __shared__ float red[256];
    red[tid] = ss; __syncthreads();
    for (int s = 128; s > 0; s >>= 1) { if (tid < s) red[tid] += red[tid + s]; __syncthreads(); }
    float rs = rsqrtf(red[0] * (1.f / cD) + 1e-6f);
#pragma unroll
    for (int i = 0; i < 4; i++) {
        int c = tid + i * 256;
        xh[base + c] = __float2half(vals[i] * rs * nw[c]);
        hh[base + c] = __float2half(hv[i]);
    }
}

// ---------------- final rmsnorm ----------------
__global__ void __launch_bounds__(256) k_rmsnorm(const float* __restrict__ in, const float* __restrict__ nw,
                                                 float* __restrict__ out) {
    int row = blockIdx.x; size_t base = (size_t)row * cD;
    int tid = threadIdx.x;
    float vals[4]; float ss = 0.f;
#pragma unroll
    for (int i = 0; i < 4; i++) {
        int c = tid + i * 256;
        float v = in[base + c];
        vals[i] = v; ss += v * v;
    }
    __shared__ float red[256];
    red[tid] = ss; __syncthreads();
    for (int s = 128; s > 0; s >>= 1) { if (tid < s) red[tid] += red[tid + s]; __syncthreads(); }
    float rs = rsqrtf(red[0] * (1.f / cD) + 1e-6f);
#pragma unroll
    for (int i = 0; i < 4; i++) {
        int c = tid + i * 256;
        out[base + c] = vals[i] * rs * nw[c];
    }
}

// ---------------- GLA chunk kernel ----------------
constexpr int SMEM_CHUNK = 49408 * 4;
__global__ void __launch_bounds__(256) k_chunk(float* __restrict__ pq, const float* __restrict__ pk,
                                               const float* __restrict__ pla, const float* __restrict__ pv,
                                               float* __restrict__ po, float* __restrict__ pkv,
                                               float* __restrict__ pbdec) {
    extern __shared__ float sm[];
    float* s_cum = sm;
    float* s_qt = sm + 8192;
    float* s_kt = sm + 16384;     // stride 132
    float* s_kc = sm + 24832;
    float* s_v  = sm + 33024;
    float* s_A  = sm;

    int cidx = blockIdx.x;
    int c = cidx / cBH, bh = cidx - c * cBH;
    int b = bh >> 3, hh = bh & 7;
    int t0 = c * cCH;
    size_t qbase = ((size_t)b * cT + t0) * PSTR + hh * cDKH;
    size_t vbase = ((size_t)b * cT + t0) * PSTR + hh * cDVH;
    size_t obase = ((size_t)b * cT + t0) * cDV + hh * cDVH;
    int tid = threadIdx.x;

    if (tid < 128) {
        int d = tid;
        float cum = 0.f;
        for (int i = 0; i < cCH; i++) {
            size_t off = qbase + (size_t)i * PSTR + d;
            cum += pla[off];
            s_cum[i * 128 + d] = cum;
            s_qt[i * 128 + d] = pq[off] * expf(cum);
            s_kt[i * 132 + d] = pk[off] * expf(-cum);
            s_kc[i * 128 + d] = pk[off];
        }
        float latot = cum;
        pbdec[(size_t)cidx * cDKH + d] = expf(latot);
        for (int i = 0; i < cCH; i++)
            s_kc[i * 128 + d] *= expf(latot - s_cum[i * 128 + d]);
        for (int i = 0; i < cCH; i++)
            pq[qbase + (size_t)i * PSTR + d] = s_qt[i * 128 + d];
    } else {
        int lt = tid - 128;
        for (int l = 0; l < 32; l++) {
            int idx4 = lt + l * 128;
            int i = idx4 >> 6;
            int u4 = (idx4 & 63) * 4;
            *(float4*)&s_v[i * 256 + u4] = *(const float4*)&pv[vbase + (size_t)i * PSTR + u4];
        }
    }
    __syncthreads();

    for (int idx = tid; idx < cCH * cCH; idx += 256) {
        int i = idx >> 6, j = idx & 63;
        float sum = 0.f;
        if (j <= i) {
            const float* qp = &s_qt[i * 128];
            const float* kp = &s_kt[j * 132];
#pragma unroll
            for (int d = 0; d < 128; d += 4) {
                float4 qa = *(const float4*)&qp[d];
                float4 kb = *(const float4*)&kp[d];
                sum += qa.x * kb.x + qa.y * kb.y + qa.z * kb.z + qa.w * kb.w;
            }
        }
        s_A[idx] = sum;
    }
    __syncthreads();

    // O_intra = A @ V
    {
        int uq = tid & 63;
        int il = tid >> 6;
#pragma unroll 1
        for (int step = 0; step < 16; step++) {
            int i = il + step * 4;
            float4 acc = make_float4(0.f, 0.f, 0.f, 0.f);
            const float* arow = &s_A[i * 64];
            for (int j = 0; j <= i; j++) {
                float a = arow[j];
                float4 vv = *(const float4*)&s_v[j * 256 + uq * 4];
                acc.x += a * vv.x; acc.y += a * vv.y; acc.z += a * vv.z; acc.w += a * vv.w;
            }
            *(float4*)&po[obase + (size_t)i * cDV + uq * 4] = acc;
        }
    }

    // KV_c = kc^T @ V
    {
#pragma unroll 1
        for (int s = 0; s < 8; s++) {
            int idx = tid + s * 256;
            int dq = idx >> 6;
            int uq = idx & 63;
            float4 a0 = make_float4(0.f,0.f,0.f,0.f), a1 = a0, a2 = a0, a3 = a0;
#pragma unroll 4
            for (int j = 0; j < cCH; j++) {
                float4 kc = *(const float4*)&s_kc[j * 128 + dq * 4];
                float4 vv = *(const float4*)&s_v[j * 256 + uq * 4];
                a0.x += kc.x * vv.x; a0.y += kc.x * vv.y; a0.z += kc.x * vv.z; a0.w += kc.x * vv.w;
                a1.x += kc.y * vv.x; a1.y += kc.y * vv.y; a1.z += kc.y * vv.z; a1.w += kc.y * vv.w;
                a2.x += kc.z * vv.x; a2.y += kc.z * vv.y; a2.z += kc.z * vv.z; a2.w += kc.z * vv.w;
                a3.x += kc.w * vv.x; a3.y += kc.w * vv.y; a3.z += kc.w * vv.z; a3.w += kc.w * vv.w;
            }
            size_t kvbase = (size_t)cidx * (cDKH * cDVH) + (size_t)(dq * 4) * cDVH + uq * 4;
            *(float4*)&pkv[kvbase]            = a0;
            *(float4*)&pkv[kvbase + cDVH]     = a1;
            *(float4*)&pkv[kvbase + 2 * cDVH] = a2;
            *(float4*)&pkv[kvbase + 3 * cDVH] = a3;
        }
    }
}

// ---------------- state propagation ----------------
__global__ void __launch_bounds__(256) k_state(const float* __restrict__ pkv, const float* __restrict__ pbdec,
                                               float* __restrict__ Sout) {
    int blk = blockIdx.x;
    int bh = blk >> 3;
    int vs = (blk & 7) * 32;
    int tid = threadIdx.x;
    int kr = tid >> 1;
    int vofs = vs + (tid & 1) * 16;
    float S[16];
#pragma unroll
    for (int j = 0; j < 16; j++) S[j] = 0.f;
    for (int c = 0; c < cNC; c++) {
        size_t base = ((size_t)c * cBH + bh) * (cDKH * cDVH) + (size_t)kr * cDVH + vofs;
        float bd = pbdec[((size_t)c * cBH + bh) * cDKH + kr];
#pragma unroll
        for (int j = 0; j < 16; j += 4) {
            *(float4*)&Sout[base + j] = make_float4(S[j], S[j + 1], S[j + 2], S[j + 3]);
            float4 kvv = *(const float4*)&pkv[base + j];
            S[j]     = bd * S[j]     + kvv.x;
            S[j + 1] = bd * S[j + 1] + kvv.y;
            S[j + 2] = bd * S[j + 2] + kvv.z;
            S[j + 3] = bd * S[j + 3] + kvv.w;
        }
    }
}

// ---------------- inter-chunk output + fused gate + fp16 convert ----------------
__global__ void __launch_bounds__(256) k_inter(const float* __restrict__ pq, const float* __restrict__ S,
                                               const float* __restrict__ po, const float* __restrict__ pgate,
                                               __half* __restrict__ oh) {
    __shared__ float s_q[cCH * cDKH];
    int cidx = blockIdx.x;
    int c = cidx / cBH, bh = cidx - c * cBH;
    int b = bh >> 3, hh = bh & 7;
    int t0 = c * cCH;
    size_t qbase = ((size_t)b * cT + t0) * PSTR + hh * cDKH;
    size_t gbase = ((size_t)b * cT + t0) * PSTR + hh * cDVH;
    size_t obase = ((size_t)b * cT + t0) * cDV + hh * cDVH;
    int tid = threadIdx.x;
#pragma unroll
    for (int l = 0; l < 8; l++) {
        int idx4 = tid + l * 256;
        int i = idx4 >> 5;
        int d4 = (idx4 & 31) * 4;
        *(float4*)&s_q[i * 128 + d4] = *(const float4*)&pq[qbase + (size_t)i * PSTR + d4];
    }
    __syncthreads();
    int u = tid;
    float acc[cCH];
#pragma unroll
    for (int i = 0; i < cCH; i++) acc[i] = 0.f;
    size_t sbase = (size_t)cidx * (cDKH * cDVH) + u;
    for (int d = 0; d < cDKH; d += 4) {
        float sv0 = S[sbase + (size_t)(d + 0) * cDVH];
        float sv1 = S[sbase + (size_t)(d + 1) * cDVH];
        float sv2 = S[sbase + (size_t)(d + 2) * cDVH];
        float sv3 = S[sbase + (size_t)(d + 3) * cDVH];
#pragma unroll
        for (int i = 0; i < cCH; i++) {
            float4 qv = *(const float4*)&s_q[i * 128 + d];
            acc[i] += qv.x * sv0 + qv.y * sv1 + qv.z * sv2 + qv.w * sv3;
        }
    }
#pragma unroll
    for (int i = 0; i < cCH; i++) {
        size_t offo = obase + (size_t)i * cDV + u;
        float ov = (po[offo] + acc[i]) * pgate[gbase + (size_t)i * PSTR + u];
        oh[offo] = __float2half(ov);
    }
}

// ---------------- LoRA ----------------
__global__ void __launch_bounds__(256) k_lora_down(const float* __restrict__ g, const float* __restrict__ A,
                                                   float* __restrict__ out) {
    int warp = threadIdx.x >> 5, lane = threadIdx.x & 31;
    int m = blockIdx.x * 8 + warp;
    const float* grow = &g[(size_t)m * cD];
    float acc[cRANK];
#pragma unroll
    for (int r = 0; r < cRANK; r++) acc[r] = 0.f;
    for (int kk = lane; kk < cD; kk += 32) {
        float a = grow[kk];
        const float4* Ap = (const float4*)&A[(size_t)kk * cRANK];
        float4 b0 = Ap[0], b1 = Ap[1], b2 = Ap[2], b3 = Ap[3];
        acc[0] += a * b0.x; acc[1] += a * b0.y; acc[2] += a * b0.z; acc[3] += a * b0.w;
        acc[4] += a * b1.x; acc[5] += a * b1.y; acc[6] += a * b1.z; acc[7] += a * b1.w;
        acc[8] += a * b2.x; acc[9] += a * b2.y; acc[10] += a * b2.z; acc[11] += a * b2.w;
        acc[12] += a * b3.x; acc[13] += a * b3.y; acc[14] += a * b3.z; acc[15] += a * b3.w;
    }
#pragma unroll
    for (int r = 0; r < cRANK; r++)
        for (int s = 16; s > 0; s >>= 1) acc[r] += __shfl_xor_sync(0xffffffffu, acc[r], s);
    if (lane == 0) {
#pragma unroll
        for (int r = 0; r < cRANK; r++) out[(size_t)m * cRANK + r] = acc[r];
    }
}
__global__ void __launch_bounds__(256) k_lora_up(const float* __restrict__ tmp, const float* __restrict__ Bm,
                                                 const float* __restrict__ einj, float* __restrict__ g) {
    int idx = blockIdx.x * 256 + threadIdx.x;
    int m = idx >> 10, n = idx & 1023;
    const float* tr = &tmp[(size_t)m * cRANK];
    float s = 0.f;
#pragma unroll
    for (int r = 0; r < cRANK; r++) s += tr[r] * Bm[r * cD + n];
    g[idx] += s + einj[idx];
}

// ---------------- ACT halting (first-flag folds zero-init) ----------------
__global__ void __launch_bounds__(256) k_act(const float* __restrict__ hnew, const float* __restrict__ act_w,
                                             const float* __restrict__ act_b, float* __restrict__ h,
                                             float* __restrict__ hout, float* __restrict__ cum,
                                             float* __restrict__ halt, int first) {
    int row = blockIdx.x; size_t base = (size_t)row * cD;
    int tid = threadIdx.x;
    float ss = 0.f;
#pragma unroll
    for (int i = 0; i < 4; i++) {
        int c = tid + i * 256;
        ss += hnew[base + c] * act_w[c];
    }
    __shared__ float red[256]; __shared__ float wsh;
    red[tid] = ss; __syncthreads();
    for (int s = 128; s > 0; s >>= 1) { if (tid < s) red[tid] += red[tid + s]; __syncthreads(); }
    if (tid == 0) {
        float z = red[0] + act_b[0];
        float p = 1.f / (1.f + expf(-z));
        float cm = first ? 0.f : cum[row];
        float hl = first ? 0.f : halt[row];
        float p_eff = (hl > 0.5f) ? 0.f : p;
        float ncum = cm + p_eff;
        bool newly = (hl < 0.5f) && (ncum >= 0.99f);
        float w = newly ? (1.f - cm) : p_eff;
        cum[row] = ncum;
        halt[row] = (newly || hl > 0.5f) ? 1.f : 0.f;
        wsh = w;
    }
    __syncthreads();
    float w = wsh;
#pragma unroll
    for (int i = 0; i < 4; i++) {
        int c = tid + i * 256;
        float v = hnew[base + c];
        if (first) hout[base + c] = w * v;
        else       hout[base + c] += w * v;
        h[base + c] = v;
    }
}

// ---------------- host ----------------
static void gemmH(const __half* A, const __half* B, float* C, const float* Ci,
                  int M, int N, int K, float scale, int epi) {
    if (N == 1024) {
        int nCTA = (M / GTM) * (N / 64);
        gemm_fp16_t<64><<<nCTA, 256, SMEM_G64>>>(A, B, C, Ci, M, N, K, scale, epi);
    } else {
        int nCTA = (M / GTM) * (N / 128);
        gemm_fp16_t<128><<<nCTA, 256, SMEM_G128>>>(A, B, C, Ci, M, N, K, scale, epi);
    }
}

extern "C" void kernel_launch(void* const* d_in, const int* in_sizes, int n_in,
                              void* d_out, int out_size) {
    const float* in_h  = (const float*)d_in[0];
    const float* in_e  = (const float*)d_in[1];
    const float* nw    = (const float*)d_in[2];
    const float* onw   = (const float*)d_in[3];
    const float* Wq    = (const float*)d_in[4];
    const float* Wk    = (const float*)d_in[5];
    const float* Wv    = (const float*)d_in[6];
    const float* Wgk   = (const float*)d_in[7];
    const float* Wg    = (const float*)d_in[8];
    const float* Wo    = (const float*)d_in[9];
    const float* loraA = (const float*)d_in[10];
    const float* loraB = (const float*)d_in[11];
    const float* injA  = (const float*)d_in[12];
    const float* injB  = (const float*)d_in[13];
    const float* act_w = (const float*)d_in[14];
    const float* act_b = (const float*)d_in[15];
    const float* ltab  = (const float*)d_in[16];
    float* out = (float*)d_out;

    float *p_h, *p_proj, *p_o, *p_kv, *p_S, *p_bdec,
          *p_gla, *p_lora, *p_hnew, *p_hout, *p_cum, *p_halt, *p_einj;
    cudaGetSymbolAddress((void**)&p_h, g_h);
    cudaGetSymbolAddress((void**)&p_proj, g_proj);
    cudaGetSymbolAddress((void**)&p_o, g_o);
    cudaGetSymbolAddress((void**)&p_kv, g_kv);
    cudaGetSymbolAddress((void**)&p_S, g_S);
    cudaGetSymbolAddress((void**)&p_bdec, g_bdec);
    cudaGetSymbolAddress((void**)&p_gla, g_gla);
    cudaGetSymbolAddress((void**)&p_lora, g_lora);
    cudaGetSymbolAddress((void**)&p_hnew, g_hnew);
    cudaGetSymbolAddress((void**)&p_hout, g_hout);
    cudaGetSymbolAddress((void**)&p_cum, g_cum);
    cudaGetSymbolAddress((void**)&p_halt, g_halt);
    cudaGetSymbolAddress((void**)&p_einj, g_einj);

    __half *wph, *woh, *iah, *ibh, *eh, *xh, *hh, *oh;
    cudaGetSymbolAddress((void**)&wph, g_wph);
    cudaGetSymbolAddress((void**)&woh, g_woh);
    cudaGetSymbolAddress((void**)&iah, g_iah);
    cudaGetSymbolAddress((void**)&ibh, g_ibh);
    cudaGetSymbolAddress((void**)&eh, g_eh);
    cudaGetSymbolAddress((void**)&xh, g_xh);
    cudaGetSymbolAddress((void**)&hh, g_hh2);
    cudaGetSymbolAddress((void**)&oh, g_oh);

    cudaFuncSetAttribute(k_chunk, cudaFuncAttributeMaxDynamicSharedMemorySize, SMEM_CHUNK);
    cudaFuncSetAttribute(gemm_fp16_t<128>, cudaFuncAttributeMaxDynamicSharedMemorySize, SMEM_G128);
    cudaFuncSetAttribute(gemm_fp16_t<64>,  cudaFuncAttributeMaxDynamicSharedMemorySize, SMEM_G64);

    const int nBig = cM * cD / 256;

    k_copy<<<nBig, 256>>>(p_h, in_h);
    k_cvt<<<cD * cD / 1024, 256>>>(injB, ibh);
    k_cvt<<<cM * cD / 1024, 256>>>(in_e, eh);
    k_cvt<<<cD * cD / 1024, 256>>>(injA, iah);
    dim3 tb(32, 8);
    k_wconvT<<<dim3(cD / 32, cDV / 32), tb>>>(Wo, woh, cDV, cD);
    // einj = e @ injB^T (GTN=128 template placed early for potential ncu capture)
    {
        int nCTA = (cM / GTM) * (cD / 128);
        gemm_fp16_t<128><<<nCTA, 256, SMEM_G128>>>(eh, ibh, p_einj, nullptr, cM, cD, cD, 0.f, 0);
    }

    k_wconvT<<<dim3(cDK / 32, cD / 32), tb>>>(Wq,  wph,                       cD, cDK);
    k_wconvT<<<dim3(cDK / 32, cD / 32), tb>>>(Wk,  wph + (size_t)OFF_K  * cD, cD, cDK);
    k_wconvT<<<dim3(cDK / 32, cD / 32), tb>>>(Wgk, wph + (size_t)OFF_LA * cD, cD, cDK);
    k_wconvT<<<dim3(cDV / 32, cD / 32), tb>>>(Wv,  wph + (size_t)OFF_V  * cD, cD, cDV);
    k_wconvT<<<dim3(cDV / 32, cD / 32), tb>>>(Wg,  wph + (size_t)OFF_G  * cD, cD, cDV);

    const float qscale = 0.08838834764831845f;

    for (int t = 0; t < cNL; t++) {
        k_prep<<<cM, 256>>>(p_h, in_e, nw, ltab + t * cLOOPD, xh, hh);

        // merged projection GEMM: q|k|la|v|gate with per-segment epilogue
        gemmH(xh, wph, p_proj, nullptr, cM, PSTR, cD, qscale, 9);

        k_chunk<<<cNC * cBH, 256, SMEM_CHUNK>>>(p_proj, p_proj + OFF_K, p_proj + OFF_LA,
                                                p_proj + OFF_V, p_o, p_kv, p_bdec);
        k_state<<<cBH * 8, 256>>>(p_kv, p_bdec, p_S);
        k_inter<<<cNC * cBH, 256>>>(p_proj, p_S, p_o, p_proj + OFF_G, oh);

        gemmH(oh, woh, p_gla, nullptr, cM, cD, cDV, 0.f, 0);

        k_lora_down<<<cM / 8, 256>>>(p_gla, loraA + (size_t)t * cD * cRANK, p_lora);
        k_lora_up<<<nBig, 256>>>(p_lora, loraB + (size_t)t * cRANK * cD, p_einj, p_gla);

        gemmH(hh, iah, p_hnew, p_gla, cM, cD, cD, 0.f, 0);

        k_act<<<cM, 256>>>(p_hnew, act_w, act_b, p_h, p_hout, p_cum, p_halt, t == 0 ? 1 : 0);
    }
    k_rmsnorm<<<cM, 256>>>(p_hout, onw, out);
}

// round 17
// speedup vs baseline: 2.6738x; 1.0242x over previous
#include <cuda_runtime.h>
#include <cuda_fp16.h>
#include <math.h>
#include <stdint.h>

// ---------------- problem constants ----------------
constexpr int cB = 4, cT = 4096, cD = 1024, cH = 8;
constexpr int cDK = 1024, cDV = 2048, cDKH = 128, cDVH = 256;
constexpr int cRANK = 16, cLOOPD = 128, cNL = 4;
constexpr int cCH = 64;
constexpr int cNC = cT / cCH;
constexpr int cBH = cB * cH;
constexpr int cM = cB * cT;
constexpr int PSTR = 7168;              // merged projection row stride (q|k|la|v|gate)
constexpr int OFF_K = 1024, OFF_LA = 2048, OFF_V = 3072, OFF_G = 5120;

// ---------------- device scratch ----------------
__device__ float g_h[cM * cD];
__device__ float g_proj[(size_t)cM * PSTR];
__device__ float g_o[cM * cDV];
__device__ float g_kv[cNC * cBH * cDKH * cDVH];
__device__ float g_bdec[cNC * cBH * cDKH];
__device__ float g_gla[cM * cD];
__device__ float g_lora[cM * cRANK];
__device__ float g_hnew[cM * cD];
__device__ float g_hout[cM * cD];
__device__ float g_cum[cM];
__device__ float g_halt[cM];
__device__ float g_einj[cM * cD];

// fp16 buffers
__device__ __align__(16) __half g_wph[(size_t)PSTR * cD];
__device__ __align__(16) __half g_woh[cDV * cD];
__device__ __align__(16) __half g_iah[cD * cD];
__device__ __align__(16) __half g_ibh[cD * cD];
__device__ __align__(16) __half g_eh[cM * cD];
__device__ __align__(16) __half g_xh[cM * cD];
__device__ __align__(16) __half g_hh2[cM * cD];
__device__ __align__(16) __half g_oh[cM * cDV];
__device__ __align__(16) __half g_q16[(size_t)cNC * cBH * 8192];    // per-cidx 128x64-half swizzled tile (q~ stacked halves)
__device__ __align__(16) __half g_S16[(size_t)cNC * cBH * 32768];   // per-cidx 512x64-half swizzled tile (S stacked halves)

// ---------------- helpers ----------------
__device__ __forceinline__ uint32_t s2u(const void* p) {
    uint32_t a;
    asm("{ .reg .u64 t; cvta.to.shared.u64 t, %1; cvt.u32.u64 %0, t; }" : "=r"(a) : "l"(p));
    return a;
}
__device__ __forceinline__ uint32_t sw128(uint32_t off) { return off ^ ((off >> 3) & 0x70); }

#define LDSM4(r, a) \
    asm volatile("ldmatrix.sync.aligned.m8n8.x4.shared.b16 {%0,%1,%2,%3}, [%4];" \
        : "=r"((r)[0]), "=r"((r)[1]), "=r"((r)[2]), "=r"((r)[3]) : "r"(a))

__device__ __forceinline__ void mma_f16(float* d, const uint32_t* a, const uint32_t* b) {
    asm volatile("mma.sync.aligned.m16n8k16.row.col.f32.f16.f16.f32 "
        "{%0,%1,%2,%3}, {%4,%5,%6,%7}, {%8,%9}, {%0,%1,%2,%3};"
        : "+f"(d[0]), "+f"(d[1]), "+f"(d[2]), "+f"(d[3])
        : "r"(a[0]), "r"(a[1]), "r"(a[2]), "r"(a[3]), "r"(b[0]), "r"(b[1]));
}

// ---------------- mma.sync fp16 GEMM (unchanged from R15) ----------------
constexpr int GTM = 128, GKC = 64;
constexpr int A_TILE_B = 16384;

template <int GTN_>
__global__ void __launch_bounds__(256, 2) gemm_fp16_t(
    const __half* __restrict__ A, const __half* __restrict__ B,
    float* __restrict__ C, const float* __restrict__ Ci,
    int M, int N, int K, float scale, int epi)
{
    constexpr int B_TILE_B = GTN_ * 128;
    constexpr int STG = A_TILE_B + B_TILE_B;
    constexpr int NFRAG = GTN_ / 16;
    constexpr int NLD = GTN_ / 32;
    constexpr int NT = (1024 + GTN_ * 8) / 256;

    extern __shared__ char smem[];
    int tid = threadIdx.x;
    int lane = tid & 31, wid = tid >> 5;

    int mbCnt = M >> 7;
    int per_panel = mbCnt * 8;
    int panel = blockIdx.x / per_panel;
    int rem = blockIdx.x - panel * per_panel;
    int bm = rem >> 3;
    int bn = panel * 8 + (rem & 7);
    int m0 = bm * GTM, n0 = bn * GTN_;

    int wm = (wid & 3) * 32, wn = (wid >> 2) * (GTN_ / 2);

    const int NCk = K / GKC;

    const __half* pA = A + (size_t)m0 * K;
    const __half* pB = B + (size_t)n0 * K;

    auto load_stage = [&](int kc, int s) {
        char* base = smem + s * STG;
        int k0 = kc * GKC;
#pragma unroll
        for (int i = 0; i < NT; i++) {
            int gg = tid + i * 256;
            int tile = (gg >= 1024) ? 1 : 0;
            int idx = tile ? gg - 1024 : gg;
            int r = idx >> 3, seg = idx & 7;
            uint32_t off = sw128((uint32_t)(r * 128 + seg * 16));
            const __half* src = (tile ? pB : pA) + (size_t)r * K + k0 + seg * 8;
            uint32_t dst = s2u(base + tile * A_TILE_B + off);
            asm volatile("cp.async.cg.shared.global [%0], [%1], 16;" :: "r"(dst), "l"(src));
        }
        asm volatile("cp.async.commit_group;" ::: "memory");
    };

    float acc[2][NFRAG][4];
#pragma unroll
    for (int mf = 0; mf < 2; mf++)
#pragma unroll
        for (int nf = 0; nf < NFRAG; nf++)
#pragma unroll
            for (int j = 0; j < 4; j++) acc[mf][nf][j] = 0.f;

    load_stage(0, 0);
    load_stage(1, 1);

    int a_row = (lane & 15);
    int a_col8 = (lane >> 4);
    int b_row = (lane & 7) + ((lane >> 4) & 1) * 8;
    int b_col8 = (lane >> 3) & 1;

    for (int c = 0; c < NCk; c++) {
        asm volatile("cp.async.wait_group 1;" ::: "memory");
        __syncthreads();
        if (c + 2 < NCk) load_stage(c + 2, (c + 2) % 3);
        else asm volatile("cp.async.commit_group;" ::: "memory");

        char* base = smem + (c % 3) * STG;
        uint32_t sA = s2u(base), sB = sA + A_TILE_B;
#pragma unroll
        for (int kk = 0; kk < 4; kk++) {
            uint32_t kb = (uint32_t)(kk * 32);
            uint32_t ah[2][4];
#pragma unroll
            for (int mf = 0; mf < 2; mf++) {
                uint32_t rowb = (uint32_t)((wm + mf * 16 + a_row) * 128);
                LDSM4(ah[mf], sA + sw128(rowb + kb + a_col8 * 16));
            }
            uint32_t bfr[NFRAG][2];
#pragma unroll
            for (int g = 0; g < NLD; g++) {
                uint32_t rowb = (uint32_t)((wn + g * 16 + b_row) * 128);
                uint32_t r[4];
                LDSM4(r, sB + sw128(rowb + kb + b_col8 * 16));
                bfr[g * 2][0] = r[0]; bfr[g * 2][1] = r[1];
                bfr[g * 2 + 1][0] = r[2]; bfr[g * 2 + 1][1] = r[3];
            }
#pragma unroll
            for (int mf = 0; mf < 2; mf++)
#pragma unroll
                for (int nf = 0; nf < NFRAG; nf++)
                    mma_f16(acc[mf][nf], ah[mf], bfr[nf]);
        }
    }

    const float qsc = scale;
#pragma unroll
    for (int mf = 0; mf < 2; mf++) {
#pragma unroll
        for (int nf = 0; nf < NFRAG; nf++) {
            int r0 = m0 + wm + mf * 16 + (lane >> 2);
            int cc = n0 + wn + nf * 8 + (lane & 3) * 2;
#pragma unroll
            for (int hh = 0; hh < 2; hh++) {
                int r = r0 + hh * 8;
                float vx = acc[mf][nf][hh * 2], vy = acc[mf][nf][hh * 2 + 1];
                size_t off = (size_t)r * N + cc;
                if (Ci) { vx += Ci[off]; vy += Ci[off + 1]; }
                int e = epi;
                if (e == 9) {
                    int seg = cc >> 10;
                    e = (seg == 0) ? 1 : (seg == 2) ? 2 : (seg >= 5) ? 3 : 0;
                }
                if (e == 1) { vx *= qsc; vy *= qsc; }
                else if (e == 2) {
                    vx = (fminf(vx, 0.f) - log1pf(expf(-fabsf(vx)))) * 0.0625f;
                    vy = (fminf(vy, 0.f) - log1pf(expf(-fabsf(vy)))) * 0.0625f;
                } else if (e == 3) {
                    vx = vx / (1.f + expf(-vx));
                    vy = vy / (1.f + expf(-vy));
                }
                *(float2*)&C[off] = make_float2(vx, vy);
            }
        }
    }
}

constexpr int SMEM_G128 = 3 * (A_TILE_B + 128 * 128);   // 98304
constexpr int SMEM_G64  = 3 * (A_TILE_B + 64 * 128);    // 73728

// ---------------- utility kernels ----------------
__global__ void k_copy(float* __restrict__ dst, const float* __restrict__ src) {
    int idx = blockIdx.x * 256 + threadIdx.x;
    dst[idx] = src[idx];
}
__global__ void k_cvt(const float* __restrict__ src, __half* __restrict__ dst) {
    size_t i4 = ((size_t)blockIdx.x * 256 + threadIdx.x) * 4;
    float4 v = *(const float4*)(src + i4);
    __half2* d = (__half2*)(dst + i4);
    d[0] = __floats2half2_rn(v.x, v.y);
    d[1] = __floats2half2_rn(v.z, v.w);
}
__global__ void k_wconvT(const float* __restrict__ W, __half* __restrict__ out, int K, int N) {
    __shared__ float s[32][33];
    int n0 = blockIdx.x * 32, k0 = blockIdx.y * 32;
    int tx = threadIdx.x, ty = threadIdx.y;
#pragma unroll
    for (int i = 0; i < 4; i++) {
        int r = ty + i * 8;
        s[r][tx] = W[(size_t)(k0 + r) * N + n0 + tx];
    }
    __syncthreads();
#pragma unroll
    for (int i = 0; i < 4; i++) {
        int r = ty + i * 8;
        out[(size_t)(n0 + r) * K + k0 + tx] = __float2half(s[tx][r]);
    }
}

// ---------------- fused loop-embed + rmsnorm(h+e) + fp16 conversions ----------------
__global__ void __launch_bounds__(256) k_prep(float* __restrict__ h, const float* __restrict__ e,
                                              const float* __restrict__ nw, const float* __restrict__ ltab,
                                              __half* __restrict__ xh, __half* __restrict__ hh) {
    int row = blockIdx.x; size_t base = (size_t)row * cD;
    int tid = threadIdx.x;
    if (tid < cLOOPD) h[base + tid] += ltab[tid];
    __syncthreads();
    float hv[4], vals[4]; float ss = 0.f;
#pragma unroll
    for (int i = 0; i < 4; i++) {
        int c = tid + i * 256;
        float hx = h[base + c];
        hv[i] = hx;
        float v = hx + e[base + c];
        vals[i] = v; ss += v * v;
    }
    __shared__ float red[256];
    red[tid] = ss; __syncthreads();
    for (int s = 128; s > 0; s >>= 1) { if (tid < s) red[tid] += red[tid + s]; __syncthreads(); }
    float rs = rsqrtf(red[0] * (1.f / cD) + 1e-6f);
#pragma unroll
    for (int i = 0; i < 4; i++) {
        int c = tid + i * 256;
        xh[base + c] = __float2half(vals[i] * rs * nw[c]);
        hh[base + c] = __float2half(hv[i]);
    }
}

// ---------------- final rmsnorm ----------------
__global__ void __launch_bounds__(256) k_rmsnorm(const float* __restrict__ in, const float* __restrict__ nw,
                                                 float* __restrict__ out) {
    int row = blockIdx.x; size_t base = (size_t)row * cD;
    int tid = threadIdx.x;
    float vals[4]; float ss = 0.f;
#pragma unroll
    for (int i = 0; i < 4; i++) {
        int c = tid + i * 256;
        float v = in[base + c];
        vals[i] = v; ss += v * v;
    }
    __shared__ float red[256];
    red[tid] = ss; __syncthreads();
    for (int s = 128; s > 0; s >>= 1) { if (tid < s) red[tid] += red[tid + s]; __syncthreads(); }
    float rs = rsqrtf(red[0] * (1.f / cD) + 1e-6f);
#pragma unroll
    for (int i = 0; i < 4; i++) {
        int c = tid + i * 256;
        out[base + c] = vals[i] * rs * nw[c];
    }
}

// ---------------- GLA chunk kernel: cumsum + QK(fp32) + AV(fp32) + KV(fp16 mma) ----------------
// smem: s_A 16KB | s_qt 32KB | s_kt 33.8KB | s_v 64KB | s_kc16 16KB | s_v16 32KB = 193KB
constexpr int SMEM_CHUNK = 197632;
__global__ void __launch_bounds__(256) k_chunk(const float* __restrict__ pq, const float* __restrict__ pk,
                                               const float* __restrict__ pla, const float* __restrict__ pv,
                                               float* __restrict__ po, float* __restrict__ pkv,
                                               float* __restrict__ pbdec, __half* __restrict__ q16) {
    extern __shared__ float sm[];
    float* s_A  = sm;                 // 4096 f (after sync)
    float* s_qt = sm + 4096;          // 8192 f
    float* s_kt = sm + 12288;         // 8448 f, stride 132
    float* s_v  = sm + 20736;         // 16384 f
    char* smc = (char*)sm;
    char* s_kc16 = smc + 148480;      // [d][j] 128x64 half, 128B rows, sw128
    char* s_v16  = smc + 164864;      // [u][j] 256x64 half

    int cidx = blockIdx.x;
    int c = cidx / cBH, bh = cidx - c * cBH;
    int b = bh >> 3, hh = bh & 7;
    int t0 = c * cCH;
    size_t qbase = ((size_t)b * cT + t0) * PSTR + hh * cDKH;
    size_t vbase = ((size_t)b * cT + t0) * PSTR + hh * cDVH;
    size_t obase = ((size_t)b * cT + t0) * cDV + hh * cDVH;
    int tid = threadIdx.x;

    if (tid < 128) {
        int d = tid;
        int dh = d >> 6;
        uint32_t dc = (uint32_t)((d & 63) * 2);
        char* qg = (char*)q16 + (size_t)cidx * 16384;
        float cum = 0.f, ec = 1.f;
        for (int i = 0; i < cCH; i++) {
            size_t off = qbase + (size_t)i * PSTR + d;
            cum += pla[off];
            ec = expf(cum);
            float qt = pq[off] * ec;
            s_qt[i * 128 + d] = qt;
            s_kt[i * 132 + d] = pk[off] / ec;
            *(__half*)(qg + sw128((uint32_t)((i + 64 * dh) * 128) + dc)) = __float2half(qt);
        }
        float elat = ec;                     // exp(latot)
        pbdec[(size_t)cidx * cDKH + d] = elat;
        for (int i = 0; i < cCH; i++) {
            float kc = s_kt[i * 132 + d] * elat;   // k * exp(latot - cum_i)
            *(__half*)(s_kc16 + sw128((uint32_t)(d * 128 + i * 2))) = __float2half(kc);
        }
    } else {
        int lt = tid - 128;
        for (int l = 0; l < 32; l++) {
            int idx4 = lt + l * 128;
            int i = idx4 >> 6;
            int u4 = (idx4 & 63) * 4;
            float4 vv = *(const float4*)&pv[vbase + (size_t)i * PSTR + u4];
            *(float4*)&s_v[i * 256 + u4] = vv;
            uint32_t ib = (uint32_t)(i * 2);
            *(__half*)(s_v16 + sw128((uint32_t)((u4 + 0) * 128) + ib)) = __float2half(vv.x);
            *(__half*)(s_v16 + sw128((uint32_t)((u4 + 1) * 128) + ib)) = __float2half(vv.y);
            *(__half*)(s_v16 + sw128((uint32_t)((u4 + 2) * 128) + ib)) = __float2half(vv.z);
            *(__half*)(s_v16 + sw128((uint32_t)((u4 + 3) * 128) + ib)) = __float2half(vv.w);
        }
    }
    __syncthreads();

    // A = mask(q~ k~^T)  (fp32)
    for (int idx = tid; idx < cCH * cCH; idx += 256) {
        int i = idx >> 6, j = idx & 63;
        float sum = 0.f;
        if (j <= i) {
            const float* qp = &s_qt[i * 128];
            const float* kp = &s_kt[j * 132];
#pragma unroll
            for (int d = 0; d < 128; d += 4) {
                float4 qa = *(const float4*)&qp[d];
                float4 kb = *(const float4*)&kp[d];
                sum += qa.x * kb.x + qa.y * kb.y + qa.z * kb.z + qa.w * kb.w;
            }
        }
        s_A[idx] = sum;
    }
    __syncthreads();

    // O_intra = A @ V (fp32)
    {
        int uq = tid & 63;
        int il = tid >> 6;
#pragma unroll 1
        for (int step = 0; step < 16; step++) {
            int i = il + step * 4;
            float4 acc = make_float4(0.f, 0.f, 0.f, 0.f);
            const float* arow = &s_A[i * 64];
            for (int j = 0; j <= i; j++) {
                float a = arow[j];
                float4 vv = *(const float4*)&s_v[j * 256 + uq * 4];
                acc.x += a * vv.x; acc.y += a * vv.y; acc.z += a * vv.z; acc.w += a * vv.w;
            }
            *(float4*)&po[obase + (size_t)i * cDV + uq * 4] = acc;
        }
    }

    // KV_c = kc^T @ V  (fp16 mma; K=64)
    {
        int lane = tid & 31, w = tid >> 5;
        int a_row = lane & 15, a_col8 = lane >> 4;
        int b_row = (lane & 7) + ((lane >> 4) & 1) * 8, b_col8 = (lane >> 3) & 1;
        uint32_t sKC = s2u(s_kc16), sV = s2u(s_v16);
        uint32_t Af[4][4];
#pragma unroll
        for (int kf = 0; kf < 4; kf++)
            LDSM4(Af[kf], sKC + sw128((uint32_t)((w * 16 + a_row) * 128 + kf * 32 + a_col8 * 16)));
        size_t kvb = (size_t)cidx * (cDKH * cDVH);
#pragma unroll 1
        for (int nh = 0; nh < 2; nh++) {
            float acc[16][4];
#pragma unroll
            for (int nf = 0; nf < 16; nf++)
#pragma unroll
                for (int j = 0; j < 4; j++) acc[nf][j] = 0.f;
#pragma unroll
            for (int kf = 0; kf < 4; kf++) {
                uint32_t bfr[16][2];
#pragma unroll
                for (int g = 0; g < 8; g++) {
                    uint32_t r[4];
                    LDSM4(r, sV + sw128((uint32_t)((nh * 128 + g * 16 + b_row) * 128 + kf * 32 + b_col8 * 16)));
                    bfr[g * 2][0] = r[0]; bfr[g * 2][1] = r[1];
                    bfr[g * 2 + 1][0] = r[2]; bfr[g * 2 + 1][1] = r[3];
                }
#pragma unroll
                for (int nf = 0; nf < 16; nf++)
                    mma_f16(acc[nf], Af[kf], bfr[nf]);
            }
#pragma unroll
            for (int nf = 0; nf < 16; nf++)
#pragma unroll
                for (int h2 = 0; h2 < 2; h2++) {
                    int d = w * 16 + (lane >> 2) + h2 * 8;
                    int u = nh * 128 + nf * 8 + (lane & 3) * 2;
                    *(float2*)&pkv[kvb + (size_t)d * cDVH + u] =
                        make_float2(acc[nf][h2 * 2], acc[nf][h2 * 2 + 1]);
                }
        }
    }
}

// ---------------- state propagation: fp32 recurrence, fp16 swizzled snapshots ----------------
__global__ void __launch_bounds__(256) k_state(const float* __restrict__ pkv, const float* __restrict__ pbdec,
                                               __half* __restrict__ S16) {
    int blk = blockIdx.x;
    int bh = blk >> 3;
    int vs = (blk & 7) * 32;
    int tid = threadIdx.x;
    int kr = tid >> 1;
    int vofs = vs + (tid & 1) * 16;
    int dh = kr >> 6;
    uint32_t colb = (uint32_t)((kr & 63) * 2);
    float S[16];
#pragma unroll
    for (int j = 0; j < 16; j++) S[j] = 0.f;
    for (int c = 0; c < cNC; c++) {
        size_t base = ((size_t)c * cBH + bh) * (cDKH * cDVH) + (size_t)kr * cDVH + vofs;
        float bd = pbdec[((size_t)c * cBH + bh) * cDKH + kr];
        char* sg = (char*)S16 + ((size_t)c * cBH + bh) * 65536;
#pragma unroll
        for (int j = 0; j < 16; j += 4) {
#pragma unroll
            for (int jj = 0; jj < 4; jj++) {
                int u = vofs + j + jj;
                *(__half*)(sg + sw128((uint32_t)((u + 256 * dh) * 128) + colb)) = __float2half(S[j + jj]);
            }
            float4 kvv = *(const float4*)&pkv[base + j];
            S[j]     = bd * S[j]     + kvv.x;
            S[j + 1] = bd * S[j + 1] + kvv.y;
            S[j + 2] = bd * S[j + 2] + kvv.z;
            S[j + 3] = bd * S[j + 3] + kvv.w;
        }
    }
}

// ---------------- inter-chunk: o = (intra + q~@S)*gate  (fp16 mma, K=128) ----------------
constexpr int SMEM_INTER = 81920;
__global__ void __launch_bounds__(256) k_inter(const __half* __restrict__ q16, const __half* __restrict__ S16,
                                               const float* __restrict__ po, const float* __restrict__ pgate,
                                               __half* __restrict__ oh) {
    extern __shared__ char smi[];
    char* sQ = smi;              // 16KB
    char* sS = smi + 16384;      // 64KB
    int cidx = blockIdx.x;
    int c = cidx / cBH, bh = cidx - c * cBH;
    int b = bh >> 3, hhd = bh & 7;
    int t0 = c * cCH;
    size_t gbase = ((size_t)b * cT + t0) * PSTR + hhd * cDVH;
    size_t obase = ((size_t)b * cT + t0) * cDV + hhd * cDVH;
    int tid = threadIdx.x;

    const char* gq = (const char*)q16 + (size_t)cidx * 16384;
    const char* gs = (const char*)S16 + (size_t)cidx * 65536;
#pragma unroll
    for (int i = 0; i < 4; i++) {
        int t = tid + i * 256;
        asm volatile("cp.async.cg.shared.global [%0], [%1], 16;"
                     :: "r"(s2u(sQ + t * 16)), "l"(gq + t * 16));
    }
#pragma unroll
    for (int i = 0; i < 16; i++) {
        int t = tid + i * 256;
        asm volatile("cp.async.cg.shared.global [%0], [%1], 16;"
                     :: "r"(s2u(sS + t * 16)), "l"(gs + t * 16));
    }
    asm volatile("cp.async.commit_group;" ::: "memory");
    asm volatile("cp.async.wait_group 0;" ::: "memory");
    __syncthreads();

    int lane = tid & 31, w = tid >> 5;
    int m0w = (w & 3) * 16, nh = w >> 2;
    int a_row = lane & 15, a_col8 = lane >> 4;
    int b_row = (lane & 7) + ((lane >> 4) & 1) * 8, b_col8 = (lane >> 3) & 1;
    uint32_t sQu = s2u(sQ), sSu = s2u(sS);

    float acc[16][4];
#pragma unroll
    for (int nf = 0; nf < 16; nf++)
#pragma unroll
        for (int j = 0; j < 4; j++) acc[nf][j] = 0.f;

    uint32_t Af[8][4];
#pragma unroll
    for (int kf = 0; kf < 8; kf++) {
        int rowa = ((kf < 4) ? 0 : 64) + m0w + a_row;
        uint32_t colb = (uint32_t)((kf & 3) * 32 + a_col8 * 16);
        LDSM4(Af[kf], sQu + sw128((uint32_t)(rowa * 128) + colb));
    }
#pragma unroll
    for (int kf = 0; kf < 8; kf++) {
        uint32_t bfr[16][2];
#pragma unroll
        for (int g = 0; g < 8; g++) {
            int rowb = ((kf < 4) ? 0 : 256) + nh * 128 + g * 16 + b_row;
            uint32_t colb = (uint32_t)((kf & 3) * 32 + b_col8 * 16);
            uint32_t r[4];
            LDSM4(r, sSu + sw128((uint32_t)(rowb * 128) + colb));
            bfr[g * 2][0] = r[0]; bfr[g * 2][1] = r[1];
            bfr[g * 2 + 1][0] = r[2]; bfr[g * 2 + 1][1] = r[3];
        }
#pragma unroll
        for (int nf = 0; nf < 16; nf++)
            mma_f16(acc[nf], Af[kf], bfr[nf]);
    }

#pragma unroll
    for (int nf = 0; nf < 16; nf++)
#pragma unroll
        for (int h2 = 0; h2 < 2; h2++) {
            int i = m0w + (lane >> 2) + h2 * 8;
            int u = nh * 128 + nf * 8 + (lane & 3) * 2;
            size_t offo = obase + (size_t)i * cDV + u;
            float2 pv2 = *(const float2*)&po[offo];
            float2 gv2 = *(const float2*)&pgate[gbase + (size_t)i * PSTR + u];
            float ov0 = (pv2.x + acc[nf][h2 * 2]) * gv2.x;
            float ov1 = (pv2.y + acc[nf][h2 * 2 + 1]) * gv2.y;
            *(__half2*)(oh + offo) = __floats2half2_rn(ov0, ov1);
        }
}

// ---------------- LoRA ----------------
__global__ void __launch_bounds__(256) k_lora_down(const float* __restrict__ g, const float* __restrict__ A,
                                                   float* __restrict__ out) {
    int warp = threadIdx.x >> 5, lane = threadIdx.x & 31;
    int m = blockIdx.x * 8 + warp;
    const float* grow = &g[(size_t)m * cD];
    float acc[cRANK];
#pragma unroll
    for (int r = 0; r < cRANK; r++) acc[r] = 0.f;
    for (int kk = lane; kk < cD; kk += 32) {
        float a = grow[kk];
        const float4* Ap = (const float4*)&A[(size_t)kk * cRANK];
        float4 b0 = Ap[0], b1 = Ap[1], b2 = Ap[2], b3 = Ap[3];
        acc[0] += a * b0.x; acc[1] += a * b0.y; acc[2] += a * b0.z; acc[3] += a * b0.w;
        acc[4] += a * b1.x; acc[5] += a * b1.y; acc[6] += a * b1.z; acc[7] += a * b1.w;
        acc[8] += a * b2.x; acc[9] += a * b2.y; acc[10] += a * b2.z; acc[11] += a * b2.w;
        acc[12] += a * b3.x; acc[13] += a * b3.y; acc[14] += a * b3.z; acc[15] += a * b3.w;
    }
#pragma unroll
    for (int r = 0; r < cRANK; r++)
        for (int s = 16; s > 0; s >>= 1) acc[r] += __shfl_xor_sync(0xffffffffu, acc[r], s);
    if (lane == 0) {
#pragma unroll
        for (int r = 0; r < cRANK; r++) out[(size_t)m * cRANK + r] = acc[r];
    }
}
__global__ void __launch_bounds__(256) k_lora_up(const float* __restrict__ tmp, const float* __restrict__ Bm,
                                                 const float* __restrict__ einj, float* __restrict__ g) {
    int idx = blockIdx.x * 256 + threadIdx.x;
    int m = idx >> 10, n = idx & 1023;
    const float* tr = &tmp[(size_t)m * cRANK];
    float s = 0.f;
#pragma unroll
    for (int r = 0; r < cRANK; r++) s += tr[r] * Bm[r * cD + n];
    g[idx] += s + einj[idx];
}

// ---------------- ACT halting ----------------
__global__ void __launch_bounds__(256) k_act(const float* __restrict__ hnew, const float* __restrict__ act_w,
                                             const float* __restrict__ act_b, float* __restrict__ h,
                                             float* __restrict__ hout, float* __restrict__ cum,
                                             float* __restrict__ halt, int first) {
    int row = blockIdx.x; size_t base = (size_t)row * cD;
    int tid = threadIdx.x;
    float ss = 0.f;
#pragma unroll
    for (int i = 0; i < 4; i++) {
        int c = tid + i * 256;
        ss += hnew[base + c] * act_w[c];
    }
    __shared__ float red[256]; __shared__ float wsh;
    red[tid] = ss; __syncthreads();
    for (int s = 128; s > 0; s >>= 1) { if (tid < s) red[tid] += red[tid + s]; __syncthreads(); }
    if (tid == 0) {
        float z = red[0] + act_b[0];
        float p = 1.f / (1.f + expf(-z));
        float cm = first ? 0.f : cum[row];
        float hl = first ? 0.f : halt[row];
        float p_eff = (hl > 0.5f) ? 0.f : p;
        float ncum = cm + p_eff;
        bool newly = (hl < 0.5f) && (ncum >= 0.99f);
        float w = newly ? (1.f - cm) : p_eff;
        cum[row] = ncum;
        halt[row] = (newly || hl > 0.5f) ? 1.f : 0.f;
        wsh = w;
    }
    __syncthreads();
    float w = wsh;
#pragma unroll
    for (int i = 0; i < 4; i++) {
        int c = tid + i * 256;
        float v = hnew[base + c];
        if (first) hout[base + c] = w * v;
        else       hout[base + c] += w * v;
        h[base + c] = v;
    }
}

// ---------------- host ----------------
static void gemmH(const __half* A, const __half* B, float* C, const float* Ci,
                  int M, int N, int K, float scale, int epi) {
    if (N == 1024) {
        int nCTA = (M / GTM) * (N / 64);
        gemm_fp16_t<64><<<nCTA, 256, SMEM_G64>>>(A, B, C, Ci, M, N, K, scale, epi);
    } else {
        int nCTA = (M / GTM) * (N / 128);
        gemm_fp16_t<128><<<nCTA, 256, SMEM_G128>>>(A, B, C, Ci, M, N, K, scale, epi);
    }
}

extern "C" void kernel_launch(void* const* d_in, const int* in_sizes, int n_in,
                              void* d_out, int out_size) {
    const float* in_h  = (const float*)d_in[0];
    const float* in_e  = (const float*)d_in[1];
    const float* nw    = (const float*)d_in[2];
    const float* onw   = (const float*)d_in[3];
    const float* Wq    = (const float*)d_in[4];
    const float* Wk    = (const float*)d_in[5];
    const float* Wv    = (const float*)d_in[6];
    const float* Wgk   = (const float*)d_in[7];
    const float* Wg    = (const float*)d_in[8];
    const float* Wo    = (const float*)d_in[9];
    const float* loraA = (const float*)d_in[10];
    const float* loraB = (const float*)d_in[11];
    const float* injA  = (const float*)d_in[12];
    const float* injB  = (const float*)d_in[13];
    const float* act_w = (const float*)d_in[14];
    const float* act_b = (const float*)d_in[15];
    const float* ltab  = (const float*)d_in[16];
    float* out = (float*)d_out;

    float *p_h, *p_proj, *p_o, *p_kv, *p_bdec,
          *p_gla, *p_lora, *p_hnew, *p_hout, *p_cum, *p_halt, *p_einj;
    cudaGetSymbolAddress((void**)&p_h, g_h);
    cudaGetSymbolAddress((void**)&p_proj, g_proj);
    cudaGetSymbolAddress((void**)&p_o, g_o);
    cudaGetSymbolAddress((void**)&p_kv, g_kv);
    cudaGetSymbolAddress((void**)&p_bdec, g_bdec);
    cudaGetSymbolAddress((void**)&p_gla, g_gla);
    cudaGetSymbolAddress((void**)&p_lora, g_lora);
    cudaGetSymbolAddress((void**)&p_hnew, g_hnew);
    cudaGetSymbolAddress((void**)&p_hout, g_hout);
    cudaGetSymbolAddress((void**)&p_cum, g_cum);
    cudaGetSymbolAddress((void**)&p_halt, g_halt);
    cudaGetSymbolAddress((void**)&p_einj, g_einj);

    __half *wph, *woh, *iah, *ibh, *eh, *xh, *hh, *oh, *q16, *S16;
    cudaGetSymbolAddress((void**)&wph, g_wph);
    cudaGetSymbolAddress((void**)&woh, g_woh);
    cudaGetSymbolAddress((void**)&iah, g_iah);
    cudaGetSymbolAddress((void**)&ibh, g_ibh);
    cudaGetSymbolAddress((void**)&eh, g_eh);
    cudaGetSymbolAddress((void**)&xh, g_xh);
    cudaGetSymbolAddress((void**)&hh, g_hh2);
    cudaGetSymbolAddress((void**)&oh, g_oh);
    cudaGetSymbolAddress((void**)&q16, g_q16);
    cudaGetSymbolAddress((void**)&S16, g_S16);

    cudaFuncSetAttribute(k_chunk, cudaFuncAttributeMaxDynamicSharedMemorySize, SMEM_CHUNK);
    cudaFuncSetAttribute(k_inter, cudaFuncAttributeMaxDynamicSharedMemorySize, SMEM_INTER);
    cudaFuncSetAttribute(gemm_fp16_t<128>, cudaFuncAttributeMaxDynamicSharedMemorySize, SMEM_G128);
    cudaFuncSetAttribute(gemm_fp16_t<64>,  cudaFuncAttributeMaxDynamicSharedMemorySize, SMEM_G64);

    const int nBig = cM * cD / 256;

    k_copy<<<nBig, 256>>>(p_h, in_h);
    k_cvt<<<cD * cD / 1024, 256>>>(injB, ibh);
    k_cvt<<<cM * cD / 1024, 256>>>(in_e, eh);
    k_cvt<<<cD * cD / 1024, 256>>>(injA, iah);
    dim3 tb(32, 8);
    k_wconvT<<<dim3(cD / 32, cDV / 32), tb>>>(Wo, woh, cDV, cD);
    {
        int nCTA = (cM / GTM) * (cD / 128);
        gemm_fp16_t<128><<<nCTA, 256, SMEM_G128>>>(eh, ibh, p_einj, nullptr, cM, cD, cD, 0.f, 0);
    }

    k_wconvT<<<dim3(cDK / 32, cD / 32), tb>>>(Wq,  wph,                       cD, cDK);
    k_wconvT<<<dim3(cDK / 32, cD / 32), tb>>>(Wk,  wph + (size_t)OFF_K  * cD, cD, cDK);
    k_wconvT<<<dim3(cDK / 32, cD / 32), tb>>>(Wgk, wph + (size_t)OFF_LA * cD, cD, cDK);
    k_wconvT<<<dim3(cDV / 32, cD / 32), tb>>>(Wv,  wph + (size_t)OFF_V  * cD, cD, cDV);
    k_wconvT<<<dim3(cDV / 32, cD / 32), tb>>>(Wg,  wph + (size_t)OFF_G  * cD, cD, cDV);

    const float qscale = 0.08838834764831845f;

    for (int t = 0; t < cNL; t++) {
        k_prep<<<cM, 256>>>(p_h, in_e, nw, ltab + t * cLOOPD, xh, hh);

        gemmH(xh, wph, p_proj, nullptr, cM, PSTR, cD, qscale, 9);

        k_chunk<<<cNC * cBH, 256, SMEM_CHUNK>>>(p_proj, p_proj + OFF_K, p_proj + OFF_LA,
                                                p_proj + OFF_V, p_o, p_kv, p_bdec, q16);
        k_state<<<cBH * 8, 256>>>(p_kv, p_bdec, S16);
        k_inter<<<cNC * cBH, 256, SMEM_INTER>>>(q16, S16, p_o, p_proj + OFF_G, oh);

        gemmH(oh, woh, p_gla, nullptr, cM, cD, cDV, 0.f, 0);

        k_lora_down<<<cM / 8, 256>>>(p_gla, loraA + (size_t)t * cD * cRANK, p_lora);
        k_lora_up<<<nBig, 256>>>(p_lora, loraB + (size_t)t * cRANK * cD, p_einj, p_gla);

        gemmH(hh, iah, p_hnew, p_gla, cM, cD, cD, 0.f, 0);

        k_act<<<cM, 256>>>(p_hnew, act_w, act_b, p_h, p_hout, p_cum, p_halt, t == 0 ? 1 : 0);
    }
    k_rmsnorm<<<cM, 256>>>(p_hout, onw, out);
}